// round 9
// baseline (speedup 1.0000x reference)
#include <cuda_runtime.h>
#include <cuda_bf16.h>
#include <math.h>
#include <stdint.h>

#define BB 2
#define SS 1024
#define TT 2048
#define DD 1024
#define HH 8
#define KV 2
#define HDIM 128
#define EE 8
#define FFND 3584
#define NQKV 1536

typedef __nv_bfloat16 bf16;

// ---- bf16 GEMM (kept for O-proj) ----
#define KT 64
#define STAGES 3
#define TILE_BYTES 16384
#define STAGE_BYTES (3 * TILE_BYTES)
#define SC_OFF (STAGES * STAGE_BYTES)
#define SMEM_SZ (SC_OFF + 28 * 128 * 4)
// ---- int8 GEMM ----
#define I8_STAGE 49152                   // A1 16K + A2 16K + B 16K (128 k-bytes per stage)
#define I8_SC_OFF (3 * I8_STAGE)
#define I8_SMEM (I8_SC_OFF + 28 * 128 * 4)
// ---- attention ----
#define SCR_SMEM (2 * 4 * TILE_BYTES)
#define AV_STAGE (3 * TILE_BYTES)
#define AV_SMEM (3 * AV_STAGE)

// int8 weights + per-group fp32 scale
__device__ int8_t g_wqkv8[NQKV * DD];     __device__ float g_wqkvs[NQKV * DD / 128];
__device__ int8_t g_w18[EE * FFND * DD];  __device__ float g_w1s[EE * FFND * DD / 128];
__device__ int8_t g_w38[EE * FFND * DD];  __device__ float g_w3s[EE * FFND * DD / 128];
__device__ int8_t g_w28[EE * DD * FFND];  __device__ float g_w2s[EE * DD * FFND / 128];
// bf16 weights for O-proj
__device__ bf16  g_won[DD * DD];          __device__ float g_wos[DD * DD / 128];
// int8 activations (digit decomposition)
__device__ int8_t g_xd1[TT * DD];  __device__ int8_t g_xd2[TT * DD];  __device__ float g_xsr[TT];
__device__ int8_t g_hd1[TT * DD];  __device__ int8_t g_hd2[TT * DD];  __device__ float g_hsr[TT];
__device__ int8_t g_ud1[EE * TT * FFND]; __device__ int8_t g_ud2[EE * TT * FFND];
__device__ float g_usr[EE * TT];
// attention buffers
__device__ float g_qkv[TT * NQKV];
__device__ bf16 g_qh[TT * DD];         __device__ bf16 g_ql[TT * DD];
__device__ bf16 g_kh[TT * KV * HDIM];  __device__ bf16 g_kl[TT * KV * HDIM];
__device__ bf16 g_vn[TT * KV * HDIM];  __device__ float g_vs[TT * KV];
__device__ float g_sc[BB * HH * SS * SS];
__device__ bf16 g_ph[BB * HH * SS * SS];
__device__ bf16 g_pl[BB * HH * SS * SS];
__device__ bf16 g_oh[TT * DD];         __device__ bf16 g_ol[TT * DD];
__device__ float g_h[TT * DD];
__device__ float g_hn[TT * DD];
__device__ float g_up1[EE * TT * FFND];
__device__ float g_moe[TT * DD];
__device__ int   g_cnt[EE];
__device__ int   g_tok[EE * TT];
__device__ float g_twt[EE * TT];

// ---------------- ptx helpers ----------------
__device__ __forceinline__ uint32_t smem_u32(const void* p) {
    uint32_t a;
    asm("{ .reg .u64 t; cvta.to.shared.u64 t, %1; cvt.u32.u64 %0, t; }" : "=r"(a) : "l"(p));
    return a;
}
__device__ __forceinline__ void ldsm4(uint32_t a, uint32_t& r0, uint32_t& r1,
                                      uint32_t& r2, uint32_t& r3) {
    asm volatile("ldmatrix.sync.aligned.m8n8.x4.shared.b16 {%0,%1,%2,%3}, [%4];"
                 : "=r"(r0), "=r"(r1), "=r"(r2), "=r"(r3) : "r"(a));
}
__device__ __forceinline__ void ldsm4t(uint32_t a, uint32_t& r0, uint32_t& r1,
                                       uint32_t& r2, uint32_t& r3) {
    asm volatile("ldmatrix.sync.aligned.m8n8.x4.trans.shared.b16 {%0,%1,%2,%3}, [%4];"
                 : "=r"(r0), "=r"(r1), "=r"(r2), "=r"(r3) : "r"(a));
}
__device__ __forceinline__ void mma16816(float* c, const uint32_t* a, const uint32_t* b) {
    asm volatile("mma.sync.aligned.m16n8k16.row.col.f32.bf16.bf16.f32 "
                 "{%0,%1,%2,%3}, {%4,%5,%6,%7}, {%8,%9}, {%0,%1,%2,%3};"
                 : "+f"(c[0]), "+f"(c[1]), "+f"(c[2]), "+f"(c[3])
                 : "r"(a[0]), "r"(a[1]), "r"(a[2]), "r"(a[3]), "r"(b[0]), "r"(b[1]));
}
__device__ __forceinline__ void imma16832(int* c, const uint32_t* a, const uint32_t* b) {
    asm volatile("mma.sync.aligned.m16n8k32.row.col.s32.s8.s8.s32 "
                 "{%0,%1,%2,%3}, {%4,%5,%6,%7}, {%8,%9}, {%0,%1,%2,%3};"
                 : "+r"(c[0]), "+r"(c[1]), "+r"(c[2]), "+r"(c[3])
                 : "r"(a[0]), "r"(a[1]), "r"(a[2]), "r"(a[3]), "r"(b[0]), "r"(b[1]));
}
__device__ __forceinline__ void cpa16(uint32_t dst, const void* src) {
    asm volatile("cp.async.cg.shared.global [%0], [%1], 16;" :: "r"(dst), "l"(src));
}
__device__ __forceinline__ void cpa_commit() { asm volatile("cp.async.commit_group;" ::: "memory"); }
__device__ __forceinline__ void cpa_wait1() { asm volatile("cp.async.wait_group 1;" ::: "memory"); }
__device__ __forceinline__ void cpa_wait0() { asm volatile("cp.async.wait_group 0;" ::: "memory"); }

__device__ __forceinline__ float warp_min(float v) {
    #pragma unroll
    for (int o = 16; o; o >>= 1) v = fminf(v, __shfl_xor_sync(0xffffffffu, v, o));
    return v;
}
__device__ __forceinline__ float warp_max(float v) {
    #pragma unroll
    for (int o = 16; o; o >>= 1) v = fmaxf(v, __shfl_xor_sync(0xffffffffu, v, o));
    return v;
}
__device__ __forceinline__ float warp_sum(float v) {
    #pragma unroll
    for (int o = 16; o; o >>= 1) v += __shfl_xor_sync(0xffffffffu, v, o);
    return v;
}
__device__ __forceinline__ void split_bf(float v, bf16& h, bf16& l) {
    h = __float2bfloat16(v);
    l = __float2bfloat16(v - __bfloat162float(h));
}
__device__ __forceinline__ uint32_t swz(uint32_t off) { return off ^ ((off >> 3) & 0x70); }

// ---------------- small kernels ----------------
__global__ void zero_kernel(float* __restrict__ moe, int* __restrict__ cnt) {
    int i = blockIdx.x * 256 + threadIdx.x;
    if (i < TT * DD) moe[i] = 0.f;
    if (i < EE) cnt[i] = 0;
}

// weight quant -> int8 + scale
__global__ void quantw_i8(const float* __restrict__ w, int8_t* __restrict__ nq,
                          float* __restrict__ sc, int ngroups) {
    int g = blockIdx.x * 8 + (threadIdx.x >> 5);
    if (g >= ngroups) return;
    int lane = threadIdx.x & 31;
    float4 v = reinterpret_cast<const float4*>(w)[(size_t)g * 32 + lane];
    float mn = fminf(fminf(v.x, v.y), fminf(v.z, v.w));
    float mx = fmaxf(fmaxf(v.x, v.y), fmaxf(v.z, v.w));
    mn = warp_min(mn); mx = warp_max(mx);
    float scale = fmaxf(mx - mn, 1e-5f) / 15.0f;
    float base = fminf(fmaxf(rintf(-mn / scale), 0.f), 15.f);
    float r[4] = {v.x, v.y, v.z, v.w};
    char q4[4];
    #pragma unroll
    for (int j = 0; j < 4; j++) {
        float q = fminf(fmaxf(rintf(r[j] / scale) + base, 0.f), 15.f) - base;
        q4[j] = (char)(int)q;
    }
    size_t idx = (size_t)g * 128 + lane * 4;
    *reinterpret_cast<char4*>(nq + idx) = *reinterpret_cast<char4*>(q4);
    if (lane == 0) sc[g] = scale;
}

// weight quant -> bf16 integer + scale (O-proj)
__global__ void quantw_bf(const float* __restrict__ w, bf16* __restrict__ nq,
                          float* __restrict__ sc, int ngroups) {
    int g = blockIdx.x * 8 + (threadIdx.x >> 5);
    if (g >= ngroups) return;
    int lane = threadIdx.x & 31;
    float4 v = reinterpret_cast<const float4*>(w)[(size_t)g * 32 + lane];
    float mn = fminf(fminf(v.x, v.y), fminf(v.z, v.w));
    float mx = fmaxf(fmaxf(v.x, v.y), fmaxf(v.z, v.w));
    mn = warp_min(mn); mx = warp_max(mx);
    float scale = fmaxf(mx - mn, 1e-5f) / 15.0f;
    float base = fminf(fmaxf(rintf(-mn / scale), 0.f), 15.f);
    float r[4] = {v.x, v.y, v.z, v.w};
    bf16 n4[4];
    #pragma unroll
    for (int j = 0; j < 4; j++) {
        float q = fminf(fmaxf(rintf(r[j] / scale) + base, 0.f), 15.f) - base;
        n4[j] = __float2bfloat16(q);
    }
    size_t idx = (size_t)g * 128 + lane * 4;
    *reinterpret_cast<uint2*>(nq + idx) = *reinterpret_cast<uint2*>(n4);
    if (lane == 0) sc[g] = scale;
}

// rmsnorm -> int8 digit decomposition (+ optional f32 copy for router)
template<bool WF32>
__global__ void rms_i8_kernel(const float* __restrict__ x, const float* __restrict__ g,
                              float* __restrict__ f32o, int8_t* __restrict__ d1,
                              int8_t* __restrict__ d2, float* __restrict__ sr) {
    int row = blockIdx.x;
    const float* xr = x + (size_t)row * DD;
    __shared__ float sbuf[DD];
    __shared__ float red[256];
    float s = 0.f;
    for (int i = threadIdx.x; i < DD; i += 256) { float v = xr[i]; s += v * v; }
    red[threadIdx.x] = s; __syncthreads();
    for (int o2 = 128; o2; o2 >>= 1) {
        if (threadIdx.x < o2) red[threadIdx.x] += red[threadIdx.x + o2];
        __syncthreads();
    }
    float inv = rsqrtf(red[0] * (1.0f / DD) + 1e-5f);
    __syncthreads();
    float mx = 0.f;
    for (int i = threadIdx.x; i < DD; i += 256) {
        float v = xr[i] * inv * g[i];
        sbuf[i] = v;
        if (WF32) f32o[(size_t)row * DD + i] = v;
        mx = fmaxf(mx, fabsf(v));
    }
    red[threadIdx.x] = mx; __syncthreads();
    for (int o2 = 128; o2; o2 >>= 1) {
        if (threadIdx.x < o2) red[threadIdx.x] = fmaxf(red[threadIdx.x], red[threadIdx.x + o2]);
        __syncthreads();
    }
    float sc = fmaxf(red[0], 1e-30f) * (1.0f / 16256.0f);
    float r128 = 1.0f / (128.0f * sc), r1 = 1.0f / sc;
    for (int i = threadIdx.x; i < DD; i += 256) {
        float v = sbuf[i];
        float f1 = fminf(fmaxf(rintf(v * r128), -127.f), 127.f);
        float rr = v - f1 * (128.0f * sc);
        float f2 = fminf(fmaxf(rintf(rr * r1), -127.f), 127.f);
        d1[(size_t)row * DD + i] = (int8_t)(int)f1;
        d2[(size_t)row * DD + i] = (int8_t)(int)f2;
    }
    if (threadIdx.x == 0) sr[row] = sc;
}

// quantize gated up rows (fp32 -> digits) for w2 GEMM
__global__ void quant_up_kernel(const float* __restrict__ up, const int* __restrict__ cnt,
                                int8_t* __restrict__ d1, int8_t* __restrict__ d2,
                                float* __restrict__ sr) {
    int e = blockIdx.z, slot = blockIdx.y;
    if (slot >= cnt[e]) return;
    const float* r = up + ((size_t)e * TT + slot) * FFND;
    __shared__ float red[256];
    float mx = 0.f;
    for (int i = threadIdx.x; i < FFND; i += 256) mx = fmaxf(mx, fabsf(r[i]));
    red[threadIdx.x] = mx; __syncthreads();
    for (int o2 = 128; o2; o2 >>= 1) {
        if (threadIdx.x < o2) red[threadIdx.x] = fmaxf(red[threadIdx.x], red[threadIdx.x + o2]);
        __syncthreads();
    }
    float sc = fmaxf(red[0], 1e-30f) * (1.0f / 16256.0f);
    float r128 = 1.0f / (128.0f * sc), r1 = 1.0f / sc;
    size_t base = ((size_t)e * TT + slot) * FFND;
    for (int i = threadIdx.x; i < FFND; i += 256) {
        float v = r[i];
        float f1 = fminf(fmaxf(rintf(v * r128), -127.f), 127.f);
        float rr = v - f1 * (128.0f * sc);
        float f2 = fminf(fmaxf(rintf(rr * r1), -127.f), 127.f);
        d1[base + i] = (int8_t)(int)f1;
        d2[base + i] = (int8_t)(int)f2;
    }
    if (threadIdx.x == 0) sr[(size_t)e * TT + slot] = sc;
}

// ===== int8 IMMA GEMM: C = (s_row*(D1*128+D2)) @ (N*ws)^T =====
// MODE 0 dense store f32 | 2 gather-A store f32 | 5 gather-A, silu(C)*acc -> C in place |
// MODE 3 slot-A, scatter-add to token rows with weights
template<int MODE>
__global__ __launch_bounds__(256, 1) void gemm_i8(
    const int8_t* __restrict__ Ad1, const int8_t* __restrict__ Ad2,
    const float* __restrict__ Asr, size_t strideAsr, int lda, size_t strideA,
    const int8_t* __restrict__ Bn, const float* __restrict__ Bsc, int ldb,
    size_t strideB, size_t strideBs,
    float* C, int ldc, size_t strideC,
    int M, const int* __restrict__ Mptr, int K,
    const int* __restrict__ idx, const float* __restrict__ wts)
{
    int z = blockIdx.z;
    if (Mptr) M = Mptr[z];
    int m0 = blockIdx.y * 128;
    if (m0 >= M) return;
    int n0 = blockIdx.x * 128;
    int tid = threadIdx.x;
    int wid = tid >> 5, lid = tid & 31;

    extern __shared__ char smem[];
    uint32_t sb = smem_u32(smem);
    float* scs = reinterpret_cast<float*>(smem + I8_SC_OFF);
    const int* idxz = (MODE == 2 || MODE == 5 || MODE == 3) ? (idx + (size_t)z * TT)
                                                            : (const int*)nullptr;
    int G = K >> 7;

    for (int i = tid; i < G * 128; i += 256) {
        int g = i >> 7, c = i & 127;
        scs[i] = Bsc[strideBs * z + (size_t)(n0 + c) * G + g];
    }

    // per-thread cp.async slots: 3 tiles x 16KB / 256thr / 16B = 12 chunks
    const int8_t* srcA[4]; const int8_t* srcB[4];
    uint32_t dstA[4], dstB[4];
    ptrdiff_t dl2 = Ad2 - Ad1;
    #pragma unroll
    for (int ci = 0; ci < 4; ci++) {
        int gid = ci * 256 + tid;
        int r = (gid >> 3) & 127;
        int c8 = gid & 7;
        int row = m0 + r;
        if (row >= M) row = m0;
        int rg = (MODE == 2 || MODE == 5) ? idxz[row] : row;
        srcA[ci] = Ad1 + strideA * (size_t)z + (size_t)rg * lda + c8 * 16;
        dstA[ci] = swz((uint32_t)(r * 128 + c8 * 16));
        int gid2 = 2048 + gid;
        int r2 = (gid2 >> 3) & 127;
        int c82 = gid2 & 7;
        srcB[ci] = Bn + strideB * (size_t)z + (size_t)(n0 + r2) * ldb + c82 * 16;
        dstB[ci] = (uint32_t)(2 * TILE_BYTES) + swz((uint32_t)(r2 * 128 + c82 * 16));
    }

    int n_st = K >> 7;  // 128 k-elems per stage
    #pragma unroll 1
    for (int p = 0; p < 2 && p < n_st; p++) {
        uint32_t base = sb + p * I8_STAGE;
        size_t ko = (size_t)p * 128;
        #pragma unroll
        for (int ci = 0; ci < 4; ci++) {
            cpa16(base + dstA[ci], srcA[ci] + ko);
            cpa16(base + TILE_BYTES + dstA[ci], srcA[ci] + dl2 + ko);
            cpa16(base + dstB[ci], srcB[ci] + ko);
        }
        cpa_commit();
    }

    int wr = (wid & 3) * 32;
    int wc = (wid >> 2) * 64;
    int rowm = (lid & 7) + ((lid >> 3) & 1) * 8;
    int colb = (lid >> 4) * 16;

    float accf[2][8][4] = {};
    int ag1[2][8][4] = {};
    int ag2[2][8][4] = {};

    #pragma unroll 1
    for (int kt = 0; kt < n_st; kt++) {
        cpa_wait1();
        __syncthreads();
        if (kt + 2 < n_st) {
            int sl = (kt + 2) % 3;
            uint32_t base = sb + sl * I8_STAGE;
            size_t ko = (size_t)(kt + 2) * 128;
            #pragma unroll
            for (int ci = 0; ci < 4; ci++) {
                cpa16(base + dstA[ci], srcA[ci] + ko);
                cpa16(base + TILE_BYTES + dstA[ci], srcA[ci] + dl2 + ko);
                cpa16(base + dstB[ci], srcB[ci] + ko);
            }
            cpa_commit();
        }
        uint32_t sbase = sb + (kt % 3) * I8_STAGE;
        #pragma unroll
        for (int sub = 0; sub < 4; sub++) {
            int kb0 = sub * 32 + colb;
            uint32_t a1[2][4], a2[2][4], bn[8][2];
            #pragma unroll
            for (int i = 0; i < 2; i++) {
                uint32_t off = (uint32_t)((wr + i * 16 + rowm) * 128 + kb0);
                ldsm4(sbase + swz(off), a1[i][0], a1[i][1], a1[i][2], a1[i][3]);
                ldsm4(sbase + TILE_BYTES + swz(off), a2[i][0], a2[i][1], a2[i][2], a2[i][3]);
            }
            #pragma unroll
            for (int j = 0; j < 4; j++) {
                uint32_t off = (uint32_t)((wc + j * 16 + rowm) * 128 + kb0);
                uint32_t r0, r1, r2, r3;
                ldsm4(sbase + 2 * TILE_BYTES + swz(off), r0, r1, r2, r3);
                bn[j * 2][0] = r0; bn[j * 2][1] = r2;
                bn[j * 2 + 1][0] = r1; bn[j * 2 + 1][1] = r3;
            }
            #pragma unroll
            for (int i = 0; i < 2; i++)
                #pragma unroll
                for (int jn = 0; jn < 8; jn++) {
                    imma16832(ag1[i][jn], a1[i], bn[jn]);
                    imma16832(ag2[i][jn], a2[i], bn[jn]);
                }
        }
        // fold group kt
        #pragma unroll
        for (int jn = 0; jn < 8; jn++) {
            int c = wc + jn * 8 + (lid & 3) * 2;
            float s0 = scs[kt * 128 + c];
            float s1 = scs[kt * 128 + c + 1];
            #pragma unroll
            for (int i = 0; i < 2; i++) {
                accf[i][jn][0] += s0 * (float)(ag1[i][jn][0] * 128 + ag2[i][jn][0]);
                accf[i][jn][1] += s1 * (float)(ag1[i][jn][1] * 128 + ag2[i][jn][1]);
                accf[i][jn][2] += s0 * (float)(ag1[i][jn][2] * 128 + ag2[i][jn][2]);
                accf[i][jn][3] += s1 * (float)(ag1[i][jn][3] * 128 + ag2[i][jn][3]);
                ag1[i][jn][0] = 0; ag1[i][jn][1] = 0; ag1[i][jn][2] = 0; ag1[i][jn][3] = 0;
                ag2[i][jn][0] = 0; ag2[i][jn][1] = 0; ag2[i][jn][2] = 0; ag2[i][jn][3] = 0;
            }
        }
    }

    // epilogue
    #pragma unroll
    for (int i = 0; i < 2; i++) {
        #pragma unroll
        for (int half = 0; half < 2; half++) {
            int row = m0 + wr + i * 16 + (lid >> 2) + half * 8;
            if (row >= M) continue;
            int arow = (MODE == 2 || MODE == 5) ? idxz[row] : row;
            float srow = Asr[strideAsr * z + arow];
            #pragma unroll
            for (int jn = 0; jn < 8; jn++) {
                int cc = n0 + wc + jn * 8 + (lid & 3) * 2;
                float v0 = accf[i][jn][half * 2 + 0] * srow;
                float v1 = accf[i][jn][half * 2 + 1] * srow;
                if (MODE == 0 || MODE == 2) {
                    float* Cr = C + strideC * z + (size_t)row * ldc + cc;
                    *reinterpret_cast<float2*>(Cr) = make_float2(v0, v1);
                } else if (MODE == 5) {
                    float* Cr = C + strideC * z + (size_t)row * ldc + cc;
                    float a0 = Cr[0], a1 = Cr[1];
                    Cr[0] = (a0 / (1.f + expf(-a0))) * v0;
                    Cr[1] = (a1 / (1.f + expf(-a1))) * v1;
                } else {  // MODE 3
                    int tk = idxz[row];
                    float w = wts[(size_t)z * TT + row];
                    float* Cr = C + (size_t)tk * ldc + cc;
                    atomicAdd(Cr + 0, w * v0);
                    atomicAdd(Cr + 1, w * v1);
                }
            }
        }
    }
}

// ===== bf16x2 GEMM with integer bf16 weights (O-proj only, MODE1: +resid) =====
__global__ __launch_bounds__(256, 1) void gemm_bf(
    const bf16* __restrict__ Ahi, const bf16* __restrict__ Alo, int lda,
    const bf16* __restrict__ Bn, const float* __restrict__ Bsc, int ldb,
    float* __restrict__ C, int ldc, int M, int K, const float* __restrict__ resid)
{
    int m0 = blockIdx.y * 128;
    int n0 = blockIdx.x * 128;
    int tid = threadIdx.x;
    int wid = tid >> 5, lid = tid & 31;
    extern __shared__ char smem[];
    uint32_t sb = smem_u32(smem);
    float* scs = reinterpret_cast<float*>(smem + SC_OFF);
    int G = K >> 7;
    for (int i = tid; i < G * 128; i += 256) {
        int g = i >> 7, c = i & 127;
        scs[i] = Bsc[(size_t)(n0 + c) * G + g];
    }
    const bf16* srcA[4]; const bf16* srcB[4];
    uint32_t dstA[4], dstB[4];
    ptrdiff_t dlo = Alo - Ahi;
    #pragma unroll
    for (int ci = 0; ci < 4; ci++) {
        int gid = ci * 256 + tid;
        int r = (gid >> 3) & 127;
        int c8 = gid & 7;
        srcA[ci] = Ahi + (size_t)(m0 + r) * lda + c8 * 8;
        dstA[ci] = swz((uint32_t)(r * 128 + c8 * 16));
        int gid2 = 2048 + gid;
        int r2 = (gid2 >> 3) & 127;
        int c82 = gid2 & 7;
        srcB[ci] = Bn + (size_t)(n0 + r2) * ldb + c82 * 8;
        dstB[ci] = (uint32_t)(2 * TILE_BYTES) + swz((uint32_t)(r2 * 128 + c82 * 16));
    }
    int n_kt = K / KT;
    #pragma unroll 1
    for (int p = 0; p < STAGES - 1; p++) {
        uint32_t base = sb + p * STAGE_BYTES;
        size_t ko = (size_t)p * KT;
        #pragma unroll
        for (int ci = 0; ci < 4; ci++) {
            cpa16(base + dstA[ci], srcA[ci] + ko);
            cpa16(base + TILE_BYTES + dstA[ci], srcA[ci] + dlo + ko);
            cpa16(base + dstB[ci], srcB[ci] + ko);
        }
        cpa_commit();
    }
    int wr = (wid & 3) * 32;
    int wc = (wid >> 2) * 64;
    int rowm = (lid & 7) + ((lid >> 3) & 1) * 8;
    int colb = (lid >> 4) * 16;
    float acc[2][8][4] = {};
    float accg[2][8][4] = {};
    #pragma unroll 1
    for (int kt = 0; kt < n_kt; kt++) {
        cpa_wait1();
        __syncthreads();
        if (kt + STAGES - 1 < n_kt) {
            int sl = (kt + STAGES - 1) % STAGES;
            uint32_t base = sb + sl * STAGE_BYTES;
            size_t ko = (size_t)(kt + STAGES - 1) * KT;
            #pragma unroll
            for (int ci = 0; ci < 4; ci++) {
                cpa16(base + dstA[ci], srcA[ci] + ko);
                cpa16(base + TILE_BYTES + dstA[ci], srcA[ci] + dlo + ko);
                cpa16(base + dstB[ci], srcB[ci] + ko);
            }
            cpa_commit();
        }
        uint32_t sbase = sb + (kt % STAGES) * STAGE_BYTES;
        #pragma unroll
        for (int s16 = 0; s16 < 4; s16++) {
            int kb0 = s16 * 32 + colb;
            uint32_t ah[2][4], al[2][4], bn[8][2];
            #pragma unroll
            for (int i = 0; i < 2; i++) {
                uint32_t off = (uint32_t)((wr + i * 16 + rowm) * 128 + kb0);
                ldsm4(sbase + swz(off), ah[i][0], ah[i][1], ah[i][2], ah[i][3]);
                ldsm4(sbase + TILE_BYTES + swz(off), al[i][0], al[i][1], al[i][2], al[i][3]);
            }
            #pragma unroll
            for (int j = 0; j < 4; j++) {
                uint32_t off = (uint32_t)((wc + j * 16 + rowm) * 128 + kb0);
                uint32_t r0, r1, r2, r3;
                ldsm4(sbase + 2 * TILE_BYTES + swz(off), r0, r1, r2, r3);
                bn[j * 2][0] = r0; bn[j * 2][1] = r2;
                bn[j * 2 + 1][0] = r1; bn[j * 2 + 1][1] = r3;
            }
            #pragma unroll
            for (int i = 0; i < 2; i++)
                #pragma unroll
                for (int jn = 0; jn < 8; jn++) {
                    mma16816(accg[i][jn], ah[i], bn[jn]);
                    mma16816(accg[i][jn], al[i], bn[jn]);
                }
        }
        if (kt & 1) {
            int g = kt >> 1;
            #pragma unroll
            for (int jn = 0; jn < 8; jn++) {
                int c = wc + jn * 8 + (lid & 3) * 2;
                float s0 = scs[g * 128 + c];
                float s1 = scs[g * 128 + c + 1];
                #pragma unroll
                for (int i = 0; i < 2; i++) {
                    acc[i][jn][0] += s0 * accg[i][jn][0];
                    acc[i][jn][1] += s1 * accg[i][jn][1];
                    acc[i][jn][2] += s0 * accg[i][jn][2];
                    acc[i][jn][3] += s1 * accg[i][jn][3];
                    accg[i][jn][0] = 0.f; accg[i][jn][1] = 0.f;
                    accg[i][jn][2] = 0.f; accg[i][jn][3] = 0.f;
                }
            }
        }
    }
    #pragma unroll
    for (int i = 0; i < 2; i++)
        #pragma unroll
        for (int jn = 0; jn < 8; jn++) {
            int r0 = m0 + wr + i * 16 + (lid >> 2);
            int cc = n0 + wc + jn * 8 + (lid & 3) * 2;
            #pragma unroll
            for (int half = 0; half < 2; half++) {
                int row = r0 + half * 8;
                float v0 = acc[i][jn][half * 2 + 0] + resid[(size_t)row * ldc + cc];
                float v1 = acc[i][jn][half * 2 + 1] + resid[(size_t)row * ldc + cc + 1];
                *reinterpret_cast<float2*>(C + (size_t)row * ldc + cc) = make_float2(v0, v1);
            }
        }
}

// ---------------- RoPE / kv quant ----------------
__global__ void rope_q_kernel(const float* __restrict__ qkv,
                              bf16* __restrict__ qh, bf16* __restrict__ ql) {
    int rowid = blockIdx.x;
    int d = threadIdx.x;
    int t = rowid >> 3, hh = rowid & 7;
    __shared__ float sh[HDIM];
    sh[d] = qkv[(size_t)t * NQKV + hh * HDIM + d];
    __syncthreads();
    int pos = t & (SS - 1);
    int i = d & 63;
    float invf = expf(-13.815510557964274f * ((float)(2 * i) * (1.0f / HDIM)));
    float f = (float)pos * invf;
    float c = cosf(f), sn = sinf(f);
    float v = (d < 64) ? (sh[d] * c - sh[d + 64] * sn)
                       : (sh[d] * c + sh[d - 64] * sn);
    bf16 h, l; split_bf(v, h, l);
    qh[(size_t)rowid * HDIM + d] = h;
    ql[(size_t)rowid * HDIM + d] = l;
}

__global__ void quant_k_kernel(const float* __restrict__ qkv,
                               bf16* __restrict__ kh, bf16* __restrict__ kl) {
    int rowid = blockIdx.x;
    int d = threadIdx.x;
    int t = rowid >> 1, kvh = rowid & 1;
    float v = qkv[(size_t)t * NQKV + 1024 + kvh * HDIM + d];
    __shared__ float smn[HDIM], smx[HDIM], sh[HDIM];
    smn[d] = v; smx[d] = v; __syncthreads();
    for (int o2 = 64; o2; o2 >>= 1) {
        if (d < o2) {
            smn[d] = fminf(smn[d], smn[d + o2]);
            smx[d] = fmaxf(smx[d], smx[d + o2]);
        }
        __syncthreads();
    }
    float scale = fmaxf(smx[0] - smn[0], 1e-5f) / 15.0f;
    float base = fminf(fmaxf(rintf(-smn[0] / scale), 0.f), 15.f);
    float q = (fminf(fmaxf(rintf(v / scale) + base, 0.f), 15.f) - base) * scale;
    sh[d] = q; __syncthreads();
    int pos = t & (SS - 1);
    int i = d & 63;
    float invf = expf(-13.815510557964274f * ((float)(2 * i) * (1.0f / HDIM)));
    float f = (float)pos * invf;
    float c = cosf(f), sn = sinf(f);
    q = (d < 64) ? (sh[d] * c - sh[d + 64] * sn)
                 : (sh[d] * c + sh[d - 64] * sn);
    bf16 h, l; split_bf(q, h, l);
    kh[(size_t)rowid * HDIM + d] = h;
    kl[(size_t)rowid * HDIM + d] = l;
}

__global__ void quant_v_kernel(const float* __restrict__ qkv,
                               bf16* __restrict__ vn, float* __restrict__ vs) {
    int rowid = blockIdx.x;
    int d = threadIdx.x;
    int t = rowid >> 1, kvh = rowid & 1;
    float v = qkv[(size_t)t * NQKV + 1280 + kvh * HDIM + d];
    __shared__ float smn[HDIM], smx[HDIM];
    smn[d] = v; smx[d] = v; __syncthreads();
    for (int o2 = 64; o2; o2 >>= 1) {
        if (d < o2) {
            smn[d] = fminf(smn[d], smn[d + o2]);
            smx[d] = fmaxf(smx[d], smx[d + o2]);
        }
        __syncthreads();
    }
    float scale = fmaxf(smx[0] - smn[0], 1e-5f) / 15.0f;
    float base = fminf(fmaxf(rintf(-smn[0] / scale), 0.f), 15.f);
    float q = fminf(fmaxf(rintf(v / scale) + base, 0.f), 15.f) - base;
    vn[(size_t)rowid * HDIM + d] = __float2bfloat16(q);
    if (d == 0) vs[rowid] = scale;
}

// ---------------- TC scores ----------------
__global__ __launch_bounds__(256, 1) void scores_tc(
    const bf16* __restrict__ qh, const bf16* __restrict__ ql,
    const bf16* __restrict__ kh, const bf16* __restrict__ kl,
    float* __restrict__ sc)
{
    int z = blockIdx.z;
    int m0 = blockIdx.y * 128, n0 = blockIdx.x * 128;
    if (n0 > m0) return;
    int b = z >> 3, hh = z & 7, kvh = (z & 7) >> 2;
    int tid = threadIdx.x, wid = tid >> 5, lid = tid & 31;
    extern __shared__ char smem[];
    uint32_t sb = smem_u32(smem);

    const bf16* src[16]; uint32_t dst[16];
    #pragma unroll
    for (int ci = 0; ci < 16; ci++) {
        int gid = ci * 256 + tid;
        int t4 = gid >> 10;
        int r = (gid >> 3) & 127;
        int c8 = gid & 7;
        const bf16* p;
        if (t4 == 0)      p = qh + ((size_t)(b * SS + m0 + r) * HH + hh) * HDIM;
        else if (t4 == 1) p = ql + ((size_t)(b * SS + m0 + r) * HH + hh) * HDIM;
        else if (t4 == 2) p = kh + ((size_t)(b * SS + n0 + r) * KV + kvh) * HDIM;
        else              p = kl + ((size_t)(b * SS + n0 + r) * KV + kvh) * HDIM;
        src[ci] = p + c8 * 8;
        dst[ci] = (uint32_t)(t4 * TILE_BYTES) + swz((uint32_t)(r * 128 + c8 * 16));
    }
    #pragma unroll
    for (int ci = 0; ci < 16; ci++) cpa16(sb + dst[ci], src[ci]);
    cpa_commit();
    #pragma unroll
    for (int ci = 0; ci < 16; ci++) cpa16(sb + 4 * TILE_BYTES + dst[ci], src[ci] + 64);
    cpa_commit();

    int wr = (wid & 3) * 32;
    int wc = (wid >> 2) * 64;
    int rowm = (lid & 7) + ((lid >> 3) & 1) * 8;
    int colb = (lid >> 4) * 16;
    float acc[2][8][4] = {};

    #pragma unroll 1
    for (int ch = 0; ch < 2; ch++) {
        if (ch == 0) cpa_wait1(); else cpa_wait0();
        __syncthreads();
        uint32_t base = sb + ch * 4 * TILE_BYTES;
        #pragma unroll
        for (int s16 = 0; s16 < 4; s16++) {
            int kb0 = s16 * 32 + colb;
            uint32_t ah[2][4], al[2][4], bh[8][2], bl[8][2];
            #pragma unroll
            for (int i = 0; i < 2; i++) {
                uint32_t off = (uint32_t)((wr + i * 16 + rowm) * 128 + kb0);
                ldsm4(base + swz(off), ah[i][0], ah[i][1], ah[i][2], ah[i][3]);
                ldsm4(base + TILE_BYTES + swz(off), al[i][0], al[i][1], al[i][2], al[i][3]);
            }
            #pragma unroll
            for (int j = 0; j < 4; j++) {
                uint32_t off = (uint32_t)((wc + j * 16 + rowm) * 128 + kb0);
                uint32_t r0, r1, r2, r3;
                ldsm4(base + 2 * TILE_BYTES + swz(off), r0, r1, r2, r3);
                bh[j * 2][0] = r0; bh[j * 2][1] = r2;
                bh[j * 2 + 1][0] = r1; bh[j * 2 + 1][1] = r3;
                ldsm4(base + 3 * TILE_BYTES + swz(off), r0, r1, r2, r3);
                bl[j * 2][0] = r0; bl[j * 2][1] = r2;
                bl[j * 2 + 1][0] = r1; bl[j * 2 + 1][1] = r3;
            }
            #pragma unroll
            for (int i = 0; i < 2; i++)
                #pragma unroll
                for (int jn = 0; jn < 8; jn++) {
                    mma16816(acc[i][jn], ah[i], bh[jn]);
                    mma16816(acc[i][jn], ah[i], bl[jn]);
                    mma16816(acc[i][jn], al[i], bh[jn]);
                }
        }
    }
    const float scalef = 0.08838834764831845f;
    float* C = sc + (size_t)z * SS * SS;
    #pragma unroll
    for (int i = 0; i < 2; i++)
        #pragma unroll
        for (int jn = 0; jn < 8; jn++) {
            int r0 = m0 + wr + i * 16 + (lid >> 2);
            int cc = n0 + wc + jn * 8 + (lid & 3) * 2;
            #pragma unroll
            for (int half = 0; half < 2; half++) {
                int row = r0 + half * 8;
                float v0 = acc[i][jn][half * 2 + 0] * scalef;
                float v1 = acc[i][jn][half * 2 + 1] * scalef;
                *reinterpret_cast<float2*>(C + (size_t)row * SS + cc) = make_float2(v0, v1);
            }
        }
}

// ---------------- softmax ----------------
__global__ void softmax_kernel(float* __restrict__ sc, const float* __restrict__ vs,
                               bf16* __restrict__ ph, bf16* __restrict__ pl) {
    int r = blockIdx.x;
    int z = r >> 10;
    int s = r & (SS - 1);
    int b = z >> 3, kvh = (z & 7) >> 2;
    float* row = sc + (size_t)r * SS;
    int n = s + 1;
    __shared__ float sh[256];
    float m = -INFINITY;
    for (int i = threadIdx.x; i < n; i += 256) m = fmaxf(m, row[i]);
    sh[threadIdx.x] = m; __syncthreads();
    for (int o2 = 128; o2; o2 >>= 1) {
        if (threadIdx.x < o2) sh[threadIdx.x] = fmaxf(sh[threadIdx.x], sh[threadIdx.x + o2]);
        __syncthreads();
    }
    m = sh[0]; __syncthreads();
    float sum = 0.f;
    for (int i = threadIdx.x; i < n; i += 256) {
        float e = expf(row[i] - m);
        row[i] = e; sum += e;
    }
    sh[threadIdx.x] = sum; __syncthreads();
    for (int o2 = 128; o2; o2 >>= 1) {
        if (threadIdx.x < o2) sh[threadIdx.x] += sh[threadIdx.x + o2];
        __syncthreads();
    }
    float inv = 1.0f / sh[0];
    for (int i = threadIdx.x; i < SS; i += 256) {
        float p = (i < n) ? row[i] * inv : 0.f;
        float pv = p * vs[(size_t)((b * SS + i) * KV + kvh)];
        bf16 h, l; split_bf(pv, h, l);
        ph[(size_t)r * SS + i] = h;
        pl[(size_t)r * SS + i] = l;
    }
}

// ---------------- TC AV ----------------
__global__ __launch_bounds__(256, 1) void av_tc(
    const bf16* __restrict__ ph, const bf16* __restrict__ pl,
    const bf16* __restrict__ vn, bf16* __restrict__ oh, bf16* __restrict__ ol)
{
    int z = blockIdx.z;
    int b = z >> 3, hh = z & 7, kvh = (z & 7) >> 2;
    int m0 = blockIdx.y * 128;
    int tid = threadIdx.x, wid = tid >> 5, lid = tid & 31;
    extern __shared__ char smem[];
    uint32_t sb = smem_u32(smem);

    const bf16* srcP[4]; const bf16* srcV[4];
    uint32_t dstP[4], dstV[4];
    ptrdiff_t dpl = pl - ph;
    #pragma unroll
    for (int ci = 0; ci < 4; ci++) {
        int gid = ci * 256 + tid;
        int r = (gid >> 3) & 127;
        int c8 = gid & 7;
        srcP[ci] = ph + (size_t)z * SS * SS + (size_t)(m0 + r) * SS + c8 * 8;
        dstP[ci] = swz((uint32_t)(r * 128 + c8 * 16));
        int gid2 = 2048 + gid;
        int vrow = (gid2 >> 4) & 63;
        int c16 = gid2 & 15;
        int plane = c16 >> 3, cc8 = c16 & 7;
        srcV[ci] = vn + ((size_t)(b * SS + vrow) * KV + kvh) * HDIM + plane * 64 + cc8 * 8;
        dstV[ci] = (uint32_t)(2 * TILE_BYTES + plane * 8192) + swz((uint32_t)(vrow * 128 + cc8 * 16));
    }

    int n_ch = (m0 >> 6) + 2;
    #pragma unroll 1
    for (int p = 0; p < 2 && p < n_ch; p++) {
        uint32_t base = sb + p * AV_STAGE;
        #pragma unroll
        for (int ci = 0; ci < 4; ci++) {
            size_t ko = (size_t)p * KT;
            cpa16(base + dstP[ci], srcP[ci] + ko);
            cpa16(base + TILE_BYTES + dstP[ci], srcP[ci] + dpl + ko);
            cpa16(base + dstV[ci], srcV[ci] + ko * (KV * HDIM));
        }
        cpa_commit();
    }

    int wr = (wid & 3) * 32;
    int wc = (wid >> 2) * 64;
    int vplane = wc >> 6;
    int rowm = (lid & 7) + ((lid >> 3) & 1) * 8;
    int colb = (lid >> 4) * 16;
    float acc[2][8][4] = {};

    #pragma unroll 1
    for (int kt = 0; kt < n_ch; kt++) {
        cpa_wait1();
        __syncthreads();
        if (kt + 2 < n_ch) {
            int sl = (kt + 2) % 3;
            uint32_t base = sb + sl * AV_STAGE;
            size_t ko = (size_t)(kt + 2) * KT;
            #pragma unroll
            for (int ci = 0; ci < 4; ci++) {
                cpa16(base + dstP[ci], srcP[ci] + ko);
                cpa16(base + TILE_BYTES + dstP[ci], srcP[ci] + dpl + ko);
                cpa16(base + dstV[ci], srcV[ci] + ko * (KV * HDIM));
            }
            cpa_commit();
        }
        uint32_t sbase = sb + (kt % 3) * AV_STAGE;
        uint32_t vbase = sbase + 2 * TILE_BYTES + vplane * 8192;
        #pragma unroll
        for (int s16 = 0; s16 < 4; s16++) {
            int kb0 = s16 * 32 + colb;
            uint32_t ah[2][4], al[2][4], bv[8][2];
            #pragma unroll
            for (int i = 0; i < 2; i++) {
                uint32_t off = (uint32_t)((wr + i * 16 + rowm) * 128 + kb0);
                ldsm4(sbase + swz(off), ah[i][0], ah[i][1], ah[i][2], ah[i][3]);
                ldsm4(sbase + TILE_BYTES + swz(off), al[i][0], al[i][1], al[i][2], al[i][3]);
            }
            #pragma unroll
            for (int j16 = 0; j16 < 4; j16++) {
                uint32_t krow = (uint32_t)(s16 * 16 + (lid & 7) + 8 * ((lid >> 3) & 1));
                uint32_t off = krow * 128 + (uint32_t)(j16 * 32 + 16 * (lid >> 4));
                uint32_t r0, r1, r2, r3;
                ldsm4t(vbase + swz(off), r0, r1, r2, r3);
                bv[j16 * 2][0] = r0; bv[j16 * 2][1] = r1;
                bv[j16 * 2 + 1][0] = r2; bv[j16 * 2 + 1][1] = r3;
            }
            #pragma unroll
            for (int i = 0; i < 2; i++)
                #pragma unroll
                for (int jn = 0; jn < 8; jn++) {
                    mma16816(acc[i][jn], ah[i], bv[jn]);
                    mma16816(acc[i][jn], al[i], bv[jn]);
                }
        }
    }

    #pragma unroll
    for (int i = 0; i < 2; i++)
        #pragma unroll
        for (int jn = 0; jn < 8; jn++) {
            int r0 = m0 + wr + i * 16 + (lid >> 2);
            int cc = wc + jn * 8 + (lid & 3) * 2;
            #pragma unroll
            for (int half = 0; half < 2; half++) {
                int row = r0 + half * 8;
                float v0 = acc[i][jn][half * 2 + 0];
                float v1 = acc[i][jn][half * 2 + 1];
                size_t o = ((size_t)(b * SS + row) * HH + hh) * HDIM + cc;
                bf16 h0, l0, h1, l1;
                split_bf(v0, h0, l0); split_bf(v1, h1, l1);
                oh[o] = h0; oh[o + 1] = h1;
                ol[o] = l0; ol[o + 1] = l1;
            }
        }
}

// ---------------- router ----------------
__global__ __launch_bounds__(256) void router_kernel(
    const float* __restrict__ hn, const float* __restrict__ wg)
{
    int tkn = blockIdx.x;
    int w = threadIdx.x >> 5, lane = threadIdx.x & 31;
    const float* x = hn + (size_t)tkn * DD;
    const float* g = wg + (size_t)w * DD;
    float s = 0.f;
    for (int i = lane; i < DD; i += 32) s += x[i] * g[i];
    s = warp_sum(s);
    __shared__ float lg[EE];
    if (lane == 0) lg[w] = s;
    __syncthreads();
    if (threadIdx.x == 0) {
        float m = -INFINITY;
        #pragma unroll
        for (int e = 0; e < EE; e++) m = fmaxf(m, lg[e]);
        float ex[EE];
        #pragma unroll
        for (int e = 0; e < EE; e++) ex[e] = expf(lg[e] - m);
        int i1 = 0; float m1 = ex[0];
        #pragma unroll
        for (int e = 1; e < EE; e++) if (ex[e] > m1) { m1 = ex[e]; i1 = e; }
        int i2 = -1; float m2 = -1.f;
        #pragma unroll
        for (int e = 0; e < EE; e++) if (e != i1 && ex[e] > m2) { m2 = ex[e]; i2 = e; }
        float inv = 1.0f / (m1 + m2);
        int p1 = atomicAdd(&g_cnt[i1], 1);
        g_tok[i1 * TT + p1] = tkn; g_twt[i1 * TT + p1] = m1 * inv;
        int p2 = atomicAdd(&g_cnt[i2], 1);
        g_tok[i2 * TT + p2] = tkn; g_twt[i2 * TT + p2] = m2 * inv;
    }
}

__global__ void final_add_kernel(const float* __restrict__ h, const float* __restrict__ moe,
                                 float* __restrict__ out) {
    int i = blockIdx.x * 256 + threadIdx.x;
    out[i] = h[i] + moe[i];
}

// ======================= host =======================
extern "C" void kernel_launch(void* const* d_in, const int* in_sizes, int n_in,
                              void* d_out, int out_size) {
    const float* hidden = (const float*)d_in[0];
    const float* w_q    = (const float*)d_in[1];
    const float* w_k    = (const float*)d_in[2];
    const float* w_v    = (const float*)d_in[3];
    const float* w_o    = (const float*)d_in[4];
    const float* g1     = (const float*)d_in[5];
    const float* g2     = (const float*)d_in[6];
    const float* w_gate = (const float*)d_in[7];
    const float* w1     = (const float*)d_in[8];
    const float* w3     = (const float*)d_in[9];
    const float* w2     = (const float*)d_in[10];
    float* out = (float*)d_out;

    int8_t *p_wqkv8, *p_w18, *p_w38, *p_w28;
    float *p_wqkvs, *p_w1s, *p_w3s, *p_w2s, *p_wos;
    bf16 *p_won, *p_oh, *p_ol, *p_qh, *p_ql, *p_kh, *p_kl, *p_vn, *p_ph, *p_pl;
    int8_t *p_xd1, *p_xd2, *p_hd1, *p_hd2, *p_ud1, *p_ud2;
    float *p_xsr, *p_hsr, *p_usr;
    float *p_qkv, *p_vs, *p_sc, *p_h, *p_hn, *p_up1, *p_moe, *p_twt;
    int *p_cnt, *p_tok;
    cudaGetSymbolAddress((void**)&p_wqkv8, g_wqkv8); cudaGetSymbolAddress((void**)&p_wqkvs, g_wqkvs);
    cudaGetSymbolAddress((void**)&p_w18, g_w18); cudaGetSymbolAddress((void**)&p_w1s, g_w1s);
    cudaGetSymbolAddress((void**)&p_w38, g_w38); cudaGetSymbolAddress((void**)&p_w3s, g_w3s);
    cudaGetSymbolAddress((void**)&p_w28, g_w28); cudaGetSymbolAddress((void**)&p_w2s, g_w2s);
    cudaGetSymbolAddress((void**)&p_won, g_won); cudaGetSymbolAddress((void**)&p_wos, g_wos);
    cudaGetSymbolAddress((void**)&p_xd1, g_xd1); cudaGetSymbolAddress((void**)&p_xd2, g_xd2);
    cudaGetSymbolAddress((void**)&p_xsr, g_xsr);
    cudaGetSymbolAddress((void**)&p_hd1, g_hd1); cudaGetSymbolAddress((void**)&p_hd2, g_hd2);
    cudaGetSymbolAddress((void**)&p_hsr, g_hsr);
    cudaGetSymbolAddress((void**)&p_ud1, g_ud1); cudaGetSymbolAddress((void**)&p_ud2, g_ud2);
    cudaGetSymbolAddress((void**)&p_usr, g_usr);
    cudaGetSymbolAddress((void**)&p_oh, g_oh);   cudaGetSymbolAddress((void**)&p_ol, g_ol);
    cudaGetSymbolAddress((void**)&p_qkv, g_qkv);
    cudaGetSymbolAddress((void**)&p_qh, g_qh);   cudaGetSymbolAddress((void**)&p_ql, g_ql);
    cudaGetSymbolAddress((void**)&p_kh, g_kh);   cudaGetSymbolAddress((void**)&p_kl, g_kl);
    cudaGetSymbolAddress((void**)&p_vn, g_vn);   cudaGetSymbolAddress((void**)&p_vs, g_vs);
    cudaGetSymbolAddress((void**)&p_sc, g_sc);
    cudaGetSymbolAddress((void**)&p_ph, g_ph);   cudaGetSymbolAddress((void**)&p_pl, g_pl);
    cudaGetSymbolAddress((void**)&p_h, g_h);     cudaGetSymbolAddress((void**)&p_hn, g_hn);
    cudaGetSymbolAddress((void**)&p_up1, g_up1); cudaGetSymbolAddress((void**)&p_moe, g_moe);
    cudaGetSymbolAddress((void**)&p_cnt, g_cnt); cudaGetSymbolAddress((void**)&p_tok, g_tok);
    cudaGetSymbolAddress((void**)&p_twt, g_twt);

    cudaFuncSetAttribute(gemm_i8<0>, cudaFuncAttributeMaxDynamicSharedMemorySize, I8_SMEM);
    cudaFuncSetAttribute(gemm_i8<2>, cudaFuncAttributeMaxDynamicSharedMemorySize, I8_SMEM);
    cudaFuncSetAttribute(gemm_i8<5>, cudaFuncAttributeMaxDynamicSharedMemorySize, I8_SMEM);
    cudaFuncSetAttribute(gemm_i8<3>, cudaFuncAttributeMaxDynamicSharedMemorySize, I8_SMEM);
    cudaFuncSetAttribute(gemm_bf, cudaFuncAttributeMaxDynamicSharedMemorySize, SMEM_SZ);
    cudaFuncSetAttribute(scores_tc, cudaFuncAttributeMaxDynamicSharedMemorySize, SCR_SMEM);
    cudaFuncSetAttribute(av_tc, cudaFuncAttributeMaxDynamicSharedMemorySize, AV_SMEM);

    zero_kernel<<<8192, 256>>>(p_moe, p_cnt);

    quantw_i8<<<1024, 256>>>(w_q, p_wqkv8, p_wqkvs, DD * DD / 128);
    quantw_i8<<<256, 256>>>(w_k, p_wqkv8 + 1024 * DD, p_wqkvs + 1024 * 8, KV * HDIM * DD / 128);
    quantw_i8<<<256, 256>>>(w_v, p_wqkv8 + 1280 * DD, p_wqkvs + 1280 * 8, KV * HDIM * DD / 128);
    quantw_bf<<<1024, 256>>>(w_o, p_won, p_wos, DD * DD / 128);
    quantw_i8<<<28672, 256>>>(w1, p_w18, p_w1s, EE * FFND * DD / 128);
    quantw_i8<<<28672, 256>>>(w3, p_w38, p_w3s, EE * FFND * DD / 128);
    quantw_i8<<<28672, 256>>>(w2, p_w28, p_w2s, EE * DD * FFND / 128);

    // ---- attention ----
    rms_i8_kernel<false><<<TT, 256>>>(hidden, g1, nullptr, p_xd1, p_xd2, p_xsr);
    gemm_i8<0><<<dim3(12, 16, 1), 256, I8_SMEM>>>(p_xd1, p_xd2, p_xsr, 0, DD, 0,
        p_wqkv8, p_wqkvs, DD, 0, 0,
        p_qkv, NQKV, 0, TT, nullptr, DD, nullptr, nullptr);
    rope_q_kernel<<<TT * HH, HDIM>>>(p_qkv, p_qh, p_ql);
    quant_k_kernel<<<TT * KV, HDIM>>>(p_qkv, p_kh, p_kl);
    quant_v_kernel<<<TT * KV, HDIM>>>(p_qkv, p_vn, p_vs);
    scores_tc<<<dim3(8, 8, BB * HH), 256, SCR_SMEM>>>(p_qh, p_ql, p_kh, p_kl, p_sc);
    softmax_kernel<<<BB * HH * SS, 256>>>(p_sc, p_vs, p_ph, p_pl);
    av_tc<<<dim3(1, 8, BB * HH), 256, AV_SMEM>>>(p_ph, p_pl, p_vn, p_oh, p_ol);
    gemm_bf<<<dim3(8, 16, 1), 256, SMEM_SZ>>>(p_oh, p_ol, DD, p_won, p_wos, DD,
        p_h, DD, TT, DD, hidden);

    // ---- MoE ----
    rms_i8_kernel<true><<<TT, 256>>>(p_h, g2, p_hn, p_hd1, p_hd2, p_hsr);
    router_kernel<<<TT, 256>>>(p_hn, w_gate);
    gemm_i8<2><<<dim3(28, 16, EE), 256, I8_SMEM>>>(p_hd1, p_hd2, p_hsr, 0, DD, 0,
        p_w18, p_w1s, DD, (size_t)FFND * DD, (size_t)FFND * 8,
        p_up1, FFND, (size_t)TT * FFND, 0, p_cnt, DD, p_tok, nullptr);
    gemm_i8<5><<<dim3(28, 16, EE), 256, I8_SMEM>>>(p_hd1, p_hd2, p_hsr, 0, DD, 0,
        p_w38, p_w3s, DD, (size_t)FFND * DD, (size_t)FFND * 8,
        p_up1, FFND, (size_t)TT * FFND, 0, p_cnt, DD, p_tok, nullptr);
    quant_up_kernel<<<dim3(1, TT, EE), 256>>>(p_up1, p_cnt, p_ud1, p_ud2, p_usr);
    gemm_i8<3><<<dim3(8, 16, EE), 256, I8_SMEM>>>(p_ud1, p_ud2, p_usr, TT, FFND,
        (size_t)TT * FFND,
        p_w28, p_w2s, FFND, (size_t)DD * FFND, (size_t)DD * 28,
        p_moe, DD, 0, 0, p_cnt, FFND, p_tok, p_twt);
    final_add_kernel<<<8192, 256>>>(p_h, p_moe, out);
}

// round 10
// speedup vs baseline: 1.8568x; 1.8568x over previous
#include <cuda_runtime.h>
#include <cuda_bf16.h>
#include <math.h>
#include <stdint.h>

#define BB 2
#define SS 1024
#define TT 2048
#define DD 1024
#define HH 8
#define KV 2
#define HDIM 128
#define EE 8
#define FFND 3584
#define NQKV 1536

#define KT 64
#define STAGES 4
#define TILE_BYTES 16384
#define STAGE_BYTES (3 * TILE_BYTES)
#define SC_OFF (STAGES * STAGE_BYTES)
#define SMEM_SZ (SC_OFF + 28 * 128 * 4)          // 196608 + 14336 = 210944
// scores: 2 stages x 4 tiles x 16KB
#define SCR_SMEM (2 * 4 * TILE_BYTES)
// av: 3 stages x (Ph 16K + Pl 16K + V 16K)
#define AV_STAGE (3 * TILE_BYTES)
#define AV_SMEM (3 * AV_STAGE)

typedef __nv_bfloat16 bf16;

// weights: integer bf16 + per-group fp32 scale
__device__ bf16  g_wqkvn[NQKV * DD];       __device__ float g_wqkvs[NQKV * DD / 128];
__device__ bf16  g_won[DD * DD];           __device__ float g_wos[DD * DD / 128];
__device__ bf16  g_w1n[EE * FFND * DD];    __device__ float g_w1s[EE * FFND * DD / 128];
__device__ bf16  g_w3n[EE * FFND * DD];    __device__ float g_w3s[EE * FFND * DD / 128];
__device__ bf16  g_w2n[EE * DD * FFND];    __device__ float g_w2s[EE * DD * FFND / 128];
// activations
__device__ bf16 g_xnh[TT * DD];        __device__ bf16 g_xnl[TT * DD];
__device__ bf16 g_hnh[TT * DD];        __device__ bf16 g_hnl[TT * DD];
__device__ bf16 g_oh[TT * DD];         __device__ bf16 g_ol[TT * DD];
__device__ bf16 g_uph[EE * TT * FFND]; __device__ bf16 g_upl[EE * TT * FFND];
__device__ float g_qkv[TT * NQKV];
__device__ bf16 g_qh[TT * DD];         __device__ bf16 g_ql[TT * DD];
__device__ bf16 g_kh[TT * KV * HDIM];  __device__ bf16 g_kl[TT * KV * HDIM];
__device__ bf16 g_vn[TT * KV * HDIM];  __device__ float g_vs[TT * KV];
__device__ float g_sc[BB * HH * SS * SS];
__device__ bf16 g_ph[BB * HH * SS * SS];
__device__ bf16 g_pl[BB * HH * SS * SS];
__device__ float g_h[TT * DD];
__device__ float g_hn[TT * DD];
__device__ float g_up1[EE * TT * FFND];
__device__ float g_moe[TT * DD];
__device__ int   g_cnt[EE];
__device__ int   g_tok[EE * TT];
__device__ float g_twt[EE * TT];

// ---------------- ptx helpers ----------------
__device__ __forceinline__ uint32_t smem_u32(const void* p) {
    uint32_t a;
    asm("{ .reg .u64 t; cvta.to.shared.u64 t, %1; cvt.u32.u64 %0, t; }" : "=r"(a) : "l"(p));
    return a;
}
__device__ __forceinline__ void ldsm4(uint32_t a, uint32_t& r0, uint32_t& r1,
                                      uint32_t& r2, uint32_t& r3) {
    asm volatile("ldmatrix.sync.aligned.m8n8.x4.shared.b16 {%0,%1,%2,%3}, [%4];"
                 : "=r"(r0), "=r"(r1), "=r"(r2), "=r"(r3) : "r"(a));
}
__device__ __forceinline__ void ldsm4t(uint32_t a, uint32_t& r0, uint32_t& r1,
                                       uint32_t& r2, uint32_t& r3) {
    asm volatile("ldmatrix.sync.aligned.m8n8.x4.trans.shared.b16 {%0,%1,%2,%3}, [%4];"
                 : "=r"(r0), "=r"(r1), "=r"(r2), "=r"(r3) : "r"(a));
}
__device__ __forceinline__ void mma16816(float* c, const uint32_t* a, const uint32_t* b) {
    asm volatile("mma.sync.aligned.m16n8k16.row.col.f32.bf16.bf16.f32 "
                 "{%0,%1,%2,%3}, {%4,%5,%6,%7}, {%8,%9}, {%0,%1,%2,%3};"
                 : "+f"(c[0]), "+f"(c[1]), "+f"(c[2]), "+f"(c[3])
                 : "r"(a[0]), "r"(a[1]), "r"(a[2]), "r"(a[3]), "r"(b[0]), "r"(b[1]));
}
__device__ __forceinline__ void cpa16(uint32_t dst, const void* src) {
    asm volatile("cp.async.cg.shared.global [%0], [%1], 16;" :: "r"(dst), "l"(src));
}
__device__ __forceinline__ void cpa_commit() { asm volatile("cp.async.commit_group;" ::: "memory"); }
__device__ __forceinline__ void cpa_wait1() { asm volatile("cp.async.wait_group 1;" ::: "memory"); }
__device__ __forceinline__ void cpa_wait2() { asm volatile("cp.async.wait_group 2;" ::: "memory"); }
__device__ __forceinline__ void cpa_wait0() { asm volatile("cp.async.wait_group 0;" ::: "memory"); }

__device__ __forceinline__ float warp_min(float v) {
    #pragma unroll
    for (int o = 16; o; o >>= 1) v = fminf(v, __shfl_xor_sync(0xffffffffu, v, o));
    return v;
}
__device__ __forceinline__ float warp_max(float v) {
    #pragma unroll
    for (int o = 16; o; o >>= 1) v = fmaxf(v, __shfl_xor_sync(0xffffffffu, v, o));
    return v;
}
__device__ __forceinline__ float warp_sum(float v) {
    #pragma unroll
    for (int o = 16; o; o >>= 1) v += __shfl_xor_sync(0xffffffffu, v, o);
    return v;
}
__device__ __forceinline__ void split_bf(float v, bf16& h, bf16& l) {
    h = __float2bfloat16(v);
    l = __float2bfloat16(v - __bfloat162float(h));
}
__device__ __forceinline__ uint32_t swz(uint32_t off) { return off ^ ((off >> 3) & 0x70); }

// ---------------- small kernels ----------------
__global__ void zero_kernel(float* __restrict__ moe, int* __restrict__ cnt) {
    int i = blockIdx.x * 256 + threadIdx.x;
    if (i < TT * DD) moe[i] = 0.f;
    if (i < EE) cnt[i] = 0;
}

__global__ void quantw_kernel(const float* __restrict__ w, bf16* __restrict__ nq,
                              float* __restrict__ sc, int ngroups) {
    int g = blockIdx.x * 8 + (threadIdx.x >> 5);
    if (g >= ngroups) return;
    int lane = threadIdx.x & 31;
    float4 v = reinterpret_cast<const float4*>(w)[(size_t)g * 32 + lane];
    float mn = fminf(fminf(v.x, v.y), fminf(v.z, v.w));
    float mx = fmaxf(fmaxf(v.x, v.y), fmaxf(v.z, v.w));
    mn = warp_min(mn); mx = warp_max(mx);
    float scale = fmaxf(mx - mn, 1e-5f) / 15.0f;
    float base = fminf(fmaxf(rintf(-mn / scale), 0.f), 15.f);
    float r[4] = {v.x, v.y, v.z, v.w};
    bf16 n4[4];
    #pragma unroll
    for (int j = 0; j < 4; j++) {
        float q = fminf(fmaxf(rintf(r[j] / scale) + base, 0.f), 15.f) - base;
        n4[j] = __float2bfloat16(q);  // exact integer in [-15,15]
    }
    size_t idx = (size_t)g * 128 + lane * 4;
    *reinterpret_cast<uint2*>(nq + idx) = *reinterpret_cast<uint2*>(n4);
    if (lane == 0) sc[g] = scale;
}

template<bool WF32>
__global__ void rms_split_kernel(const float* __restrict__ x, const float* __restrict__ g,
                                 float* __restrict__ f32o, bf16* __restrict__ hi,
                                 bf16* __restrict__ lo) {
    int row = blockIdx.x;
    const float* xr = x + (size_t)row * DD;
    float s = 0.f;
    for (int i = threadIdx.x; i < DD; i += 256) { float v = xr[i]; s += v * v; }
    __shared__ float sh[256];
    sh[threadIdx.x] = s; __syncthreads();
    for (int o2 = 128; o2; o2 >>= 1) {
        if (threadIdx.x < o2) sh[threadIdx.x] += sh[threadIdx.x + o2];
        __syncthreads();
    }
    float inv = rsqrtf(sh[0] * (1.0f / DD) + 1e-5f);
    for (int i = threadIdx.x; i < DD; i += 256) {
        float v = xr[i] * inv * g[i];
        if (WF32) f32o[(size_t)row * DD + i] = v;
        bf16 h, l; split_bf(v, h, l);
        hi[(size_t)row * DD + i] = h;
        lo[(size_t)row * DD + i] = l;
    }
}

// ===== bf16x2 mma.sync GEMM with exact integer weights + per-group rescale =====
// MODE 0 store f32 | 1 +resid | 2 gather-A, M=Mptr[z] | 3 scatter-add w/ wts |
// MODE 4 gather-A, silu(resid)*acc split-> CH/CL
template<int MODE>
__global__ __launch_bounds__(256, 1) void gemm_tc(
    const bf16* __restrict__ Ahi, const bf16* __restrict__ Alo, int lda, size_t strideA,
    const bf16* __restrict__ Bn, const float* __restrict__ Bsc, int ldb,
    size_t strideB, size_t strideBs,
    float* __restrict__ C, bf16* __restrict__ CH, bf16* __restrict__ CL,
    int ldc, size_t strideC,
    int M, const int* __restrict__ Mptr, int K,
    const float* __restrict__ resid, const int* __restrict__ idx,
    const float* __restrict__ wts)
{
    int z = blockIdx.z;
    if (Mptr) M = Mptr[z];
    int m0 = blockIdx.y * 128;
    if (m0 >= M) return;
    int n0 = blockIdx.x * 128;
    int tid = threadIdx.x;
    int wid = tid >> 5, lid = tid & 31;

    extern __shared__ char smem[];
    uint32_t sb = smem_u32(smem);
    float* scs = reinterpret_cast<float*>(smem + SC_OFF);
    const int* idxz = (MODE >= 2) ? (idx + (size_t)z * TT) : (const int*)nullptr;
    int G = K >> 7;

    for (int i = tid; i < G * 128; i += 256) {
        int g = i >> 7, c = i & 127;
        scs[i] = Bsc[strideBs * z + (size_t)(n0 + c) * G + g];
    }

    const bf16* srcA[4]; const bf16* srcB[4];
    uint32_t dstA[4], dstB[4];
    ptrdiff_t dlo = Alo - Ahi;
    #pragma unroll
    for (int ci = 0; ci < 4; ci++) {
        int gid = ci * 256 + tid;
        int r = (gid >> 3) & 127;
        int c8 = gid & 7;
        int row = m0 + r;
        if (row >= M) row = m0;
        int rg = (MODE == 2 || MODE == 4) ? idxz[row] : row;
        srcA[ci] = Ahi + strideA * (size_t)z + (size_t)rg * lda + c8 * 8;
        dstA[ci] = swz((uint32_t)(r * 128 + c8 * 16));
        int gid2 = 2048 + gid;
        int r2 = (gid2 >> 3) & 127;
        int c82 = gid2 & 7;
        srcB[ci] = Bn + strideB * (size_t)z + (size_t)(n0 + r2) * ldb + c82 * 8;
        dstB[ci] = (uint32_t)(2 * TILE_BYTES) + swz((uint32_t)(r2 * 128 + c82 * 16));
    }

    int n_kt = K / KT;
    int npro = STAGES - 1; if (npro > n_kt) npro = n_kt;
    #pragma unroll 1
    for (int p = 0; p < npro; p++) {
        uint32_t base = sb + p * STAGE_BYTES;
        size_t ko = (size_t)p * KT;
        #pragma unroll
        for (int ci = 0; ci < 4; ci++) {
            cpa16(base + dstA[ci], srcA[ci] + ko);
            cpa16(base + TILE_BYTES + dstA[ci], srcA[ci] + dlo + ko);
            cpa16(base + dstB[ci], srcB[ci] + ko);
        }
        cpa_commit();
    }

    int wr = (wid & 3) * 32;
    int wc = (wid >> 2) * 64;
    int rowm = (lid & 7) + ((lid >> 3) & 1) * 8;
    int colb = (lid >> 4) * 16;

    float acc[2][8][4] = {};
    float accg[2][8][4] = {};

    #pragma unroll 1
    for (int kt = 0; kt < n_kt; kt++) {
        int pending = n_kt - kt - 1; if (pending > STAGES - 2) pending = STAGES - 2;
        if (pending >= 2) cpa_wait2();
        else if (pending == 1) cpa_wait1();
        else cpa_wait0();
        __syncthreads();
        if (kt + STAGES - 1 < n_kt) {
            int sl = (kt + STAGES - 1) % STAGES;
            uint32_t base = sb + sl * STAGE_BYTES;
            size_t ko = (size_t)(kt + STAGES - 1) * KT;
            #pragma unroll
            for (int ci = 0; ci < 4; ci++) {
                cpa16(base + dstA[ci], srcA[ci] + ko);
                cpa16(base + TILE_BYTES + dstA[ci], srcA[ci] + dlo + ko);
                cpa16(base + dstB[ci], srcB[ci] + ko);
            }
            cpa_commit();
        }
        uint32_t sbase = sb + (kt % STAGES) * STAGE_BYTES;
        #pragma unroll
        for (int s16 = 0; s16 < 4; s16++) {
            int kb0 = s16 * 32 + colb;
            uint32_t ah[2][4], al[2][4], bn[8][2];
            #pragma unroll
            for (int i = 0; i < 2; i++) {
                uint32_t off = (uint32_t)((wr + i * 16 + rowm) * 128 + kb0);
                ldsm4(sbase + swz(off), ah[i][0], ah[i][1], ah[i][2], ah[i][3]);
                ldsm4(sbase + TILE_BYTES + swz(off), al[i][0], al[i][1], al[i][2], al[i][3]);
            }
            #pragma unroll
            for (int j = 0; j < 4; j++) {
                uint32_t off = (uint32_t)((wc + j * 16 + rowm) * 128 + kb0);
                uint32_t r0, r1, r2, r3;
                ldsm4(sbase + 2 * TILE_BYTES + swz(off), r0, r1, r2, r3);
                bn[j * 2][0] = r0; bn[j * 2][1] = r2;
                bn[j * 2 + 1][0] = r1; bn[j * 2 + 1][1] = r3;
            }
            #pragma unroll
            for (int i = 0; i < 2; i++)
                #pragma unroll
                for (int jn = 0; jn < 8; jn++) {
                    mma16816(accg[i][jn], ah[i], bn[jn]);
                    mma16816(accg[i][jn], al[i], bn[jn]);
                }
        }
        if (kt & 1) {
            int g = kt >> 1;
            #pragma unroll
            for (int jn = 0; jn < 8; jn++) {
                int c = wc + jn * 8 + (lid & 3) * 2;
                float s0 = scs[g * 128 + c];
                float s1 = scs[g * 128 + c + 1];
                #pragma unroll
                for (int i = 0; i < 2; i++) {
                    acc[i][jn][0] += s0 * accg[i][jn][0];
                    acc[i][jn][1] += s1 * accg[i][jn][1];
                    acc[i][jn][2] += s0 * accg[i][jn][2];
                    acc[i][jn][3] += s1 * accg[i][jn][3];
                    accg[i][jn][0] = 0.f; accg[i][jn][1] = 0.f;
                    accg[i][jn][2] = 0.f; accg[i][jn][3] = 0.f;
                }
            }
        }
    }

    #pragma unroll
    for (int i = 0; i < 2; i++) {
        #pragma unroll
        for (int jn = 0; jn < 8; jn++) {
            int r0 = m0 + wr + i * 16 + (lid >> 2);
            int cc = n0 + wc + jn * 8 + (lid & 3) * 2;
            #pragma unroll
            for (int half = 0; half < 2; half++) {
                int row = r0 + half * 8;
                if (row >= M) continue;
                float v0 = acc[i][jn][half * 2 + 0];
                float v1 = acc[i][jn][half * 2 + 1];
                if (MODE == 0 || MODE == 1 || MODE == 2) {
                    float* Cr = C + strideC * z + (size_t)row * ldc + cc;
                    if (MODE == 1) {
                        const float* rr = resid + (size_t)row * ldc + cc;
                        v0 += rr[0]; v1 += rr[1];
                    }
                    *reinterpret_cast<float2*>(Cr) = make_float2(v0, v1);
                } else if (MODE == 3) {
                    int tk = idxz[row];
                    float w = wts[(size_t)z * TT + row];
                    float* Cr = C + (size_t)tk * ldc + cc;
                    atomicAdd(Cr + 0, w * v0);
                    atomicAdd(Cr + 1, w * v1);
                } else {  // MODE 4
                    const float* ar = resid + strideC * z + (size_t)row * ldc + cc;
                    float a0 = ar[0], a1 = ar[1];
                    float gv0 = (a0 / (1.f + expf(-a0))) * v0;
                    float gv1 = (a1 / (1.f + expf(-a1))) * v1;
                    bf16 h0, l0, h1, l1;
                    split_bf(gv0, h0, l0); split_bf(gv1, h1, l1);
                    size_t o = strideC * z + (size_t)row * ldc + cc;
                    CH[o] = h0; CH[o + 1] = h1;
                    CL[o] = l0; CL[o + 1] = l1;
                }
            }
        }
    }
}

// ---------------- fused q-rope / k-quant+rope / v-quant prep ----------------
__global__ void kvprep_kernel(const float* __restrict__ qkv,
                              bf16* __restrict__ qh, bf16* __restrict__ ql,
                              bf16* __restrict__ kh, bf16* __restrict__ kl,
                              bf16* __restrict__ vn, float* __restrict__ vs) {
    int j = blockIdx.x;
    int d = threadIdx.x;
    __shared__ float smn[HDIM], smx[HDIM], sh[HDIM];
    if (j < TT * HH) {
        // q rope
        int t = j >> 3, hh = j & 7;
        sh[d] = qkv[(size_t)t * NQKV + hh * HDIM + d];
        __syncthreads();
        int pos = t & (SS - 1);
        int i = d & 63;
        float invf = expf(-13.815510557964274f * ((float)(2 * i) * (1.0f / HDIM)));
        float f = (float)pos * invf;
        float c = cosf(f), sn = sinf(f);
        float v = (d < 64) ? (sh[d] * c - sh[d + 64] * sn)
                           : (sh[d] * c + sh[d - 64] * sn);
        bf16 h, l; split_bf(v, h, l);
        qh[(size_t)j * HDIM + d] = h;
        ql[(size_t)j * HDIM + d] = l;
        return;
    }
    int j2 = j - TT * HH;
    bool isK = j2 < TT * KV;
    int rowid = isK ? j2 : (j2 - TT * KV);
    int t = rowid >> 1, kvh = rowid & 1;
    float v = qkv[(size_t)t * NQKV + (isK ? 1024 : 1280) + kvh * HDIM + d];
    smn[d] = v; smx[d] = v; __syncthreads();
    for (int o2 = 64; o2; o2 >>= 1) {
        if (d < o2) {
            smn[d] = fminf(smn[d], smn[d + o2]);
            smx[d] = fmaxf(smx[d], smx[d + o2]);
        }
        __syncthreads();
    }
    float scale = fmaxf(smx[0] - smn[0], 1e-5f) / 15.0f;
    float base = fminf(fmaxf(rintf(-smn[0] / scale), 0.f), 15.f);
    float qn = fminf(fmaxf(rintf(v / scale) + base, 0.f), 15.f) - base;
    if (!isK) {
        vn[(size_t)rowid * HDIM + d] = __float2bfloat16(qn);  // exact integer
        if (d == 0) vs[rowid] = scale;
        return;
    }
    float q = qn * scale;
    sh[d] = q; __syncthreads();
    int pos = t & (SS - 1);
    int i = d & 63;
    float invf = expf(-13.815510557964274f * ((float)(2 * i) * (1.0f / HDIM)));
    float f = (float)pos * invf;
    float c = cosf(f), sn = sinf(f);
    q = (d < 64) ? (sh[d] * c - sh[d + 64] * sn)
                 : (sh[d] * c + sh[d - 64] * sn);
    bf16 h, l; split_bf(q, h, l);
    kh[(size_t)rowid * HDIM + d] = h;
    kl[(size_t)rowid * HDIM + d] = l;
}

// ---------------- TC scores ----------------
__global__ __launch_bounds__(256, 1) void scores_tc(
    const bf16* __restrict__ qh, const bf16* __restrict__ ql,
    const bf16* __restrict__ kh, const bf16* __restrict__ kl,
    float* __restrict__ sc)
{
    int z = blockIdx.z;
    int m0 = blockIdx.y * 128, n0 = blockIdx.x * 128;
    if (n0 > m0) return;
    int b = z >> 3, hh = z & 7, kvh = (z & 7) >> 2;
    int tid = threadIdx.x, wid = tid >> 5, lid = tid & 31;
    extern __shared__ char smem[];
    uint32_t sb = smem_u32(smem);

    const bf16* src[16]; uint32_t dst[16];
    #pragma unroll
    for (int ci = 0; ci < 16; ci++) {
        int gid = ci * 256 + tid;
        int t4 = gid >> 10;
        int r = (gid >> 3) & 127;
        int c8 = gid & 7;
        const bf16* p;
        if (t4 == 0)      p = qh + ((size_t)(b * SS + m0 + r) * HH + hh) * HDIM;
        else if (t4 == 1) p = ql + ((size_t)(b * SS + m0 + r) * HH + hh) * HDIM;
        else if (t4 == 2) p = kh + ((size_t)(b * SS + n0 + r) * KV + kvh) * HDIM;
        else              p = kl + ((size_t)(b * SS + n0 + r) * KV + kvh) * HDIM;
        src[ci] = p + c8 * 8;
        dst[ci] = (uint32_t)(t4 * TILE_BYTES) + swz((uint32_t)(r * 128 + c8 * 16));
    }
    #pragma unroll
    for (int ci = 0; ci < 16; ci++) cpa16(sb + dst[ci], src[ci]);
    cpa_commit();
    #pragma unroll
    for (int ci = 0; ci < 16; ci++) cpa16(sb + 4 * TILE_BYTES + dst[ci], src[ci] + 64);
    cpa_commit();

    int wr = (wid & 3) * 32;
    int wc = (wid >> 2) * 64;
    int rowm = (lid & 7) + ((lid >> 3) & 1) * 8;
    int colb = (lid >> 4) * 16;
    float acc[2][8][4] = {};

    #pragma unroll 1
    for (int ch = 0; ch < 2; ch++) {
        if (ch == 0) cpa_wait1(); else cpa_wait0();
        __syncthreads();
        uint32_t base = sb + ch * 4 * TILE_BYTES;
        #pragma unroll
        for (int s16 = 0; s16 < 4; s16++) {
            int kb0 = s16 * 32 + colb;
            uint32_t ah[2][4], al[2][4], bh[8][2], bl[8][2];
            #pragma unroll
            for (int i = 0; i < 2; i++) {
                uint32_t off = (uint32_t)((wr + i * 16 + rowm) * 128 + kb0);
                ldsm4(base + swz(off), ah[i][0], ah[i][1], ah[i][2], ah[i][3]);
                ldsm4(base + TILE_BYTES + swz(off), al[i][0], al[i][1], al[i][2], al[i][3]);
            }
            #pragma unroll
            for (int j = 0; j < 4; j++) {
                uint32_t off = (uint32_t)((wc + j * 16 + rowm) * 128 + kb0);
                uint32_t r0, r1, r2, r3;
                ldsm4(base + 2 * TILE_BYTES + swz(off), r0, r1, r2, r3);
                bh[j * 2][0] = r0; bh[j * 2][1] = r2;
                bh[j * 2 + 1][0] = r1; bh[j * 2 + 1][1] = r3;
                ldsm4(base + 3 * TILE_BYTES + swz(off), r0, r1, r2, r3);
                bl[j * 2][0] = r0; bl[j * 2][1] = r2;
                bl[j * 2 + 1][0] = r1; bl[j * 2 + 1][1] = r3;
            }
            #pragma unroll
            for (int i = 0; i < 2; i++)
                #pragma unroll
                for (int jn = 0; jn < 8; jn++) {
                    mma16816(acc[i][jn], ah[i], bh[jn]);
                    mma16816(acc[i][jn], ah[i], bl[jn]);
                    mma16816(acc[i][jn], al[i], bh[jn]);
                }
        }
    }
    const float scalef = 0.08838834764831845f;
    float* C = sc + (size_t)z * SS * SS;
    #pragma unroll
    for (int i = 0; i < 2; i++)
        #pragma unroll
        for (int jn = 0; jn < 8; jn++) {
            int r0 = m0 + wr + i * 16 + (lid >> 2);
            int cc = n0 + wc + jn * 8 + (lid & 3) * 2;
            #pragma unroll
            for (int half = 0; half < 2; half++) {
                int row = r0 + half * 8;
                float v0 = acc[i][jn][half * 2 + 0] * scalef;
                float v1 = acc[i][jn][half * 2 + 1] * scalef;
                *reinterpret_cast<float2*>(C + (size_t)row * SS + cc) = make_float2(v0, v1);
            }
        }
}

// ---------------- softmax ----------------
__global__ void softmax_kernel(float* __restrict__ sc, const float* __restrict__ vs,
                               bf16* __restrict__ ph, bf16* __restrict__ pl) {
    int r = blockIdx.x;
    int z = r >> 10;
    int s = r & (SS - 1);
    int b = z >> 3, kvh = (z & 7) >> 2;
    float* row = sc + (size_t)r * SS;
    int n = s + 1;
    __shared__ float sh[256];
    float m = -INFINITY;
    for (int i = threadIdx.x; i < n; i += 256) m = fmaxf(m, row[i]);
    sh[threadIdx.x] = m; __syncthreads();
    for (int o2 = 128; o2; o2 >>= 1) {
        if (threadIdx.x < o2) sh[threadIdx.x] = fmaxf(sh[threadIdx.x], sh[threadIdx.x + o2]);
        __syncthreads();
    }
    m = sh[0]; __syncthreads();
    float sum = 0.f;
    for (int i = threadIdx.x; i < n; i += 256) {
        float e = expf(row[i] - m);
        row[i] = e; sum += e;
    }
    sh[threadIdx.x] = sum; __syncthreads();
    for (int o2 = 128; o2; o2 >>= 1) {
        if (threadIdx.x < o2) sh[threadIdx.x] += sh[threadIdx.x + o2];
        __syncthreads();
    }
    float inv = 1.0f / sh[0];
    for (int i = threadIdx.x; i < SS; i += 256) {
        float p = (i < n) ? row[i] * inv : 0.f;
        float pv = p * vs[(size_t)((b * SS + i) * KV + kvh)];
        bf16 h, l; split_bf(pv, h, l);
        ph[(size_t)r * SS + i] = h;
        pl[(size_t)r * SS + i] = l;
    }
}

// ---------------- TC AV ----------------
__global__ __launch_bounds__(256, 1) void av_tc(
    const bf16* __restrict__ ph, const bf16* __restrict__ pl,
    const bf16* __restrict__ vn, bf16* __restrict__ oh, bf16* __restrict__ ol)
{
    int z = blockIdx.z;
    int b = z >> 3, hh = z & 7, kvh = (z & 7) >> 2;
    int m0 = blockIdx.y * 128;
    int tid = threadIdx.x, wid = tid >> 5, lid = tid & 31;
    extern __shared__ char smem[];
    uint32_t sb = smem_u32(smem);

    const bf16* srcP[4]; const bf16* srcV[4];
    uint32_t dstP[4], dstV[4];
    ptrdiff_t dpl = pl - ph;
    #pragma unroll
    for (int ci = 0; ci < 4; ci++) {
        int gid = ci * 256 + tid;
        int r = (gid >> 3) & 127;
        int c8 = gid & 7;
        srcP[ci] = ph + (size_t)z * SS * SS + (size_t)(m0 + r) * SS + c8 * 8;
        dstP[ci] = swz((uint32_t)(r * 128 + c8 * 16));
        int gid2 = 2048 + gid;
        int vrow = (gid2 >> 4) & 63;
        int c16 = gid2 & 15;
        int plane = c16 >> 3, cc8 = c16 & 7;
        srcV[ci] = vn + ((size_t)(b * SS + vrow) * KV + kvh) * HDIM + plane * 64 + cc8 * 8;
        dstV[ci] = (uint32_t)(2 * TILE_BYTES + plane * 8192) + swz((uint32_t)(vrow * 128 + cc8 * 16));
    }

    int n_ch = (m0 >> 6) + 2;
    #pragma unroll 1
    for (int p = 0; p < 2 && p < n_ch; p++) {
        uint32_t base = sb + p * AV_STAGE;
        #pragma unroll
        for (int ci = 0; ci < 4; ci++) {
            size_t ko = (size_t)p * KT;
            cpa16(base + dstP[ci], srcP[ci] + ko);
            cpa16(base + TILE_BYTES + dstP[ci], srcP[ci] + dpl + ko);
            cpa16(base + dstV[ci], srcV[ci] + ko * (KV * HDIM));
        }
        cpa_commit();
    }

    int wr = (wid & 3) * 32;
    int wc = (wid >> 2) * 64;
    int vplane = wc >> 6;
    int rowm = (lid & 7) + ((lid >> 3) & 1) * 8;
    int colb = (lid >> 4) * 16;
    float acc[2][8][4] = {};

    #pragma unroll 1
    for (int kt = 0; kt < n_ch; kt++) {
        cpa_wait1();
        __syncthreads();
        if (kt + 2 < n_ch) {
            int sl = (kt + 2) % 3;
            uint32_t base = sb + sl * AV_STAGE;
            size_t ko = (size_t)(kt + 2) * KT;
            #pragma unroll
            for (int ci = 0; ci < 4; ci++) {
                cpa16(base + dstP[ci], srcP[ci] + ko);
                cpa16(base + TILE_BYTES + dstP[ci], srcP[ci] + dpl + ko);
                cpa16(base + dstV[ci], srcV[ci] + ko * (KV * HDIM));
            }
            cpa_commit();
        }
        uint32_t sbase = sb + (kt % 3) * AV_STAGE;
        uint32_t vbase = sbase + 2 * TILE_BYTES + vplane * 8192;
        #pragma unroll
        for (int s16 = 0; s16 < 4; s16++) {
            int kb0 = s16 * 32 + colb;
            uint32_t ah[2][4], al[2][4], bv[8][2];
            #pragma unroll
            for (int i = 0; i < 2; i++) {
                uint32_t off = (uint32_t)((wr + i * 16 + rowm) * 128 + kb0);
                ldsm4(sbase + swz(off), ah[i][0], ah[i][1], ah[i][2], ah[i][3]);
                ldsm4(sbase + TILE_BYTES + swz(off), al[i][0], al[i][1], al[i][2], al[i][3]);
            }
            #pragma unroll
            for (int j16 = 0; j16 < 4; j16++) {
                uint32_t krow = (uint32_t)(s16 * 16 + (lid & 7) + 8 * ((lid >> 3) & 1));
                uint32_t off = krow * 128 + (uint32_t)(j16 * 32 + 16 * (lid >> 4));
                uint32_t r0, r1, r2, r3;
                ldsm4t(vbase + swz(off), r0, r1, r2, r3);
                bv[j16 * 2][0] = r0; bv[j16 * 2][1] = r1;
                bv[j16 * 2 + 1][0] = r2; bv[j16 * 2 + 1][1] = r3;
            }
            #pragma unroll
            for (int i = 0; i < 2; i++)
                #pragma unroll
                for (int jn = 0; jn < 8; jn++) {
                    mma16816(acc[i][jn], ah[i], bv[jn]);
                    mma16816(acc[i][jn], al[i], bv[jn]);
                }
        }
    }

    #pragma unroll
    for (int i = 0; i < 2; i++)
        #pragma unroll
        for (int jn = 0; jn < 8; jn++) {
            int r0 = m0 + wr + i * 16 + (lid >> 2);
            int cc = wc + jn * 8 + (lid & 3) * 2;
            #pragma unroll
            for (int half = 0; half < 2; half++) {
                int row = r0 + half * 8;
                float v0 = acc[i][jn][half * 2 + 0];
                float v1 = acc[i][jn][half * 2 + 1];
                size_t o = ((size_t)(b * SS + row) * HH + hh) * HDIM + cc;
                bf16 h0, l0, h1, l1;
                split_bf(v0, h0, l0); split_bf(v1, h1, l1);
                oh[o] = h0; oh[o + 1] = h1;
                ol[o] = l0; ol[o + 1] = l1;
            }
        }
}

// ---------------- router ----------------
__global__ __launch_bounds__(256) void router_kernel(
    const float* __restrict__ hn, const float* __restrict__ wg)
{
    int tkn = blockIdx.x;
    int w = threadIdx.x >> 5, lane = threadIdx.x & 31;
    const float* x = hn + (size_t)tkn * DD;
    const float* g = wg + (size_t)w * DD;
    float s = 0.f;
    for (int i = lane; i < DD; i += 32) s += x[i] * g[i];
    s = warp_sum(s);
    __shared__ float lg[EE];
    if (lane == 0) lg[w] = s;
    __syncthreads();
    if (threadIdx.x == 0) {
        float m = -INFINITY;
        #pragma unroll
        for (int e = 0; e < EE; e++) m = fmaxf(m, lg[e]);
        float ex[EE];
        #pragma unroll
        for (int e = 0; e < EE; e++) ex[e] = expf(lg[e] - m);
        int i1 = 0; float m1 = ex[0];
        #pragma unroll
        for (int e = 1; e < EE; e++) if (ex[e] > m1) { m1 = ex[e]; i1 = e; }
        int i2 = -1; float m2 = -1.f;
        #pragma unroll
        for (int e = 0; e < EE; e++) if (e != i1 && ex[e] > m2) { m2 = ex[e]; i2 = e; }
        float inv = 1.0f / (m1 + m2);
        int p1 = atomicAdd(&g_cnt[i1], 1);
        g_tok[i1 * TT + p1] = tkn; g_twt[i1 * TT + p1] = m1 * inv;
        int p2 = atomicAdd(&g_cnt[i2], 1);
        g_tok[i2 * TT + p2] = tkn; g_twt[i2 * TT + p2] = m2 * inv;
    }
}

__global__ void final_add_kernel(const float* __restrict__ h, const float* __restrict__ moe,
                                 float* __restrict__ out) {
    int i = blockIdx.x * 256 + threadIdx.x;
    out[i] = h[i] + moe[i];
}

// ======================= host =======================
extern "C" void kernel_launch(void* const* d_in, const int* in_sizes, int n_in,
                              void* d_out, int out_size) {
    const float* hidden = (const float*)d_in[0];
    const float* w_q    = (const float*)d_in[1];
    const float* w_k    = (const float*)d_in[2];
    const float* w_v    = (const float*)d_in[3];
    const float* w_o    = (const float*)d_in[4];
    const float* g1     = (const float*)d_in[5];
    const float* g2     = (const float*)d_in[6];
    const float* w_gate = (const float*)d_in[7];
    const float* w1     = (const float*)d_in[8];
    const float* w3     = (const float*)d_in[9];
    const float* w2     = (const float*)d_in[10];
    float* out = (float*)d_out;

    bf16 *p_wqkvn, *p_won, *p_w1n, *p_w3n, *p_w2n;
    float *p_wqkvs, *p_wos, *p_w1s, *p_w3s, *p_w2s;
    bf16 *p_hnh, *p_hnl, *p_oh, *p_ol, *p_uph, *p_upl;
    bf16 *p_xnh, *p_xnl;
    bf16 *p_qh, *p_ql, *p_kh, *p_kl, *p_vn, *p_ph, *p_pl;
    float *p_qkv, *p_vs, *p_sc, *p_h, *p_hn, *p_up1, *p_moe, *p_twt;
    int *p_cnt, *p_tok;
    cudaGetSymbolAddress((void**)&p_wqkvn, g_wqkvn); cudaGetSymbolAddress((void**)&p_wqkvs, g_wqkvs);
    cudaGetSymbolAddress((void**)&p_won, g_won); cudaGetSymbolAddress((void**)&p_wos, g_wos);
    cudaGetSymbolAddress((void**)&p_w1n, g_w1n); cudaGetSymbolAddress((void**)&p_w1s, g_w1s);
    cudaGetSymbolAddress((void**)&p_w3n, g_w3n); cudaGetSymbolAddress((void**)&p_w3s, g_w3s);
    cudaGetSymbolAddress((void**)&p_w2n, g_w2n); cudaGetSymbolAddress((void**)&p_w2s, g_w2s);
    cudaGetSymbolAddress((void**)&p_xnh, g_xnh); cudaGetSymbolAddress((void**)&p_xnl, g_xnl);
    cudaGetSymbolAddress((void**)&p_hnh, g_hnh); cudaGetSymbolAddress((void**)&p_hnl, g_hnl);
    cudaGetSymbolAddress((void**)&p_oh, g_oh);   cudaGetSymbolAddress((void**)&p_ol, g_ol);
    cudaGetSymbolAddress((void**)&p_uph, g_uph); cudaGetSymbolAddress((void**)&p_upl, g_upl);
    cudaGetSymbolAddress((void**)&p_qkv, g_qkv);
    cudaGetSymbolAddress((void**)&p_qh, g_qh);   cudaGetSymbolAddress((void**)&p_ql, g_ql);
    cudaGetSymbolAddress((void**)&p_kh, g_kh);   cudaGetSymbolAddress((void**)&p_kl, g_kl);
    cudaGetSymbolAddress((void**)&p_vn, g_vn);   cudaGetSymbolAddress((void**)&p_vs, g_vs);
    cudaGetSymbolAddress((void**)&p_sc, g_sc);
    cudaGetSymbolAddress((void**)&p_ph, g_ph);   cudaGetSymbolAddress((void**)&p_pl, g_pl);
    cudaGetSymbolAddress((void**)&p_h, g_h);     cudaGetSymbolAddress((void**)&p_hn, g_hn);
    cudaGetSymbolAddress((void**)&p_up1, g_up1); cudaGetSymbolAddress((void**)&p_moe, g_moe);
    cudaGetSymbolAddress((void**)&p_cnt, g_cnt); cudaGetSymbolAddress((void**)&p_tok, g_tok);
    cudaGetSymbolAddress((void**)&p_twt, g_twt);

    cudaFuncSetAttribute(gemm_tc<0>, cudaFuncAttributeMaxDynamicSharedMemorySize, SMEM_SZ);
    cudaFuncSetAttribute(gemm_tc<1>, cudaFuncAttributeMaxDynamicSharedMemorySize, SMEM_SZ);
    cudaFuncSetAttribute(gemm_tc<2>, cudaFuncAttributeMaxDynamicSharedMemorySize, SMEM_SZ);
    cudaFuncSetAttribute(gemm_tc<3>, cudaFuncAttributeMaxDynamicSharedMemorySize, SMEM_SZ);
    cudaFuncSetAttribute(gemm_tc<4>, cudaFuncAttributeMaxDynamicSharedMemorySize, SMEM_SZ);
    cudaFuncSetAttribute(scores_tc, cudaFuncAttributeMaxDynamicSharedMemorySize, SCR_SMEM);
    cudaFuncSetAttribute(av_tc, cudaFuncAttributeMaxDynamicSharedMemorySize, AV_SMEM);

    zero_kernel<<<8192, 256>>>(p_moe, p_cnt);

    quantw_kernel<<<1024, 256>>>(w_q, p_wqkvn, p_wqkvs, DD * DD / 128);
    quantw_kernel<<<256, 256>>>(w_k, p_wqkvn + 1024 * DD, p_wqkvs + 1024 * 8, KV * HDIM * DD / 128);
    quantw_kernel<<<256, 256>>>(w_v, p_wqkvn + 1280 * DD, p_wqkvs + 1280 * 8, KV * HDIM * DD / 128);
    quantw_kernel<<<1024, 256>>>(w_o, p_won, p_wos, DD * DD / 128);
    quantw_kernel<<<28672, 256>>>(w1, p_w1n, p_w1s, EE * FFND * DD / 128);
    quantw_kernel<<<28672, 256>>>(w3, p_w3n, p_w3s, EE * FFND * DD / 128);
    quantw_kernel<<<28672, 256>>>(w2, p_w2n, p_w2s, EE * DD * FFND / 128);

    // ---- attention ----
    rms_split_kernel<false><<<TT, 256>>>(hidden, g1, nullptr, p_xnh, p_xnl);
    gemm_tc<0><<<dim3(12, 16, 1), 256, SMEM_SZ>>>(p_xnh, p_xnl, DD, 0,
        p_wqkvn, p_wqkvs, DD, 0, 0,
        p_qkv, nullptr, nullptr, NQKV, 0, TT, nullptr, DD, nullptr, nullptr, nullptr);
    kvprep_kernel<<<TT * (HH + KV + KV), HDIM>>>(p_qkv, p_qh, p_ql, p_kh, p_kl, p_vn, p_vs);
    scores_tc<<<dim3(8, 8, BB * HH), 256, SCR_SMEM>>>(p_qh, p_ql, p_kh, p_kl, p_sc);
    softmax_kernel<<<BB * HH * SS, 256>>>(p_sc, p_vs, p_ph, p_pl);
    av_tc<<<dim3(1, 8, BB * HH), 256, AV_SMEM>>>(p_ph, p_pl, p_vn, p_oh, p_ol);
    gemm_tc<1><<<dim3(8, 16, 1), 256, SMEM_SZ>>>(p_oh, p_ol, DD, 0,
        p_won, p_wos, DD, 0, 0,
        p_h, nullptr, nullptr, DD, 0, TT, nullptr, DD, hidden, nullptr, nullptr);

    // ---- MoE ----
    rms_split_kernel<true><<<TT, 256>>>(p_h, g2, p_hn, p_hnh, p_hnl);
    router_kernel<<<TT, 256>>>(p_hn, w_gate);
    gemm_tc<2><<<dim3(28, 16, EE), 256, SMEM_SZ>>>(p_hnh, p_hnl, DD, 0,
        p_w1n, p_w1s, DD, (size_t)FFND * DD, (size_t)FFND * 8,
        p_up1, nullptr, nullptr, FFND, (size_t)TT * FFND,
        0, p_cnt, DD, nullptr, p_tok, nullptr);
    gemm_tc<4><<<dim3(28, 16, EE), 256, SMEM_SZ>>>(p_hnh, p_hnl, DD, 0,
        p_w3n, p_w3s, DD, (size_t)FFND * DD, (size_t)FFND * 8,
        nullptr, p_uph, p_upl, FFND, (size_t)TT * FFND,
        0, p_cnt, DD, p_up1, p_tok, nullptr);
    gemm_tc<3><<<dim3(8, 16, EE), 256, SMEM_SZ>>>(p_uph, p_upl, FFND, (size_t)TT * FFND,
        p_w2n, p_w2s, FFND, (size_t)DD * FFND, (size_t)DD * 28,
        p_moe, nullptr, nullptr, DD, 0,
        0, p_cnt, FFND, nullptr, p_tok, p_twt);
    final_add_kernel<<<8192, 256>>>(p_h, p_moe, out);
}

// round 12
// speedup vs baseline: 1.8641x; 1.0039x over previous
#include <cuda_runtime.h>
#include <cuda_bf16.h>
#include <math.h>
#include <stdint.h>

#define BB 2
#define SS 1024
#define TT 2048
#define DD 1024
#define HH 8
#define KV 2
#define HDIM 128
#define EE 8
#define FFND 3584
#define NQKV 1536

#define KT 64
#define STAGES 4
#define TILE_BYTES 16384
#define STAGE_BYTES (3 * TILE_BYTES)
#define SC_OFF (STAGES * STAGE_BYTES)
#define SMEM_SZ (SC_OFF + 28 * 128 * 4)
#define SCR_SMEM (2 * 4 * TILE_BYTES)
#define AV_STAGE (3 * TILE_BYTES)
#define AV_SMEM (3 * AV_STAGE)

typedef __nv_bfloat16 bf16;

// weights: integer bf16 + per-group fp32 scale
__device__ bf16  g_wqkvn[NQKV * DD];       __device__ float g_wqkvs[NQKV * DD / 128];
__device__ bf16  g_won[DD * DD];           __device__ float g_wos[DD * DD / 128];
__device__ bf16  g_w1n[EE * FFND * DD];    __device__ float g_w1s[EE * FFND * DD / 128];
__device__ bf16  g_w3n[EE * FFND * DD];    __device__ float g_w3s[EE * FFND * DD / 128];
__device__ bf16  g_w2n[EE * DD * FFND];    __device__ float g_w2s[EE * DD * FFND / 128];
// activations
__device__ bf16 g_xnh[TT * DD];        __device__ bf16 g_xnl[TT * DD];
__device__ bf16 g_hnh[TT * DD];        __device__ bf16 g_hnl[TT * DD];
__device__ bf16 g_oh[TT * DD];         __device__ bf16 g_ol[TT * DD];
__device__ bf16 g_uph[EE * TT * FFND]; __device__ bf16 g_upl[EE * TT * FFND];
__device__ float g_qkv[TT * NQKV];
__device__ bf16 g_qh[TT * DD];         __device__ bf16 g_ql[TT * DD];
__device__ bf16 g_kh[TT * KV * HDIM];  __device__ bf16 g_kl[TT * KV * HDIM];
__device__ bf16 g_vn[TT * KV * HDIM];  __device__ float g_vs[TT * KV];
__device__ float g_sc[BB * HH * SS * SS];
__device__ bf16 g_ph[BB * HH * SS * SS];
__device__ bf16 g_pl[BB * HH * SS * SS];
__device__ float g_h[TT * DD];
__device__ float g_hn[TT * DD];
__device__ float g_up1[EE * TT * FFND];
__device__ float g_moe[TT * DD];
__device__ int   g_cnt[EE];
__device__ int   g_tok[EE * TT];
__device__ float g_twt[EE * TT];

// ---------------- ptx helpers ----------------
__device__ __forceinline__ uint32_t smem_u32(const void* p) {
    uint32_t a;
    asm("{ .reg .u64 t; cvta.to.shared.u64 t, %1; cvt.u32.u64 %0, t; }" : "=r"(a) : "l"(p));
    return a;
}
__device__ __forceinline__ void ldsm4(uint32_t a, uint32_t& r0, uint32_t& r1,
                                      uint32_t& r2, uint32_t& r3) {
    asm volatile("ldmatrix.sync.aligned.m8n8.x4.shared.b16 {%0,%1,%2,%3}, [%4];"
                 : "=r"(r0), "=r"(r1), "=r"(r2), "=r"(r3) : "r"(a));
}
__device__ __forceinline__ void ldsm4t(uint32_t a, uint32_t& r0, uint32_t& r1,
                                       uint32_t& r2, uint32_t& r3) {
    asm volatile("ldmatrix.sync.aligned.m8n8.x4.trans.shared.b16 {%0,%1,%2,%3}, [%4];"
                 : "=r"(r0), "=r"(r1), "=r"(r2), "=r"(r3) : "r"(a));
}
__device__ __forceinline__ void mma16816(float* c, const uint32_t* a, const uint32_t* b) {
    asm volatile("mma.sync.aligned.m16n8k16.row.col.f32.bf16.bf16.f32 "
                 "{%0,%1,%2,%3}, {%4,%5,%6,%7}, {%8,%9}, {%0,%1,%2,%3};"
                 : "+f"(c[0]), "+f"(c[1]), "+f"(c[2]), "+f"(c[3])
                 : "r"(a[0]), "r"(a[1]), "r"(a[2]), "r"(a[3]), "r"(b[0]), "r"(b[1]));
}
__device__ __forceinline__ void cpa16(uint32_t dst, const void* src) {
    asm volatile("cp.async.cg.shared.global [%0], [%1], 16;" :: "r"(dst), "l"(src));
}
__device__ __forceinline__ void cpa_commit() { asm volatile("cp.async.commit_group;" ::: "memory"); }
__device__ __forceinline__ void cpa_wait0() { asm volatile("cp.async.wait_group 0;" ::: "memory"); }
__device__ __forceinline__ void cpa_wait1() { asm volatile("cp.async.wait_group 1;" ::: "memory"); }
__device__ __forceinline__ void cpa_wait2() { asm volatile("cp.async.wait_group 2;" ::: "memory"); }

__device__ __forceinline__ float warp_min(float v) {
    #pragma unroll
    for (int o = 16; o; o >>= 1) v = fminf(v, __shfl_xor_sync(0xffffffffu, v, o));
    return v;
}
__device__ __forceinline__ float warp_max(float v) {
    #pragma unroll
    for (int o = 16; o; o >>= 1) v = fmaxf(v, __shfl_xor_sync(0xffffffffu, v, o));
    return v;
}
__device__ __forceinline__ float warp_sum(float v) {
    #pragma unroll
    for (int o = 16; o; o >>= 1) v += __shfl_xor_sync(0xffffffffu, v, o);
    return v;
}
__device__ __forceinline__ void split_bf(float v, bf16& h, bf16& l) {
    h = __float2bfloat16(v);
    l = __float2bfloat16(v - __bfloat162float(h));
}
__device__ __forceinline__ uint32_t swz(uint32_t off) { return off ^ ((off >> 3) & 0x70); }

// ---------------- small kernels ----------------
__global__ void zero_kernel(float* __restrict__ moe, int* __restrict__ cnt) {
    int i = blockIdx.x * 256 + threadIdx.x;
    if (i < TT * DD) moe[i] = 0.f;
    if (i < EE) cnt[i] = 0;
}

__global__ void quantw_kernel(const float* __restrict__ w, bf16* __restrict__ nq,
                              float* __restrict__ sc, int ngroups) {
    int g = blockIdx.x * 8 + (threadIdx.x >> 5);
    if (g >= ngroups) return;
    int lane = threadIdx.x & 31;
    float4 v = reinterpret_cast<const float4*>(w)[(size_t)g * 32 + lane];
    float mn = fminf(fminf(v.x, v.y), fminf(v.z, v.w));
    float mx = fmaxf(fmaxf(v.x, v.y), fmaxf(v.z, v.w));
    mn = warp_min(mn); mx = warp_max(mx);
    float scale = fmaxf(mx - mn, 1e-5f) / 15.0f;
    float base = fminf(fmaxf(rintf(-mn / scale), 0.f), 15.f);
    float r[4] = {v.x, v.y, v.z, v.w};
    bf16 n4[4];
    #pragma unroll
    for (int j = 0; j < 4; j++) {
        float q = fminf(fmaxf(rintf(r[j] / scale) + base, 0.f), 15.f) - base;
        n4[j] = __float2bfloat16(q);  // exact integer in [-15,15]
    }
    size_t idx = (size_t)g * 128 + lane * 4;
    *reinterpret_cast<uint2*>(nq + idx) = *reinterpret_cast<uint2*>(n4);
    if (lane == 0) sc[g] = scale;
}

template<bool WF32>
__global__ void rms_split_kernel(const float* __restrict__ x, const float* __restrict__ g,
                                 float* __restrict__ f32o, bf16* __restrict__ hi,
                                 bf16* __restrict__ lo) {
    int row = blockIdx.x;
    const float* xr = x + (size_t)row * DD;
    float s = 0.f;
    for (int i = threadIdx.x; i < DD; i += 256) { float v = xr[i]; s += v * v; }
    __shared__ float sh[256];
    sh[threadIdx.x] = s; __syncthreads();
    for (int o2 = 128; o2; o2 >>= 1) {
        if (threadIdx.x < o2) sh[threadIdx.x] += sh[threadIdx.x + o2];
        __syncthreads();
    }
    float inv = rsqrtf(sh[0] * (1.0f / DD) + 1e-5f);
    for (int i = threadIdx.x; i < DD; i += 256) {
        float v = xr[i] * inv * g[i];
        if (WF32) f32o[(size_t)row * DD + i] = v;
        bf16 h, l; split_bf(v, h, l);
        hi[(size_t)row * DD + i] = h;
        lo[(size_t)row * DD + i] = l;
    }
}

// ===== bf16x2 mma.sync GEMM with exact integer weights + per-group rescale =====
template<int MODE>
__global__ __launch_bounds__(256, 1) void gemm_tc(
    const bf16* __restrict__ Ahi, const bf16* __restrict__ Alo, int lda, size_t strideA,
    const bf16* __restrict__ Bn, const float* __restrict__ Bsc, int ldb,
    size_t strideB, size_t strideBs,
    float* __restrict__ C, bf16* __restrict__ CH, bf16* __restrict__ CL,
    int ldc, size_t strideC,
    int M, const int* __restrict__ Mptr, int K,
    const float* __restrict__ resid, const int* __restrict__ idx,
    const float* __restrict__ wts)
{
    int z = blockIdx.z;
    if (Mptr) M = Mptr[z];
    int m0 = blockIdx.y * 128;
    if (m0 >= M) return;
    int n0 = blockIdx.x * 128;
    int tid = threadIdx.x;
    int wid = tid >> 5, lid = tid & 31;

    extern __shared__ char smem[];
    uint32_t sb = smem_u32(smem);
    float* scs = reinterpret_cast<float*>(smem + SC_OFF);
    const int* idxz = (MODE >= 2) ? (idx + (size_t)z * TT) : (const int*)nullptr;
    int G = K >> 7;

    for (int i = tid; i < G * 128; i += 256) {
        int g = i >> 7, c = i & 127;
        scs[i] = Bsc[strideBs * z + (size_t)(n0 + c) * G + g];
    }

    const bf16* srcA[4]; const bf16* srcB[4];
    uint32_t dstA[4], dstB[4];
    ptrdiff_t dlo = Alo - Ahi;
    #pragma unroll
    for (int ci = 0; ci < 4; ci++) {
        int gid = ci * 256 + tid;
        int r = (gid >> 3) & 127;
        int c8 = gid & 7;
        int row = m0 + r;
        if (row >= M) row = m0;
        int rg = (MODE == 2 || MODE == 4) ? idxz[row] : row;
        srcA[ci] = Ahi + strideA * (size_t)z + (size_t)rg * lda + c8 * 8;
        dstA[ci] = swz((uint32_t)(r * 128 + c8 * 16));
        int gid2 = 2048 + gid;
        int r2 = (gid2 >> 3) & 127;
        int c82 = gid2 & 7;
        srcB[ci] = Bn + strideB * (size_t)z + (size_t)(n0 + r2) * ldb + c82 * 8;
        dstB[ci] = (uint32_t)(2 * TILE_BYTES) + swz((uint32_t)(r2 * 128 + c82 * 16));
    }

    int n_kt = K / KT;
    int npro = STAGES - 1; if (npro > n_kt) npro = n_kt;
    #pragma unroll 1
    for (int p = 0; p < npro; p++) {
        uint32_t base = sb + p * STAGE_BYTES;
        size_t ko = (size_t)p * KT;
        #pragma unroll
        for (int ci = 0; ci < 4; ci++) {
            cpa16(base + dstA[ci], srcA[ci] + ko);
            cpa16(base + TILE_BYTES + dstA[ci], srcA[ci] + dlo + ko);
            cpa16(base + dstB[ci], srcB[ci] + ko);
        }
        cpa_commit();
    }

    int wr = (wid & 3) * 32;
    int wc = (wid >> 2) * 64;
    int rowm = (lid & 7) + ((lid >> 3) & 1) * 8;
    int colb = (lid >> 4) * 16;

    float acc[2][8][4] = {};
    float accg[2][8][4] = {};

    #pragma unroll 1
    for (int kt = 0; kt < n_kt; kt++) {
        int pending = n_kt - kt - 1; if (pending > STAGES - 2) pending = STAGES - 2;
        if (pending >= 2) cpa_wait2();
        else if (pending == 1) cpa_wait1();
        else cpa_wait0();
        __syncthreads();
        if (kt + STAGES - 1 < n_kt) {
            int sl = (kt + STAGES - 1) % STAGES;
            uint32_t base = sb + sl * STAGE_BYTES;
            size_t ko = (size_t)(kt + STAGES - 1) * KT;
            #pragma unroll
            for (int ci = 0; ci < 4; ci++) {
                cpa16(base + dstA[ci], srcA[ci] + ko);
                cpa16(base + TILE_BYTES + dstA[ci], srcA[ci] + dlo + ko);
                cpa16(base + dstB[ci], srcB[ci] + ko);
            }
            cpa_commit();
        }
        uint32_t sbase = sb + (kt % STAGES) * STAGE_BYTES;
        #pragma unroll
        for (int s16 = 0; s16 < 4; s16++) {
            int kb0 = s16 * 32 + colb;
            uint32_t ah[2][4], al[2][4], bn[8][2];
            #pragma unroll
            for (int i = 0; i < 2; i++) {
                uint32_t off = (uint32_t)((wr + i * 16 + rowm) * 128 + kb0);
                ldsm4(sbase + swz(off), ah[i][0], ah[i][1], ah[i][2], ah[i][3]);
                ldsm4(sbase + TILE_BYTES + swz(off), al[i][0], al[i][1], al[i][2], al[i][3]);
            }
            #pragma unroll
            for (int j = 0; j < 4; j++) {
                uint32_t off = (uint32_t)((wc + j * 16 + rowm) * 128 + kb0);
                uint32_t r0, r1, r2, r3;
                ldsm4(sbase + 2 * TILE_BYTES + swz(off), r0, r1, r2, r3);
                bn[j * 2][0] = r0; bn[j * 2][1] = r2;
                bn[j * 2 + 1][0] = r1; bn[j * 2 + 1][1] = r3;
            }
            #pragma unroll
            for (int i = 0; i < 2; i++)
                #pragma unroll
                for (int jn = 0; jn < 8; jn++) {
                    mma16816(accg[i][jn], ah[i], bn[jn]);
                    mma16816(accg[i][jn], al[i], bn[jn]);
                }
        }
        if (kt & 1) {
            int g = kt >> 1;
            #pragma unroll
            for (int jn = 0; jn < 8; jn++) {
                int c = wc + jn * 8 + (lid & 3) * 2;
                float s0 = scs[g * 128 + c];
                float s1 = scs[g * 128 + c + 1];
                #pragma unroll
                for (int i = 0; i < 2; i++) {
                    acc[i][jn][0] += s0 * accg[i][jn][0];
                    acc[i][jn][1] += s1 * accg[i][jn][1];
                    acc[i][jn][2] += s0 * accg[i][jn][2];
                    acc[i][jn][3] += s1 * accg[i][jn][3];
                    accg[i][jn][0] = 0.f; accg[i][jn][1] = 0.f;
                    accg[i][jn][2] = 0.f; accg[i][jn][3] = 0.f;
                }
            }
        }
    }

    #pragma unroll
    for (int i = 0; i < 2; i++) {
        #pragma unroll
        for (int jn = 0; jn < 8; jn++) {
            int r0 = m0 + wr + i * 16 + (lid >> 2);
            int cc = n0 + wc + jn * 8 + (lid & 3) * 2;
            #pragma unroll
            for (int half = 0; half < 2; half++) {
                int row = r0 + half * 8;
                if (row >= M) continue;
                float v0 = acc[i][jn][half * 2 + 0];
                float v1 = acc[i][jn][half * 2 + 1];
                if (MODE == 0 || MODE == 1 || MODE == 2) {
                    float* Cr = C + strideC * z + (size_t)row * ldc + cc;
                    if (MODE == 1) {
                        const float* rr = resid + (size_t)row * ldc + cc;
                        v0 += rr[0]; v1 += rr[1];
                    }
                    *reinterpret_cast<float2*>(Cr) = make_float2(v0, v1);
                } else if (MODE == 3) {
                    int tk = idxz[row];
                    float w = wts[(size_t)z * TT + row];
                    float* Cr = C + (size_t)tk * ldc + cc;
                    atomicAdd(Cr + 0, w * v0);
                    atomicAdd(Cr + 1, w * v1);
                } else {  // MODE 4
                    const float* ar = resid + strideC * z + (size_t)row * ldc + cc;
                    float a0 = ar[0], a1 = ar[1];
                    float gv0 = (a0 / (1.f + expf(-a0))) * v0;
                    float gv1 = (a1 / (1.f + expf(-a1))) * v1;
                    bf16 h0, l0, h1, l1;
                    split_bf(gv0, h0, l0); split_bf(gv1, h1, l1);
                    size_t o = strideC * z + (size_t)row * ldc + cc;
                    CH[o] = h0; CH[o + 1] = h1;
                    CL[o] = l0; CL[o + 1] = l1;
                }
            }
        }
    }
}

// ---------------- fused q-rope / k-quant+rope / v-quant prep ----------------
__global__ void kvprep_kernel(const float* __restrict__ qkv,
                              bf16* __restrict__ qh, bf16* __restrict__ ql,
                              bf16* __restrict__ kh, bf16* __restrict__ kl,
                              bf16* __restrict__ vn, float* __restrict__ vs) {
    int j = blockIdx.x;
    int d = threadIdx.x;
    __shared__ float smn[HDIM], smx[HDIM], sh[HDIM];
    if (j < TT * HH) {
        int t = j >> 3, hh = j & 7;
        sh[d] = qkv[(size_t)t * NQKV + hh * HDIM + d];
        __syncthreads();
        int pos = t & (SS - 1);
        int i = d & 63;
        float invf = expf(-13.815510557964274f * ((float)(2 * i) * (1.0f / HDIM)));
        float f = (float)pos * invf;
        float c = cosf(f), sn = sinf(f);
        float v = (d < 64) ? (sh[d] * c - sh[d + 64] * sn)
                           : (sh[d] * c + sh[d - 64] * sn);
        bf16 h, l; split_bf(v, h, l);
        qh[(size_t)j * HDIM + d] = h;
        ql[(size_t)j * HDIM + d] = l;
        return;
    }
    int j2 = j - TT * HH;
    bool isK = j2 < TT * KV;
    int rowid = isK ? j2 : (j2 - TT * KV);
    int t = rowid >> 1, kvh = rowid & 1;
    float v = qkv[(size_t)t * NQKV + (isK ? 1024 : 1280) + kvh * HDIM + d];
    smn[d] = v; smx[d] = v; __syncthreads();
    for (int o2 = 64; o2; o2 >>= 1) {
        if (d < o2) {
            smn[d] = fminf(smn[d], smn[d + o2]);
            smx[d] = fmaxf(smx[d], smx[d + o2]);
        }
        __syncthreads();
    }
    float scale = fmaxf(smx[0] - smn[0], 1e-5f) / 15.0f;
    float base = fminf(fmaxf(rintf(-smn[0] / scale), 0.f), 15.f);
    float qn = fminf(fmaxf(rintf(v / scale) + base, 0.f), 15.f) - base;
    if (!isK) {
        vn[(size_t)rowid * HDIM + d] = __float2bfloat16(qn);
        if (d == 0) vs[rowid] = scale;
        return;
    }
    float q = qn * scale;
    sh[d] = q; __syncthreads();
    int pos = t & (SS - 1);
    int i = d & 63;
    float invf = expf(-13.815510557964274f * ((float)(2 * i) * (1.0f / HDIM)));
    float f = (float)pos * invf;
    float c = cosf(f), sn = sinf(f);
    q = (d < 64) ? (sh[d] * c - sh[d + 64] * sn)
                 : (sh[d] * c + sh[d - 64] * sn);
    bf16 h, l; split_bf(q, h, l);
    kh[(size_t)rowid * HDIM + d] = h;
    kl[(size_t)rowid * HDIM + d] = l;
}

// ---------------- TC scores ----------------
__global__ __launch_bounds__(256, 1) void scores_tc(
    const bf16* __restrict__ qh, const bf16* __restrict__ ql,
    const bf16* __restrict__ kh, const bf16* __restrict__ kl,
    float* __restrict__ sc)
{
    int z = blockIdx.z;
    int m0 = blockIdx.y * 128, n0 = blockIdx.x * 128;
    if (n0 > m0) return;
    int b = z >> 3, hh = z & 7, kvh = (z & 7) >> 2;
    int tid = threadIdx.x, wid = tid >> 5, lid = tid & 31;
    extern __shared__ char smem[];
    uint32_t sb = smem_u32(smem);

    const bf16* src[16]; uint32_t dst[16];
    #pragma unroll
    for (int ci = 0; ci < 16; ci++) {
        int gid = ci * 256 + tid;
        int t4 = gid >> 10;
        int r = (gid >> 3) & 127;
        int c8 = gid & 7;
        const bf16* p;
        if (t4 == 0)      p = qh + ((size_t)(b * SS + m0 + r) * HH + hh) * HDIM;
        else if (t4 == 1) p = ql + ((size_t)(b * SS + m0 + r) * HH + hh) * HDIM;
        else if (t4 == 2) p = kh + ((size_t)(b * SS + n0 + r) * KV + kvh) * HDIM;
        else              p = kl + ((size_t)(b * SS + n0 + r) * KV + kvh) * HDIM;
        src[ci] = p + c8 * 8;
        dst[ci] = (uint32_t)(t4 * TILE_BYTES) + swz((uint32_t)(r * 128 + c8 * 16));
    }
    #pragma unroll
    for (int ci = 0; ci < 16; ci++) cpa16(sb + dst[ci], src[ci]);
    cpa_commit();
    #pragma unroll
    for (int ci = 0; ci < 16; ci++) cpa16(sb + 4 * TILE_BYTES + dst[ci], src[ci] + 64);
    cpa_commit();

    int wr = (wid & 3) * 32;
    int wc = (wid >> 2) * 64;
    int rowm = (lid & 7) + ((lid >> 3) & 1) * 8;
    int colb = (lid >> 4) * 16;
    float acc[2][8][4] = {};

    #pragma unroll 1
    for (int ch = 0; ch < 2; ch++) {
        if (ch == 0) cpa_wait1(); else cpa_wait0();
        __syncthreads();
        uint32_t base = sb + ch * 4 * TILE_BYTES;
        #pragma unroll
        for (int s16 = 0; s16 < 4; s16++) {
            int kb0 = s16 * 32 + colb;
            uint32_t ah[2][4], al[2][4], bh[8][2], bl[8][2];
            #pragma unroll
            for (int i = 0; i < 2; i++) {
                uint32_t off = (uint32_t)((wr + i * 16 + rowm) * 128 + kb0);
                ldsm4(base + swz(off), ah[i][0], ah[i][1], ah[i][2], ah[i][3]);
                ldsm4(base + TILE_BYTES + swz(off), al[i][0], al[i][1], al[i][2], al[i][3]);
            }
            #pragma unroll
            for (int j = 0; j < 4; j++) {
                uint32_t off = (uint32_t)((wc + j * 16 + rowm) * 128 + kb0);
                uint32_t r0, r1, r2, r3;
                ldsm4(base + 2 * TILE_BYTES + swz(off), r0, r1, r2, r3);
                bh[j * 2][0] = r0; bh[j * 2][1] = r2;
                bh[j * 2 + 1][0] = r1; bh[j * 2 + 1][1] = r3;
                ldsm4(base + 3 * TILE_BYTES + swz(off), r0, r1, r2, r3);
                bl[j * 2][0] = r0; bl[j * 2][1] = r2;
                bl[j * 2 + 1][0] = r1; bl[j * 2 + 1][1] = r3;
            }
            #pragma unroll
            for (int i = 0; i < 2; i++)
                #pragma unroll
                for (int jn = 0; jn < 8; jn++) {
                    mma16816(acc[i][jn], ah[i], bh[jn]);
                    mma16816(acc[i][jn], ah[i], bl[jn]);
                    mma16816(acc[i][jn], al[i], bh[jn]);
                }
        }
    }
    const float scalef = 0.08838834764831845f;
    float* C = sc + (size_t)z * SS * SS;
    #pragma unroll
    for (int i = 0; i < 2; i++)
        #pragma unroll
        for (int jn = 0; jn < 8; jn++) {
            int r0 = m0 + wr + i * 16 + (lid >> 2);
            int cc = n0 + wc + jn * 8 + (lid & 3) * 2;
            #pragma unroll
            for (int half = 0; half < 2; half++) {
                int row = r0 + half * 8;
                float v0 = acc[i][jn][half * 2 + 0] * scalef;
                float v1 = acc[i][jn][half * 2 + 1] * scalef;
                *reinterpret_cast<float2*>(C + (size_t)row * SS + cc) = make_float2(v0, v1);
            }
        }
}

// ---------------- softmax ----------------
__global__ void softmax_kernel(float* __restrict__ sc, const float* __restrict__ vs,
                               bf16* __restrict__ ph, bf16* __restrict__ pl) {
    int r = blockIdx.x;
    int z = r >> 10;
    int s = r & (SS - 1);
    int b = z >> 3, kvh = (z & 7) >> 2;
    float* row = sc + (size_t)r * SS;
    int n = s + 1;
    __shared__ float sh[256];
    float m = -INFINITY;
    for (int i = threadIdx.x; i < n; i += 256) m = fmaxf(m, row[i]);
    sh[threadIdx.x] = m; __syncthreads();
    for (int o2 = 128; o2; o2 >>= 1) {
        if (threadIdx.x < o2) sh[threadIdx.x] = fmaxf(sh[threadIdx.x], sh[threadIdx.x + o2]);
        __syncthreads();
    }
    m = sh[0]; __syncthreads();
    float sum = 0.f;
    for (int i = threadIdx.x; i < n; i += 256) {
        float e = expf(row[i] - m);
        row[i] = e; sum += e;
    }
    sh[threadIdx.x] = sum; __syncthreads();
    for (int o2 = 128; o2; o2 >>= 1) {
        if (threadIdx.x < o2) sh[threadIdx.x] += sh[threadIdx.x + o2];
        __syncthreads();
    }
    float inv = 1.0f / sh[0];
    for (int i = threadIdx.x; i < SS; i += 256) {
        float p = (i < n) ? row[i] * inv : 0.f;
        float pv = p * vs[(size_t)((b * SS + i) * KV + kvh)];
        bf16 h, l; split_bf(pv, h, l);
        ph[(size_t)r * SS + i] = h;
        pl[(size_t)r * SS + i] = l;
    }
}

// ---------------- TC AV ----------------
__global__ __launch_bounds__(256, 1) void av_tc(
    const bf16* __restrict__ ph, const bf16* __restrict__ pl,
    const bf16* __restrict__ vn, bf16* __restrict__ oh, bf16* __restrict__ ol)
{
    int z = blockIdx.z;
    int b = z >> 3, hh = z & 7, kvh = (z & 7) >> 2;
    int m0 = blockIdx.y * 128;
    int tid = threadIdx.x, wid = tid >> 5, lid = tid & 31;
    extern __shared__ char smem[];
    uint32_t sb = smem_u32(smem);

    const bf16* srcP[4]; const bf16* srcV[4];
    uint32_t dstP[4], dstV[4];
    ptrdiff_t dpl = pl - ph;
    #pragma unroll
    for (int ci = 0; ci < 4; ci++) {
        int gid = ci * 256 + tid;
        int r = (gid >> 3) & 127;
        int c8 = gid & 7;
        srcP[ci] = ph + (size_t)z * SS * SS + (size_t)(m0 + r) * SS + c8 * 8;
        dstP[ci] = swz((uint32_t)(r * 128 + c8 * 16));
        int gid2 = 2048 + gid;
        int vrow = (gid2 >> 4) & 63;
        int c16 = gid2 & 15;
        int plane = c16 >> 3, cc8 = c16 & 7;
        srcV[ci] = vn + ((size_t)(b * SS + vrow) * KV + kvh) * HDIM + plane * 64 + cc8 * 8;
        dstV[ci] = (uint32_t)(2 * TILE_BYTES + plane * 8192) + swz((uint32_t)(vrow * 128 + cc8 * 16));
    }

    int n_ch = (m0 >> 6) + 2;
    #pragma unroll 1
    for (int p = 0; p < 2 && p < n_ch; p++) {
        uint32_t base = sb + p * AV_STAGE;
        #pragma unroll
        for (int ci = 0; ci < 4; ci++) {
            size_t ko = (size_t)p * KT;
            cpa16(base + dstP[ci], srcP[ci] + ko);
            cpa16(base + TILE_BYTES + dstP[ci], srcP[ci] + dpl + ko);
            cpa16(base + dstV[ci], srcV[ci] + ko * (KV * HDIM));
        }
        cpa_commit();
    }

    int wr = (wid & 3) * 32;
    int wc = (wid >> 2) * 64;
    int vplane = wc >> 6;
    int rowm = (lid & 7) + ((lid >> 3) & 1) * 8;
    int colb = (lid >> 4) * 16;
    float acc[2][8][4] = {};

    #pragma unroll 1
    for (int kt = 0; kt < n_ch; kt++) {
        cpa_wait1();
        __syncthreads();
        if (kt + 2 < n_ch) {
            int sl = (kt + 2) % 3;
            uint32_t base = sb + sl * AV_STAGE;
            size_t ko = (size_t)(kt + 2) * KT;
            #pragma unroll
            for (int ci = 0; ci < 4; ci++) {
                cpa16(base + dstP[ci], srcP[ci] + ko);
                cpa16(base + TILE_BYTES + dstP[ci], srcP[ci] + dpl + ko);
                cpa16(base + dstV[ci], srcV[ci] + ko * (KV * HDIM));
            }
            cpa_commit();
        }
        uint32_t sbase = sb + (kt % 3) * AV_STAGE;
        uint32_t vbase = sbase + 2 * TILE_BYTES + vplane * 8192;
        #pragma unroll
        for (int s16 = 0; s16 < 4; s16++) {
            int kb0 = s16 * 32 + colb;
            uint32_t ah[2][4], al[2][4], bv[8][2];
            #pragma unroll
            for (int i = 0; i < 2; i++) {
                uint32_t off = (uint32_t)((wr + i * 16 + rowm) * 128 + kb0);
                ldsm4(sbase + swz(off), ah[i][0], ah[i][1], ah[i][2], ah[i][3]);
                ldsm4(sbase + TILE_BYTES + swz(off), al[i][0], al[i][1], al[i][2], al[i][3]);
            }
            #pragma unroll
            for (int j16 = 0; j16 < 4; j16++) {
                uint32_t krow = (uint32_t)(s16 * 16 + (lid & 7) + 8 * ((lid >> 3) & 1));
                uint32_t off = krow * 128 + (uint32_t)(j16 * 32 + 16 * (lid >> 4));
                uint32_t r0, r1, r2, r3;
                ldsm4t(vbase + swz(off), r0, r1, r2, r3);
                bv[j16 * 2][0] = r0; bv[j16 * 2][1] = r1;
                bv[j16 * 2 + 1][0] = r2; bv[j16 * 2 + 1][1] = r3;
            }
            #pragma unroll
            for (int i = 0; i < 2; i++)
                #pragma unroll
                for (int jn = 0; jn < 8; jn++) {
                    mma16816(acc[i][jn], ah[i], bv[jn]);
                    mma16816(acc[i][jn], al[i], bv[jn]);
                }
        }
    }

    #pragma unroll
    for (int i = 0; i < 2; i++)
        #pragma unroll
        for (int jn = 0; jn < 8; jn++) {
            int r0 = m0 + wr + i * 16 + (lid >> 2);
            int cc = wc + jn * 8 + (lid & 3) * 2;
            #pragma unroll
            for (int half = 0; half < 2; half++) {
                int row = r0 + half * 8;
                float v0 = acc[i][jn][half * 2 + 0];
                float v1 = acc[i][jn][half * 2 + 1];
                size_t o = ((size_t)(b * SS + row) * HH + hh) * HDIM + cc;
                bf16 h0, l0, h1, l1;
                split_bf(v0, h0, l0); split_bf(v1, h1, l1);
                oh[o] = h0; oh[o + 1] = h1;
                ol[o] = l0; ol[o + 1] = l1;
            }
        }
}

// ---------------- router ----------------
__global__ __launch_bounds__(256) void router_kernel(
    const float* __restrict__ hn, const float* __restrict__ wg)
{
    int tkn = blockIdx.x;
    int w = threadIdx.x >> 5, lane = threadIdx.x & 31;
    const float* x = hn + (size_t)tkn * DD;
    const float* g = wg + (size_t)w * DD;
    float s = 0.f;
    for (int i = lane; i < DD; i += 32) s += x[i] * g[i];
    s = warp_sum(s);
    __shared__ float lg[EE];
    if (lane == 0) lg[w] = s;
    __syncthreads();
    if (threadIdx.x == 0) {
        float m = -INFINITY;
        #pragma unroll
        for (int e = 0; e < EE; e++) m = fmaxf(m, lg[e]);
        float ex[EE];
        #pragma unroll
        for (int e = 0; e < EE; e++) ex[e] = expf(lg[e] - m);
        int i1 = 0; float m1 = ex[0];
        #pragma unroll
        for (int e = 1; e < EE; e++) if (ex[e] > m1) { m1 = ex[e]; i1 = e; }
        int i2 = -1; float m2 = -1.f;
        #pragma unroll
        for (int e = 0; e < EE; e++) if (e != i1 && ex[e] > m2) { m2 = ex[e]; i2 = e; }
        float inv = 1.0f / (m1 + m2);
        int p1 = atomicAdd(&g_cnt[i1], 1);
        g_tok[i1 * TT + p1] = tkn; g_twt[i1 * TT + p1] = m1 * inv;
        int p2 = atomicAdd(&g_cnt[i2], 1);
        g_tok[i2 * TT + p2] = tkn; g_twt[i2 * TT + p2] = m2 * inv;
    }
}

__global__ void final_add_kernel(const float* __restrict__ h, const float* __restrict__ moe,
                                 float* __restrict__ out) {
    int i = blockIdx.x * 256 + threadIdx.x;
    out[i] = h[i] + moe[i];
}

// ======================= host =======================
extern "C" void kernel_launch(void* const* d_in, const int* in_sizes, int n_in,
                              void* d_out, int out_size) {
    const float* hidden = (const float*)d_in[0];
    const float* w_q    = (const float*)d_in[1];
    const float* w_k    = (const float*)d_in[2];
    const float* w_v    = (const float*)d_in[3];
    const float* w_o    = (const float*)d_in[4];
    const float* g1     = (const float*)d_in[5];
    const float* g2     = (const float*)d_in[6];
    const float* w_gate = (const float*)d_in[7];
    const float* w1     = (const float*)d_in[8];
    const float* w3     = (const float*)d_in[9];
    const float* w2     = (const float*)d_in[10];
    float* out = (float*)d_out;

    bf16 *p_wqkvn, *p_won, *p_w1n, *p_w3n, *p_w2n;
    float *p_wqkvs, *p_wos, *p_w1s, *p_w3s, *p_w2s;
    bf16 *p_hnh, *p_hnl, *p_oh, *p_ol, *p_uph, *p_upl;
    bf16 *p_xnh, *p_xnl;
    bf16 *p_qh, *p_ql, *p_kh, *p_kl, *p_vn, *p_ph, *p_pl;
    float *p_qkv, *p_vs, *p_sc, *p_h, *p_hn, *p_up1, *p_moe, *p_twt;
    int *p_cnt, *p_tok;
    cudaGetSymbolAddress((void**)&p_wqkvn, g_wqkvn); cudaGetSymbolAddress((void**)&p_wqkvs, g_wqkvs);
    cudaGetSymbolAddress((void**)&p_won, g_won); cudaGetSymbolAddress((void**)&p_wos, g_wos);
    cudaGetSymbolAddress((void**)&p_w1n, g_w1n); cudaGetSymbolAddress((void**)&p_w1s, g_w1s);
    cudaGetSymbolAddress((void**)&p_w3n, g_w3n); cudaGetSymbolAddress((void**)&p_w3s, g_w3s);
    cudaGetSymbolAddress((void**)&p_w2n, g_w2n); cudaGetSymbolAddress((void**)&p_w2s, g_w2s);
    cudaGetSymbolAddress((void**)&p_xnh, g_xnh); cudaGetSymbolAddress((void**)&p_xnl, g_xnl);
    cudaGetSymbolAddress((void**)&p_hnh, g_hnh); cudaGetSymbolAddress((void**)&p_hnl, g_hnl);
    cudaGetSymbolAddress((void**)&p_oh, g_oh);   cudaGetSymbolAddress((void**)&p_ol, g_ol);
    cudaGetSymbolAddress((void**)&p_uph, g_uph); cudaGetSymbolAddress((void**)&p_upl, g_upl);
    cudaGetSymbolAddress((void**)&p_qkv, g_qkv);
    cudaGetSymbolAddress((void**)&p_qh, g_qh);   cudaGetSymbolAddress((void**)&p_ql, g_ql);
    cudaGetSymbolAddress((void**)&p_kh, g_kh);   cudaGetSymbolAddress((void**)&p_kl, g_kl);
    cudaGetSymbolAddress((void**)&p_vn, g_vn);   cudaGetSymbolAddress((void**)&p_vs, g_vs);
    cudaGetSymbolAddress((void**)&p_sc, g_sc);
    cudaGetSymbolAddress((void**)&p_ph, g_ph);   cudaGetSymbolAddress((void**)&p_pl, g_pl);
    cudaGetSymbolAddress((void**)&p_h, g_h);     cudaGetSymbolAddress((void**)&p_hn, g_hn);
    cudaGetSymbolAddress((void**)&p_up1, g_up1); cudaGetSymbolAddress((void**)&p_moe, g_moe);
    cudaGetSymbolAddress((void**)&p_cnt, g_cnt); cudaGetSymbolAddress((void**)&p_tok, g_tok);
    cudaGetSymbolAddress((void**)&p_twt, g_twt);

    cudaFuncSetAttribute(gemm_tc<0>, cudaFuncAttributeMaxDynamicSharedMemorySize, SMEM_SZ);
    cudaFuncSetAttribute(gemm_tc<1>, cudaFuncAttributeMaxDynamicSharedMemorySize, SMEM_SZ);
    cudaFuncSetAttribute(gemm_tc<2>, cudaFuncAttributeMaxDynamicSharedMemorySize, SMEM_SZ);
    cudaFuncSetAttribute(gemm_tc<3>, cudaFuncAttributeMaxDynamicSharedMemorySize, SMEM_SZ);
    cudaFuncSetAttribute(gemm_tc<4>, cudaFuncAttributeMaxDynamicSharedMemorySize, SMEM_SZ);
    cudaFuncSetAttribute(scores_tc, cudaFuncAttributeMaxDynamicSharedMemorySize, SCR_SMEM);
    cudaFuncSetAttribute(av_tc, cudaFuncAttributeMaxDynamicSharedMemorySize, AV_SMEM);

    // side stream + events for overlapping the big weight-quant kernels with
    // the attention phase (fork/join is capture-legal; resources lazily created,
    // host-side only — no device allocations).
    static cudaStream_t s2 = nullptr;
    static cudaEvent_t ev_fork = nullptr, ev_join = nullptr;
    if (!s2) {
        cudaStreamCreateWithFlags(&s2, cudaStreamNonBlocking);
        cudaEventCreateWithFlags(&ev_fork, cudaEventDisableTiming);
        cudaEventCreateWithFlags(&ev_join, cudaEventDisableTiming);
    }

    zero_kernel<<<8192, 256>>>(p_moe, p_cnt);

    // fork: big MoE weight quants run on s2, hidden under the attention phase
    cudaEventRecord(ev_fork, 0);
    cudaStreamWaitEvent(s2, ev_fork, 0);
    quantw_kernel<<<28672, 256, 0, s2>>>(w1, p_w1n, p_w1s, EE * FFND * DD / 128);
    quantw_kernel<<<28672, 256, 0, s2>>>(w3, p_w3n, p_w3s, EE * FFND * DD / 128);
    quantw_kernel<<<28672, 256, 0, s2>>>(w2, p_w2n, p_w2s, EE * DD * FFND / 128);
    cudaEventRecord(ev_join, s2);

    // attention-phase weights on the main stream
    quantw_kernel<<<1024, 256>>>(w_q, p_wqkvn, p_wqkvs, DD * DD / 128);
    quantw_kernel<<<256, 256>>>(w_k, p_wqkvn + 1024 * DD, p_wqkvs + 1024 * 8, KV * HDIM * DD / 128);
    quantw_kernel<<<256, 256>>>(w_v, p_wqkvn + 1280 * DD, p_wqkvs + 1280 * 8, KV * HDIM * DD / 128);
    quantw_kernel<<<1024, 256>>>(w_o, p_won, p_wos, DD * DD / 128);

    // ---- attention ----
    rms_split_kernel<false><<<TT, 256>>>(hidden, g1, nullptr, p_xnh, p_xnl);
    gemm_tc<0><<<dim3(12, 16, 1), 256, SMEM_SZ>>>(p_xnh, p_xnl, DD, 0,
        p_wqkvn, p_wqkvs, DD, 0, 0,
        p_qkv, nullptr, nullptr, NQKV, 0, TT, nullptr, DD, nullptr, nullptr, nullptr);
    kvprep_kernel<<<TT * (HH + KV + KV), HDIM>>>(p_qkv, p_qh, p_ql, p_kh, p_kl, p_vn, p_vs);
    scores_tc<<<dim3(8, 8, BB * HH), 256, SCR_SMEM>>>(p_qh, p_ql, p_kh, p_kl, p_sc);
    softmax_kernel<<<BB * HH * SS, 256>>>(p_sc, p_vs, p_ph, p_pl);
    av_tc<<<dim3(1, 8, BB * HH), 256, AV_SMEM>>>(p_ph, p_pl, p_vn, p_oh, p_ol);
    gemm_tc<1><<<dim3(8, 16, 1), 256, SMEM_SZ>>>(p_oh, p_ol, DD, 0,
        p_won, p_wos, DD, 0, 0,
        p_h, nullptr, nullptr, DD, 0, TT, nullptr, DD, hidden, nullptr, nullptr);

    // ---- MoE ----
    rms_split_kernel<true><<<TT, 256>>>(p_h, g2, p_hn, p_hnh, p_hnl);
    router_kernel<<<TT, 256>>>(p_hn, w_gate);
    // join: MoE GEMMs need the s2 weight quants
    cudaStreamWaitEvent(0, ev_join, 0);
    gemm_tc<2><<<dim3(28, 16, EE), 256, SMEM_SZ>>>(p_hnh, p_hnl, DD, 0,
        p_w1n, p_w1s, DD, (size_t)FFND * DD, (size_t)FFND * 8,
        p_up1, nullptr, nullptr, FFND, (size_t)TT * FFND,
        0, p_cnt, DD, nullptr, p_tok, nullptr);
    gemm_tc<4><<<dim3(28, 16, EE), 256, SMEM_SZ>>>(p_hnh, p_hnl, DD, 0,
        p_w3n, p_w3s, DD, (size_t)FFND * DD, (size_t)FFND * 8,
        nullptr, p_uph, p_upl, FFND, (size_t)TT * FFND,
        0, p_cnt, DD, p_up1, p_tok, nullptr);
    gemm_tc<3><<<dim3(8, 16, EE), 256, SMEM_SZ>>>(p_uph, p_upl, FFND, (size_t)TT * FFND,
        p_w2n, p_w2s, FFND, (size_t)DD * FFND, (size_t)DD * 28,
        p_moe, nullptr, nullptr, DD, 0,
        0, p_cnt, FFND, nullptr, p_tok, p_twt);
    final_add_kernel<<<8192, 256>>>(p_h, p_moe, out);
}

// round 13
// speedup vs baseline: 1.9101x; 1.0247x over previous
#include <cuda_runtime.h>
#include <cuda_bf16.h>
#include <math.h>
#include <stdint.h>

#define BB 2
#define SS 1024
#define TT 2048
#define DD 1024
#define HH 8
#define KV 2
#define HDIM 128
#define EE 8
#define FFND 3584
#define NQKV 1536

#define KT 64
#define STAGES 4
#define TILE_BYTES 16384
#define STAGE_BYTES (3 * TILE_BYTES)
#define SC_OFF (STAGES * STAGE_BYTES)
#define SMEM_SZ (SC_OFF + 28 * 128 * 4)
#define SCR_SMEM (2 * 4 * TILE_BYTES)
#define AV_STAGE (3 * TILE_BYTES)
#define AV_SMEM (3 * AV_STAGE)

typedef __nv_bfloat16 bf16;

// weights: integer bf16 + per-group fp32 scale
__device__ bf16  g_wqkvn[NQKV * DD];       __device__ float g_wqkvs[NQKV * DD / 128];
__device__ bf16  g_won[DD * DD];           __device__ float g_wos[DD * DD / 128];
__device__ bf16  g_w1n[EE * FFND * DD];    __device__ float g_w1s[EE * FFND * DD / 128];
__device__ bf16  g_w3n[EE * FFND * DD];    __device__ float g_w3s[EE * FFND * DD / 128];
__device__ bf16  g_w2n[EE * DD * FFND];    __device__ float g_w2s[EE * DD * FFND / 128];
// activations
__device__ bf16 g_xnh[TT * DD];        __device__ bf16 g_xnl[TT * DD];
__device__ bf16 g_hnh[TT * DD];        __device__ bf16 g_hnl[TT * DD];
__device__ bf16 g_oh[TT * DD];         __device__ bf16 g_ol[TT * DD];
__device__ bf16 g_uph[EE * TT * FFND]; __device__ bf16 g_upl[EE * TT * FFND];
__device__ float g_qkv[TT * NQKV];
__device__ bf16 g_qh[TT * DD];         __device__ bf16 g_ql[TT * DD];
__device__ bf16 g_kh[TT * KV * HDIM];  __device__ bf16 g_kl[TT * KV * HDIM];
__device__ bf16 g_vn[TT * KV * HDIM];  __device__ float g_vs[TT * KV];
__device__ float g_sc[BB * HH * SS * SS];
__device__ bf16 g_ph[BB * HH * SS * SS];
__device__ bf16 g_pl[BB * HH * SS * SS];
__device__ float g_h[TT * DD];
__device__ float g_hn[TT * DD];
__device__ float g_up1[EE * TT * FFND];
__device__ float g_moeX[EE * TT * DD];   // dense per-slot w2 output (no atomics)
__device__ int   g_cnt[EE];
__device__ int   g_tok[EE * TT];
__device__ float g_twt[EE * TT];
__device__ int   g_tslot[TT * 2];        // per-token (expert*TT+slot) ids

// ---------------- ptx helpers ----------------
__device__ __forceinline__ uint32_t smem_u32(const void* p) {
    uint32_t a;
    asm("{ .reg .u64 t; cvta.to.shared.u64 t, %1; cvt.u32.u64 %0, t; }" : "=r"(a) : "l"(p));
    return a;
}
__device__ __forceinline__ void ldsm4(uint32_t a, uint32_t& r0, uint32_t& r1,
                                      uint32_t& r2, uint32_t& r3) {
    asm volatile("ldmatrix.sync.aligned.m8n8.x4.shared.b16 {%0,%1,%2,%3}, [%4];"
                 : "=r"(r0), "=r"(r1), "=r"(r2), "=r"(r3) : "r"(a));
}
__device__ __forceinline__ void ldsm4t(uint32_t a, uint32_t& r0, uint32_t& r1,
                                       uint32_t& r2, uint32_t& r3) {
    asm volatile("ldmatrix.sync.aligned.m8n8.x4.trans.shared.b16 {%0,%1,%2,%3}, [%4];"
                 : "=r"(r0), "=r"(r1), "=r"(r2), "=r"(r3) : "r"(a));
}
__device__ __forceinline__ void mma16816(float* c, const uint32_t* a, const uint32_t* b) {
    asm volatile("mma.sync.aligned.m16n8k16.row.col.f32.bf16.bf16.f32 "
                 "{%0,%1,%2,%3}, {%4,%5,%6,%7}, {%8,%9}, {%0,%1,%2,%3};"
                 : "+f"(c[0]), "+f"(c[1]), "+f"(c[2]), "+f"(c[3])
                 : "r"(a[0]), "r"(a[1]), "r"(a[2]), "r"(a[3]), "r"(b[0]), "r"(b[1]));
}
__device__ __forceinline__ void cpa16(uint32_t dst, const void* src) {
    asm volatile("cp.async.cg.shared.global [%0], [%1], 16;" :: "r"(dst), "l"(src));
}
__device__ __forceinline__ void cpa_commit() { asm volatile("cp.async.commit_group;" ::: "memory"); }
__device__ __forceinline__ void cpa_wait0() { asm volatile("cp.async.wait_group 0;" ::: "memory"); }
__device__ __forceinline__ void cpa_wait1() { asm volatile("cp.async.wait_group 1;" ::: "memory"); }
__device__ __forceinline__ void cpa_wait2() { asm volatile("cp.async.wait_group 2;" ::: "memory"); }

__device__ __forceinline__ float warp_min(float v) {
    #pragma unroll
    for (int o = 16; o; o >>= 1) v = fminf(v, __shfl_xor_sync(0xffffffffu, v, o));
    return v;
}
__device__ __forceinline__ float warp_max(float v) {
    #pragma unroll
    for (int o = 16; o; o >>= 1) v = fmaxf(v, __shfl_xor_sync(0xffffffffu, v, o));
    return v;
}
__device__ __forceinline__ float warp_sum(float v) {
    #pragma unroll
    for (int o = 16; o; o >>= 1) v += __shfl_xor_sync(0xffffffffu, v, o);
    return v;
}
__device__ __forceinline__ void split_bf(float v, bf16& h, bf16& l) {
    h = __float2bfloat16(v);
    l = __float2bfloat16(v - __bfloat162float(h));
}
__device__ __forceinline__ uint32_t swz(uint32_t off) { return off ^ ((off >> 3) & 0x70); }

// ---------------- small kernels ----------------
__global__ void zero_cnt_kernel(int* __restrict__ cnt) {
    if (threadIdx.x < EE) cnt[threadIdx.x] = 0;
}

__global__ void quantw_kernel(const float* __restrict__ w, bf16* __restrict__ nq,
                              float* __restrict__ sc, int ngroups) {
    int g = blockIdx.x * 8 + (threadIdx.x >> 5);
    if (g >= ngroups) return;
    int lane = threadIdx.x & 31;
    float4 v = reinterpret_cast<const float4*>(w)[(size_t)g * 32 + lane];
    float mn = fminf(fminf(v.x, v.y), fminf(v.z, v.w));
    float mx = fmaxf(fmaxf(v.x, v.y), fmaxf(v.z, v.w));
    mn = warp_min(mn); mx = warp_max(mx);
    float scale = fmaxf(mx - mn, 1e-5f) / 15.0f;
    float sinv = 1.0f / scale;
    float base = fminf(fmaxf(rintf(-mn * sinv), 0.f), 15.f);
    float r[4] = {v.x, v.y, v.z, v.w};
    bf16 n4[4];
    #pragma unroll
    for (int j = 0; j < 4; j++) {
        float q = fminf(fmaxf(rintf(r[j] * sinv) + base, 0.f), 15.f) - base;
        n4[j] = __float2bfloat16(q);  // exact integer in [-15,15]
    }
    size_t idx = (size_t)g * 128 + lane * 4;
    *reinterpret_cast<uint2*>(nq + idx) = *reinterpret_cast<uint2*>(n4);
    if (lane == 0) sc[g] = scale;
}

template<bool WF32>
__global__ void rms_split_kernel(const float* __restrict__ x, const float* __restrict__ g,
                                 float* __restrict__ f32o, bf16* __restrict__ hi,
                                 bf16* __restrict__ lo) {
    int row = blockIdx.x;
    const float* xr = x + (size_t)row * DD;
    float s = 0.f;
    for (int i = threadIdx.x; i < DD; i += 256) { float v = xr[i]; s += v * v; }
    __shared__ float sh[256];
    sh[threadIdx.x] = s; __syncthreads();
    for (int o2 = 128; o2; o2 >>= 1) {
        if (threadIdx.x < o2) sh[threadIdx.x] += sh[threadIdx.x + o2];
        __syncthreads();
    }
    float inv = rsqrtf(sh[0] * (1.0f / DD) + 1e-5f);
    for (int i = threadIdx.x; i < DD; i += 256) {
        float v = xr[i] * inv * g[i];
        if (WF32) f32o[(size_t)row * DD + i] = v;
        bf16 h, l; split_bf(v, h, l);
        hi[(size_t)row * DD + i] = h;
        lo[(size_t)row * DD + i] = l;
    }
}

// ===== bf16x2 mma.sync GEMM with exact integer weights + per-group rescale =====
// MODE 0 store f32 | 1 +resid | 2 gather-A, M=Mptr[z] | 4 gather-A, silu(resid)*acc
// split-> CH/CL | 5 direct-A slot rows, M=Mptr[z], store f32 z-strided
template<int MODE>
__global__ __launch_bounds__(256, 1) void gemm_tc(
    const bf16* __restrict__ Ahi, const bf16* __restrict__ Alo, int lda, size_t strideA,
    const bf16* __restrict__ Bn, const float* __restrict__ Bsc, int ldb,
    size_t strideB, size_t strideBs,
    float* __restrict__ C, bf16* __restrict__ CH, bf16* __restrict__ CL,
    int ldc, size_t strideC,
    int M, const int* __restrict__ Mptr, int K,
    const float* __restrict__ resid, const int* __restrict__ idx)
{
    int z = blockIdx.z;
    if (Mptr) M = Mptr[z];
    int m0 = blockIdx.y * 128;
    if (m0 >= M) return;
    int n0 = blockIdx.x * 128;
    int tid = threadIdx.x;
    int wid = tid >> 5, lid = tid & 31;

    extern __shared__ char smem[];
    uint32_t sb = smem_u32(smem);
    float* scs = reinterpret_cast<float*>(smem + SC_OFF);
    const int* idxz = (MODE == 2 || MODE == 4) ? (idx + (size_t)z * TT) : (const int*)nullptr;
    int G = K >> 7;

    for (int i = tid; i < G * 128; i += 256) {
        int g = i >> 7, c = i & 127;
        scs[i] = Bsc[strideBs * z + (size_t)(n0 + c) * G + g];
    }

    const bf16* srcA[4]; const bf16* srcB[4];
    uint32_t dstA[4], dstB[4];
    ptrdiff_t dlo = Alo - Ahi;
    #pragma unroll
    for (int ci = 0; ci < 4; ci++) {
        int gid = ci * 256 + tid;
        int r = (gid >> 3) & 127;
        int c8 = gid & 7;
        int row = m0 + r;
        if (row >= M) row = m0;
        int rg = (MODE == 2 || MODE == 4) ? idxz[row] : row;
        srcA[ci] = Ahi + strideA * (size_t)z + (size_t)rg * lda + c8 * 8;
        dstA[ci] = swz((uint32_t)(r * 128 + c8 * 16));
        int gid2 = 2048 + gid;
        int r2 = (gid2 >> 3) & 127;
        int c82 = gid2 & 7;
        srcB[ci] = Bn + strideB * (size_t)z + (size_t)(n0 + r2) * ldb + c82 * 8;
        dstB[ci] = (uint32_t)(2 * TILE_BYTES) + swz((uint32_t)(r2 * 128 + c82 * 16));
    }

    int n_kt = K / KT;
    int npro = STAGES - 1; if (npro > n_kt) npro = n_kt;
    #pragma unroll 1
    for (int p = 0; p < npro; p++) {
        uint32_t base = sb + p * STAGE_BYTES;
        size_t ko = (size_t)p * KT;
        #pragma unroll
        for (int ci = 0; ci < 4; ci++) {
            cpa16(base + dstA[ci], srcA[ci] + ko);
            cpa16(base + TILE_BYTES + dstA[ci], srcA[ci] + dlo + ko);
            cpa16(base + dstB[ci], srcB[ci] + ko);
        }
        cpa_commit();
    }

    int wr = (wid & 3) * 32;
    int wc = (wid >> 2) * 64;
    int rowm = (lid & 7) + ((lid >> 3) & 1) * 8;
    int colb = (lid >> 4) * 16;

    float acc[2][8][4] = {};
    float accg[2][8][4] = {};

    #pragma unroll 1
    for (int kt = 0; kt < n_kt; kt++) {
        int pending = n_kt - kt - 1; if (pending > STAGES - 2) pending = STAGES - 2;
        if (pending >= 2) cpa_wait2();
        else if (pending == 1) cpa_wait1();
        else cpa_wait0();
        __syncthreads();
        if (kt + STAGES - 1 < n_kt) {
            int sl = (kt + STAGES - 1) % STAGES;
            uint32_t base = sb + sl * STAGE_BYTES;
            size_t ko = (size_t)(kt + STAGES - 1) * KT;
            #pragma unroll
            for (int ci = 0; ci < 4; ci++) {
                cpa16(base + dstA[ci], srcA[ci] + ko);
                cpa16(base + TILE_BYTES + dstA[ci], srcA[ci] + dlo + ko);
                cpa16(base + dstB[ci], srcB[ci] + ko);
            }
            cpa_commit();
        }
        uint32_t sbase = sb + (kt % STAGES) * STAGE_BYTES;
        #pragma unroll
        for (int s16 = 0; s16 < 4; s16++) {
            int kb0 = s16 * 32 + colb;
            uint32_t ah[2][4], al[2][4], bn[8][2];
            #pragma unroll
            for (int i = 0; i < 2; i++) {
                uint32_t off = (uint32_t)((wr + i * 16 + rowm) * 128 + kb0);
                ldsm4(sbase + swz(off), ah[i][0], ah[i][1], ah[i][2], ah[i][3]);
                ldsm4(sbase + TILE_BYTES + swz(off), al[i][0], al[i][1], al[i][2], al[i][3]);
            }
            #pragma unroll
            for (int j = 0; j < 4; j++) {
                uint32_t off = (uint32_t)((wc + j * 16 + rowm) * 128 + kb0);
                uint32_t r0, r1, r2, r3;
                ldsm4(sbase + 2 * TILE_BYTES + swz(off), r0, r1, r2, r3);
                bn[j * 2][0] = r0; bn[j * 2][1] = r2;
                bn[j * 2 + 1][0] = r1; bn[j * 2 + 1][1] = r3;
            }
            #pragma unroll
            for (int i = 0; i < 2; i++)
                #pragma unroll
                for (int jn = 0; jn < 8; jn++) {
                    mma16816(accg[i][jn], ah[i], bn[jn]);
                    mma16816(accg[i][jn], al[i], bn[jn]);
                }
        }
        if (kt & 1) {
            int g = kt >> 1;
            #pragma unroll
            for (int jn = 0; jn < 8; jn++) {
                int c = wc + jn * 8 + (lid & 3) * 2;
                float s0 = scs[g * 128 + c];
                float s1 = scs[g * 128 + c + 1];
                #pragma unroll
                for (int i = 0; i < 2; i++) {
                    acc[i][jn][0] += s0 * accg[i][jn][0];
                    acc[i][jn][1] += s1 * accg[i][jn][1];
                    acc[i][jn][2] += s0 * accg[i][jn][2];
                    acc[i][jn][3] += s1 * accg[i][jn][3];
                    accg[i][jn][0] = 0.f; accg[i][jn][1] = 0.f;
                    accg[i][jn][2] = 0.f; accg[i][jn][3] = 0.f;
                }
            }
        }
    }

    #pragma unroll
    for (int i = 0; i < 2; i++) {
        #pragma unroll
        for (int jn = 0; jn < 8; jn++) {
            int r0 = m0 + wr + i * 16 + (lid >> 2);
            int cc = n0 + wc + jn * 8 + (lid & 3) * 2;
            #pragma unroll
            for (int half = 0; half < 2; half++) {
                int row = r0 + half * 8;
                if (row >= M) continue;
                float v0 = acc[i][jn][half * 2 + 0];
                float v1 = acc[i][jn][half * 2 + 1];
                if (MODE == 0 || MODE == 1 || MODE == 2 || MODE == 5) {
                    float* Cr = C + strideC * z + (size_t)row * ldc + cc;
                    if (MODE == 1) {
                        const float* rr = resid + (size_t)row * ldc + cc;
                        v0 += rr[0]; v1 += rr[1];
                    }
                    *reinterpret_cast<float2*>(Cr) = make_float2(v0, v1);
                } else {  // MODE 4
                    const float* ar = resid + strideC * z + (size_t)row * ldc + cc;
                    float a0 = ar[0], a1 = ar[1];
                    float gv0 = (a0 / (1.f + expf(-a0))) * v0;
                    float gv1 = (a1 / (1.f + expf(-a1))) * v1;
                    bf16 h0, l0, h1, l1;
                    split_bf(gv0, h0, l0); split_bf(gv1, h1, l1);
                    size_t o = strideC * z + (size_t)row * ldc + cc;
                    CH[o] = h0; CH[o + 1] = h1;
                    CL[o] = l0; CL[o + 1] = l1;
                }
            }
        }
    }
}

// ---------------- fused q-rope / k-quant+rope / v-quant prep ----------------
__global__ void kvprep_kernel(const float* __restrict__ qkv,
                              bf16* __restrict__ qh, bf16* __restrict__ ql,
                              bf16* __restrict__ kh, bf16* __restrict__ kl,
                              bf16* __restrict__ vn, float* __restrict__ vs) {
    int j = blockIdx.x;
    int d = threadIdx.x;
    __shared__ float smn[HDIM], smx[HDIM], sh[HDIM];
    if (j < TT * HH) {
        int t = j >> 3, hh = j & 7;
        sh[d] = qkv[(size_t)t * NQKV + hh * HDIM + d];
        __syncthreads();
        int pos = t & (SS - 1);
        int i = d & 63;
        float invf = expf(-13.815510557964274f * ((float)(2 * i) * (1.0f / HDIM)));
        float f = (float)pos * invf;
        float c = cosf(f), sn = sinf(f);
        float v = (d < 64) ? (sh[d] * c - sh[d + 64] * sn)
                           : (sh[d] * c + sh[d - 64] * sn);
        bf16 h, l; split_bf(v, h, l);
        qh[(size_t)j * HDIM + d] = h;
        ql[(size_t)j * HDIM + d] = l;
        return;
    }
    int j2 = j - TT * HH;
    bool isK = j2 < TT * KV;
    int rowid = isK ? j2 : (j2 - TT * KV);
    int t = rowid >> 1, kvh = rowid & 1;
    float v = qkv[(size_t)t * NQKV + (isK ? 1024 : 1280) + kvh * HDIM + d];
    smn[d] = v; smx[d] = v; __syncthreads();
    for (int o2 = 64; o2; o2 >>= 1) {
        if (d < o2) {
            smn[d] = fminf(smn[d], smn[d + o2]);
            smx[d] = fmaxf(smx[d], smx[d + o2]);
        }
        __syncthreads();
    }
    float scale = fmaxf(smx[0] - smn[0], 1e-5f) / 15.0f;
    float sinv = 1.0f / scale;
    float base = fminf(fmaxf(rintf(-smn[0] * sinv), 0.f), 15.f);
    float qn = fminf(fmaxf(rintf(v * sinv) + base, 0.f), 15.f) - base;
    if (!isK) {
        vn[(size_t)rowid * HDIM + d] = __float2bfloat16(qn);
        if (d == 0) vs[rowid] = scale;
        return;
    }
    float q = qn * scale;
    sh[d] = q; __syncthreads();
    int pos = t & (SS - 1);
    int i = d & 63;
    float invf = expf(-13.815510557964274f * ((float)(2 * i) * (1.0f / HDIM)));
    float f = (float)pos * invf;
    float c = cosf(f), sn = sinf(f);
    q = (d < 64) ? (sh[d] * c - sh[d + 64] * sn)
                 : (sh[d] * c + sh[d - 64] * sn);
    bf16 h, l; split_bf(q, h, l);
    kh[(size_t)rowid * HDIM + d] = h;
    kl[(size_t)rowid * HDIM + d] = l;
}

// ---------------- TC scores ----------------
__global__ __launch_bounds__(256, 1) void scores_tc(
    const bf16* __restrict__ qh, const bf16* __restrict__ ql,
    const bf16* __restrict__ kh, const bf16* __restrict__ kl,
    float* __restrict__ sc)
{
    int z = blockIdx.z;
    int m0 = blockIdx.y * 128, n0 = blockIdx.x * 128;
    if (n0 > m0) return;
    int b = z >> 3, hh = z & 7, kvh = (z & 7) >> 2;
    int tid = threadIdx.x, wid = tid >> 5, lid = tid & 31;
    extern __shared__ char smem[];
    uint32_t sb = smem_u32(smem);

    const bf16* src[16]; uint32_t dst[16];
    #pragma unroll
    for (int ci = 0; ci < 16; ci++) {
        int gid = ci * 256 + tid;
        int t4 = gid >> 10;
        int r = (gid >> 3) & 127;
        int c8 = gid & 7;
        const bf16* p;
        if (t4 == 0)      p = qh + ((size_t)(b * SS + m0 + r) * HH + hh) * HDIM;
        else if (t4 == 1) p = ql + ((size_t)(b * SS + m0 + r) * HH + hh) * HDIM;
        else if (t4 == 2) p = kh + ((size_t)(b * SS + n0 + r) * KV + kvh) * HDIM;
        else              p = kl + ((size_t)(b * SS + n0 + r) * KV + kvh) * HDIM;
        src[ci] = p + c8 * 8;
        dst[ci] = (uint32_t)(t4 * TILE_BYTES) + swz((uint32_t)(r * 128 + c8 * 16));
    }
    #pragma unroll
    for (int ci = 0; ci < 16; ci++) cpa16(sb + dst[ci], src[ci]);
    cpa_commit();
    #pragma unroll
    for (int ci = 0; ci < 16; ci++) cpa16(sb + 4 * TILE_BYTES + dst[ci], src[ci] + 64);
    cpa_commit();

    int wr = (wid & 3) * 32;
    int wc = (wid >> 2) * 64;
    int rowm = (lid & 7) + ((lid >> 3) & 1) * 8;
    int colb = (lid >> 4) * 16;
    float acc[2][8][4] = {};

    #pragma unroll 1
    for (int ch = 0; ch < 2; ch++) {
        if (ch == 0) cpa_wait1(); else cpa_wait0();
        __syncthreads();
        uint32_t base = sb + ch * 4 * TILE_BYTES;
        #pragma unroll
        for (int s16 = 0; s16 < 4; s16++) {
            int kb0 = s16 * 32 + colb;
            uint32_t ah[2][4], al[2][4], bh[8][2], bl[8][2];
            #pragma unroll
            for (int i = 0; i < 2; i++) {
                uint32_t off = (uint32_t)((wr + i * 16 + rowm) * 128 + kb0);
                ldsm4(base + swz(off), ah[i][0], ah[i][1], ah[i][2], ah[i][3]);
                ldsm4(base + TILE_BYTES + swz(off), al[i][0], al[i][1], al[i][2], al[i][3]);
            }
            #pragma unroll
            for (int j = 0; j < 4; j++) {
                uint32_t off = (uint32_t)((wc + j * 16 + rowm) * 128 + kb0);
                uint32_t r0, r1, r2, r3;
                ldsm4(base + 2 * TILE_BYTES + swz(off), r0, r1, r2, r3);
                bh[j * 2][0] = r0; bh[j * 2][1] = r2;
                bh[j * 2 + 1][0] = r1; bh[j * 2 + 1][1] = r3;
                ldsm4(base + 3 * TILE_BYTES + swz(off), r0, r1, r2, r3);
                bl[j * 2][0] = r0; bl[j * 2][1] = r2;
                bl[j * 2 + 1][0] = r1; bl[j * 2 + 1][1] = r3;
            }
            #pragma unroll
            for (int i = 0; i < 2; i++)
                #pragma unroll
                for (int jn = 0; jn < 8; jn++) {
                    mma16816(acc[i][jn], ah[i], bh[jn]);
                    mma16816(acc[i][jn], ah[i], bl[jn]);
                    mma16816(acc[i][jn], al[i], bh[jn]);
                }
        }
    }
    const float scalef = 0.08838834764831845f;
    float* C = sc + (size_t)z * SS * SS;
    #pragma unroll
    for (int i = 0; i < 2; i++)
        #pragma unroll
        for (int jn = 0; jn < 8; jn++) {
            int r0 = m0 + wr + i * 16 + (lid >> 2);
            int cc = n0 + wc + jn * 8 + (lid & 3) * 2;
            #pragma unroll
            for (int half = 0; half < 2; half++) {
                int row = r0 + half * 8;
                float v0 = acc[i][jn][half * 2 + 0] * scalef;
                float v1 = acc[i][jn][half * 2 + 1] * scalef;
                *reinterpret_cast<float2*>(C + (size_t)row * SS + cc) = make_float2(v0, v1);
            }
        }
}

// ---------------- softmax (writes ph/pl only up to (s|127)+1) ----------------
__global__ void softmax_kernel(float* __restrict__ sc, const float* __restrict__ vs,
                               bf16* __restrict__ ph, bf16* __restrict__ pl) {
    int r = blockIdx.x;
    int z = r >> 10;
    int s = r & (SS - 1);
    int b = z >> 3, kvh = (z & 7) >> 2;
    float* row = sc + (size_t)r * SS;
    int n = s + 1;
    int nlim = (s | 127) + 1;
    __shared__ float sh[256];
    float m = -INFINITY;
    for (int i = threadIdx.x; i < n; i += 256) m = fmaxf(m, row[i]);
    sh[threadIdx.x] = m; __syncthreads();
    for (int o2 = 128; o2; o2 >>= 1) {
        if (threadIdx.x < o2) sh[threadIdx.x] = fmaxf(sh[threadIdx.x], sh[threadIdx.x + o2]);
        __syncthreads();
    }
    m = sh[0]; __syncthreads();
    float sum = 0.f;
    for (int i = threadIdx.x; i < n; i += 256) {
        float e = expf(row[i] - m);
        row[i] = e; sum += e;
    }
    sh[threadIdx.x] = sum; __syncthreads();
    for (int o2 = 128; o2; o2 >>= 1) {
        if (threadIdx.x < o2) sh[threadIdx.x] += sh[threadIdx.x + o2];
        __syncthreads();
    }
    float inv = 1.0f / sh[0];
    for (int i = threadIdx.x; i < nlim; i += 256) {
        float p = (i < n) ? row[i] * inv : 0.f;
        float pv = p * vs[(size_t)((b * SS + i) * KV + kvh)];
        bf16 h, l; split_bf(pv, h, l);
        ph[(size_t)r * SS + i] = h;
        pl[(size_t)r * SS + i] = l;
    }
}

// ---------------- TC AV ----------------
__global__ __launch_bounds__(256, 1) void av_tc(
    const bf16* __restrict__ ph, const bf16* __restrict__ pl,
    const bf16* __restrict__ vn, bf16* __restrict__ oh, bf16* __restrict__ ol)
{
    int z = blockIdx.z;
    int b = z >> 3, hh = z & 7, kvh = (z & 7) >> 2;
    int m0 = blockIdx.y * 128;
    int tid = threadIdx.x, wid = tid >> 5, lid = tid & 31;
    extern __shared__ char smem[];
    uint32_t sb = smem_u32(smem);

    const bf16* srcP[4]; const bf16* srcV[4];
    uint32_t dstP[4], dstV[4];
    ptrdiff_t dpl = pl - ph;
    #pragma unroll
    for (int ci = 0; ci < 4; ci++) {
        int gid = ci * 256 + tid;
        int r = (gid >> 3) & 127;
        int c8 = gid & 7;
        srcP[ci] = ph + (size_t)z * SS * SS + (size_t)(m0 + r) * SS + c8 * 8;
        dstP[ci] = swz((uint32_t)(r * 128 + c8 * 16));
        int gid2 = 2048 + gid;
        int vrow = (gid2 >> 4) & 63;
        int c16 = gid2 & 15;
        int plane = c16 >> 3, cc8 = c16 & 7;
        srcV[ci] = vn + ((size_t)(b * SS + vrow) * KV + kvh) * HDIM + plane * 64 + cc8 * 8;
        dstV[ci] = (uint32_t)(2 * TILE_BYTES + plane * 8192) + swz((uint32_t)(vrow * 128 + cc8 * 16));
    }

    int n_ch = (m0 >> 6) + 2;
    #pragma unroll 1
    for (int p = 0; p < 2 && p < n_ch; p++) {
        uint32_t base = sb + p * AV_STAGE;
        #pragma unroll
        for (int ci = 0; ci < 4; ci++) {
            size_t ko = (size_t)p * KT;
            cpa16(base + dstP[ci], srcP[ci] + ko);
            cpa16(base + TILE_BYTES + dstP[ci], srcP[ci] + dpl + ko);
            cpa16(base + dstV[ci], srcV[ci] + ko * (KV * HDIM));
        }
        cpa_commit();
    }

    int wr = (wid & 3) * 32;
    int wc = (wid >> 2) * 64;
    int vplane = wc >> 6;
    int rowm = (lid & 7) + ((lid >> 3) & 1) * 8;
    int colb = (lid >> 4) * 16;
    float acc[2][8][4] = {};

    #pragma unroll 1
    for (int kt = 0; kt < n_ch; kt++) {
        cpa_wait1();
        __syncthreads();
        if (kt + 2 < n_ch) {
            int sl = (kt + 2) % 3;
            uint32_t base = sb + sl * AV_STAGE;
            size_t ko = (size_t)(kt + 2) * KT;
            #pragma unroll
            for (int ci = 0; ci < 4; ci++) {
                cpa16(base + dstP[ci], srcP[ci] + ko);
                cpa16(base + TILE_BYTES + dstP[ci], srcP[ci] + dpl + ko);
                cpa16(base + dstV[ci], srcV[ci] + ko * (KV * HDIM));
            }
            cpa_commit();
        }
        uint32_t sbase = sb + (kt % 3) * AV_STAGE;
        uint32_t vbase = sbase + 2 * TILE_BYTES + vplane * 8192;
        #pragma unroll
        for (int s16 = 0; s16 < 4; s16++) {
            int kb0 = s16 * 32 + colb;
            uint32_t ah[2][4], al[2][4], bv[8][2];
            #pragma unroll
            for (int i = 0; i < 2; i++) {
                uint32_t off = (uint32_t)((wr + i * 16 + rowm) * 128 + kb0);
                ldsm4(sbase + swz(off), ah[i][0], ah[i][1], ah[i][2], ah[i][3]);
                ldsm4(sbase + TILE_BYTES + swz(off), al[i][0], al[i][1], al[i][2], al[i][3]);
            }
            #pragma unroll
            for (int j16 = 0; j16 < 4; j16++) {
                uint32_t krow = (uint32_t)(s16 * 16 + (lid & 7) + 8 * ((lid >> 3) & 1));
                uint32_t off = krow * 128 + (uint32_t)(j16 * 32 + 16 * (lid >> 4));
                uint32_t r0, r1, r2, r3;
                ldsm4t(vbase + swz(off), r0, r1, r2, r3);
                bv[j16 * 2][0] = r0; bv[j16 * 2][1] = r1;
                bv[j16 * 2 + 1][0] = r2; bv[j16 * 2 + 1][1] = r3;
            }
            #pragma unroll
            for (int i = 0; i < 2; i++)
                #pragma unroll
                for (int jn = 0; jn < 8; jn++) {
                    mma16816(acc[i][jn], ah[i], bv[jn]);
                    mma16816(acc[i][jn], al[i], bv[jn]);
                }
        }
    }

    #pragma unroll
    for (int i = 0; i < 2; i++)
        #pragma unroll
        for (int jn = 0; jn < 8; jn++) {
            int r0 = m0 + wr + i * 16 + (lid >> 2);
            int cc = wc + jn * 8 + (lid & 3) * 2;
            #pragma unroll
            for (int half = 0; half < 2; half++) {
                int row = r0 + half * 8;
                float v0 = acc[i][jn][half * 2 + 0];
                float v1 = acc[i][jn][half * 2 + 1];
                size_t o = ((size_t)(b * SS + row) * HH + hh) * HDIM + cc;
                bf16 h0, l0, h1, l1;
                split_bf(v0, h0, l0); split_bf(v1, h1, l1);
                oh[o] = h0; oh[o + 1] = h1;
                ol[o] = l0; ol[o + 1] = l1;
            }
        }
}

// ---------------- router (also records per-token slot ids) ----------------
__global__ __launch_bounds__(256) void router_kernel(
    const float* __restrict__ hn, const float* __restrict__ wg)
{
    int tkn = blockIdx.x;
    int w = threadIdx.x >> 5, lane = threadIdx.x & 31;
    const float* x = hn + (size_t)tkn * DD;
    const float* g = wg + (size_t)w * DD;
    float s = 0.f;
    for (int i = lane; i < DD; i += 32) s += x[i] * g[i];
    s = warp_sum(s);
    __shared__ float lg[EE];
    if (lane == 0) lg[w] = s;
    __syncthreads();
    if (threadIdx.x == 0) {
        float m = -INFINITY;
        #pragma unroll
        for (int e = 0; e < EE; e++) m = fmaxf(m, lg[e]);
        float ex[EE];
        #pragma unroll
        for (int e = 0; e < EE; e++) ex[e] = expf(lg[e] - m);
        int i1 = 0; float m1 = ex[0];
        #pragma unroll
        for (int e = 1; e < EE; e++) if (ex[e] > m1) { m1 = ex[e]; i1 = e; }
        int i2 = -1; float m2 = -1.f;
        #pragma unroll
        for (int e = 0; e < EE; e++) if (e != i1 && ex[e] > m2) { m2 = ex[e]; i2 = e; }
        float inv = 1.0f / (m1 + m2);
        int p1 = atomicAdd(&g_cnt[i1], 1);
        g_tok[i1 * TT + p1] = tkn; g_twt[i1 * TT + p1] = m1 * inv;
        int p2 = atomicAdd(&g_cnt[i2], 1);
        g_tok[i2 * TT + p2] = tkn; g_twt[i2 * TT + p2] = m2 * inv;
        g_tslot[tkn * 2 + 0] = i1 * TT + p1;
        g_tslot[tkn * 2 + 1] = i2 * TT + p2;
    }
}

// ---------------- final: out = h + w0*moeX[s0] + w1*moeX[s1] ----------------
__global__ void final_gather_kernel(const float* __restrict__ h,
                                    const float* __restrict__ moeX,
                                    const int* __restrict__ tsl,
                                    const float* __restrict__ twt,
                                    float* __restrict__ out) {
    int t = blockIdx.x;
    int s0 = tsl[t * 2], s1 = tsl[t * 2 + 1];
    float w0 = twt[s0], w1 = twt[s1];
    const float* b0 = moeX + (size_t)s0 * DD;
    const float* b1 = moeX + (size_t)s1 * DD;
    const float* hr = h + (size_t)t * DD;
    float* o = out + (size_t)t * DD;
    for (int d = threadIdx.x; d < DD; d += 256)
        o[d] = hr[d] + w0 * b0[d] + w1 * b1[d];
}

// ======================= host =======================
extern "C" void kernel_launch(void* const* d_in, const int* in_sizes, int n_in,
                              void* d_out, int out_size) {
    const float* hidden = (const float*)d_in[0];
    const float* w_q    = (const float*)d_in[1];
    const float* w_k    = (const float*)d_in[2];
    const float* w_v    = (const float*)d_in[3];
    const float* w_o    = (const float*)d_in[4];
    const float* g1     = (const float*)d_in[5];
    const float* g2     = (const float*)d_in[6];
    const float* w_gate = (const float*)d_in[7];
    const float* w1     = (const float*)d_in[8];
    const float* w3     = (const float*)d_in[9];
    const float* w2     = (const float*)d_in[10];
    float* out = (float*)d_out;

    bf16 *p_wqkvn, *p_won, *p_w1n, *p_w3n, *p_w2n;
    float *p_wqkvs, *p_wos, *p_w1s, *p_w3s, *p_w2s;
    bf16 *p_hnh, *p_hnl, *p_oh, *p_ol, *p_uph, *p_upl;
    bf16 *p_xnh, *p_xnl;
    bf16 *p_qh, *p_ql, *p_kh, *p_kl, *p_vn, *p_ph, *p_pl;
    float *p_qkv, *p_vs, *p_sc, *p_h, *p_hn, *p_up1, *p_moeX, *p_twt;
    int *p_cnt, *p_tok, *p_tslot;
    cudaGetSymbolAddress((void**)&p_wqkvn, g_wqkvn); cudaGetSymbolAddress((void**)&p_wqkvs, g_wqkvs);
    cudaGetSymbolAddress((void**)&p_won, g_won); cudaGetSymbolAddress((void**)&p_wos, g_wos);
    cudaGetSymbolAddress((void**)&p_w1n, g_w1n); cudaGetSymbolAddress((void**)&p_w1s, g_w1s);
    cudaGetSymbolAddress((void**)&p_w3n, g_w3n); cudaGetSymbolAddress((void**)&p_w3s, g_w3s);
    cudaGetSymbolAddress((void**)&p_w2n, g_w2n); cudaGetSymbolAddress((void**)&p_w2s, g_w2s);
    cudaGetSymbolAddress((void**)&p_xnh, g_xnh); cudaGetSymbolAddress((void**)&p_xnl, g_xnl);
    cudaGetSymbolAddress((void**)&p_hnh, g_hnh); cudaGetSymbolAddress((void**)&p_hnl, g_hnl);
    cudaGetSymbolAddress((void**)&p_oh, g_oh);   cudaGetSymbolAddress((void**)&p_ol, g_ol);
    cudaGetSymbolAddress((void**)&p_uph, g_uph); cudaGetSymbolAddress((void**)&p_upl, g_upl);
    cudaGetSymbolAddress((void**)&p_qkv, g_qkv);
    cudaGetSymbolAddress((void**)&p_qh, g_qh);   cudaGetSymbolAddress((void**)&p_ql, g_ql);
    cudaGetSymbolAddress((void**)&p_kh, g_kh);   cudaGetSymbolAddress((void**)&p_kl, g_kl);
    cudaGetSymbolAddress((void**)&p_vn, g_vn);   cudaGetSymbolAddress((void**)&p_vs, g_vs);
    cudaGetSymbolAddress((void**)&p_sc, g_sc);
    cudaGetSymbolAddress((void**)&p_ph, g_ph);   cudaGetSymbolAddress((void**)&p_pl, g_pl);
    cudaGetSymbolAddress((void**)&p_h, g_h);     cudaGetSymbolAddress((void**)&p_hn, g_hn);
    cudaGetSymbolAddress((void**)&p_up1, g_up1); cudaGetSymbolAddress((void**)&p_moeX, g_moeX);
    cudaGetSymbolAddress((void**)&p_cnt, g_cnt); cudaGetSymbolAddress((void**)&p_tok, g_tok);
    cudaGetSymbolAddress((void**)&p_twt, g_twt); cudaGetSymbolAddress((void**)&p_tslot, g_tslot);

    cudaFuncSetAttribute(gemm_tc<0>, cudaFuncAttributeMaxDynamicSharedMemorySize, SMEM_SZ);
    cudaFuncSetAttribute(gemm_tc<1>, cudaFuncAttributeMaxDynamicSharedMemorySize, SMEM_SZ);
    cudaFuncSetAttribute(gemm_tc<2>, cudaFuncAttributeMaxDynamicSharedMemorySize, SMEM_SZ);
    cudaFuncSetAttribute(gemm_tc<4>, cudaFuncAttributeMaxDynamicSharedMemorySize, SMEM_SZ);
    cudaFuncSetAttribute(gemm_tc<5>, cudaFuncAttributeMaxDynamicSharedMemorySize, SMEM_SZ);
    cudaFuncSetAttribute(scores_tc, cudaFuncAttributeMaxDynamicSharedMemorySize, SCR_SMEM);
    cudaFuncSetAttribute(av_tc, cudaFuncAttributeMaxDynamicSharedMemorySize, AV_SMEM);

    static cudaStream_t s2 = nullptr;
    static cudaEvent_t ev_fork = nullptr, ev_join = nullptr;
    if (!s2) {
        cudaStreamCreateWithFlags(&s2, cudaStreamNonBlocking);
        cudaEventCreateWithFlags(&ev_fork, cudaEventDisableTiming);
        cudaEventCreateWithFlags(&ev_join, cudaEventDisableTiming);
    }

    zero_cnt_kernel<<<1, 32>>>(p_cnt);

    // fork: big MoE weight quants on s2 (chip-saturating, but overlap is free)
    cudaEventRecord(ev_fork, 0);
    cudaStreamWaitEvent(s2, ev_fork, 0);
    quantw_kernel<<<28672, 256, 0, s2>>>(w1, p_w1n, p_w1s, EE * FFND * DD / 128);
    quantw_kernel<<<28672, 256, 0, s2>>>(w3, p_w3n, p_w3s, EE * FFND * DD / 128);
    quantw_kernel<<<28672, 256, 0, s2>>>(w2, p_w2n, p_w2s, EE * DD * FFND / 128);
    cudaEventRecord(ev_join, s2);

    quantw_kernel<<<1024, 256>>>(w_q, p_wqkvn, p_wqkvs, DD * DD / 128);
    quantw_kernel<<<256, 256>>>(w_k, p_wqkvn + 1024 * DD, p_wqkvs + 1024 * 8, KV * HDIM * DD / 128);
    quantw_kernel<<<256, 256>>>(w_v, p_wqkvn + 1280 * DD, p_wqkvs + 1280 * 8, KV * HDIM * DD / 128);
    quantw_kernel<<<1024, 256>>>(w_o, p_won, p_wos, DD * DD / 128);

    // ---- attention ----
    rms_split_kernel<false><<<TT, 256>>>(hidden, g1, nullptr, p_xnh, p_xnl);
    gemm_tc<0><<<dim3(12, 16, 1), 256, SMEM_SZ>>>(p_xnh, p_xnl, DD, 0,
        p_wqkvn, p_wqkvs, DD, 0, 0,
        p_qkv, nullptr, nullptr, NQKV, 0, TT, nullptr, DD, nullptr, nullptr);
    kvprep_kernel<<<TT * (HH + KV + KV), HDIM>>>(p_qkv, p_qh, p_ql, p_kh, p_kl, p_vn, p_vs);
    scores_tc<<<dim3(8, 8, BB * HH), 256, SCR_SMEM>>>(p_qh, p_ql, p_kh, p_kl, p_sc);
    softmax_kernel<<<BB * HH * SS, 256>>>(p_sc, p_vs, p_ph, p_pl);
    av_tc<<<dim3(1, 8, BB * HH), 256, AV_SMEM>>>(p_ph, p_pl, p_vn, p_oh, p_ol);
    gemm_tc<1><<<dim3(8, 16, 1), 256, SMEM_SZ>>>(p_oh, p_ol, DD, 0,
        p_won, p_wos, DD, 0, 0,
        p_h, nullptr, nullptr, DD, 0, TT, nullptr, DD, hidden, nullptr);

    // ---- MoE ----
    rms_split_kernel<true><<<TT, 256>>>(p_h, g2, p_hn, p_hnh, p_hnl);
    router_kernel<<<TT, 256>>>(p_hn, w_gate);
    cudaStreamWaitEvent(0, ev_join, 0);
    gemm_tc<2><<<dim3(28, 16, EE), 256, SMEM_SZ>>>(p_hnh, p_hnl, DD, 0,
        p_w1n, p_w1s, DD, (size_t)FFND * DD, (size_t)FFND * 8,
        p_up1, nullptr, nullptr, FFND, (size_t)TT * FFND,
        0, p_cnt, DD, nullptr, p_tok);
    gemm_tc<4><<<dim3(28, 16, EE), 256, SMEM_SZ>>>(p_hnh, p_hnl, DD, 0,
        p_w3n, p_w3s, DD, (size_t)FFND * DD, (size_t)FFND * 8,
        nullptr, p_uph, p_upl, FFND, (size_t)TT * FFND,
        0, p_cnt, DD, p_up1, p_tok);
    gemm_tc<5><<<dim3(8, 16, EE), 256, SMEM_SZ>>>(p_uph, p_upl, FFND, (size_t)TT * FFND,
        p_w2n, p_w2s, FFND, (size_t)DD * FFND, (size_t)DD * 28,
        p_moeX, nullptr, nullptr, DD, (size_t)TT * DD,
        0, p_cnt, FFND, nullptr, nullptr);
    final_gather_kernel<<<TT, 256>>>(p_h, p_moeX, p_tslot, p_twt, out);
}

// round 14
// speedup vs baseline: 1.9221x; 1.0063x over previous
#include <cuda_runtime.h>
#include <cuda_bf16.h>
#include <math.h>
#include <stdint.h>

#define BB 2
#define SS 1024
#define TT 2048
#define DD 1024
#define HH 8
#define KV 2
#define HDIM 128
#define EE 8
#define FFND 3584
#define NQKV 1536

#define KT 64
#define STAGES 4
#define TILE_BYTES 16384
#define STAGE_BYTES (3 * TILE_BYTES)
#define SC_OFF (STAGES * STAGE_BYTES)
#define SMEM_SZ (SC_OFF + 28 * 128 * 4)
#define SCR_SMEM (2 * 4 * TILE_BYTES)
#define AV_STAGE (3 * TILE_BYTES)
#define AV_SMEM (3 * AV_STAGE)

typedef __nv_bfloat16 bf16;

// weights: integer bf16 + per-group fp32 scale
__device__ bf16  g_wqkvn[NQKV * DD];       __device__ float g_wqkvs[NQKV * DD / 128];
__device__ bf16  g_won[DD * DD];           __device__ float g_wos[DD * DD / 128];
__device__ bf16  g_w1n[EE * FFND * DD];    __device__ float g_w1s[EE * FFND * DD / 128];
__device__ bf16  g_w3n[EE * FFND * DD];    __device__ float g_w3s[EE * FFND * DD / 128];
__device__ bf16  g_w2n[EE * DD * FFND];    __device__ float g_w2s[EE * DD * FFND / 128];
// activations
__device__ bf16 g_xnh[TT * DD];        __device__ bf16 g_xnl[TT * DD];
__device__ bf16 g_hnh[TT * DD];        __device__ bf16 g_hnl[TT * DD];
__device__ bf16 g_oh[TT * DD];         __device__ bf16 g_ol[TT * DD];
__device__ bf16 g_uph[EE * TT * FFND]; __device__ bf16 g_upl[EE * TT * FFND];
__device__ float g_qkv[TT * NQKV];
__device__ bf16 g_qh[TT * DD];         __device__ bf16 g_ql[TT * DD];
__device__ bf16 g_kh[TT * KV * HDIM];  __device__ bf16 g_kl[TT * KV * HDIM];
__device__ bf16 g_vn[TT * KV * HDIM];  __device__ float g_vs[TT * KV];
__device__ float g_sc[BB * HH * SS * SS];
__device__ bf16 g_ph[BB * HH * SS * SS];
__device__ bf16 g_pl[BB * HH * SS * SS];
__device__ float g_h[TT * DD];
__device__ float g_hn[TT * DD];
__device__ float g_up1[EE * TT * FFND];
__device__ float g_moeX[EE * TT * DD];
__device__ int   g_cnt[EE];
__device__ int   g_tok[EE * TT];
__device__ float g_twt[EE * TT];
__device__ int   g_tslot[TT * 2];

// ---------------- ptx helpers ----------------
__device__ __forceinline__ uint32_t smem_u32(const void* p) {
    uint32_t a;
    asm("{ .reg .u64 t; cvta.to.shared.u64 t, %1; cvt.u32.u64 %0, t; }" : "=r"(a) : "l"(p));
    return a;
}
__device__ __forceinline__ void ldsm4(uint32_t a, uint32_t& r0, uint32_t& r1,
                                      uint32_t& r2, uint32_t& r3) {
    asm volatile("ldmatrix.sync.aligned.m8n8.x4.shared.b16 {%0,%1,%2,%3}, [%4];"
                 : "=r"(r0), "=r"(r1), "=r"(r2), "=r"(r3) : "r"(a));
}
__device__ __forceinline__ void ldsm4t(uint32_t a, uint32_t& r0, uint32_t& r1,
                                       uint32_t& r2, uint32_t& r3) {
    asm volatile("ldmatrix.sync.aligned.m8n8.x4.trans.shared.b16 {%0,%1,%2,%3}, [%4];"
                 : "=r"(r0), "=r"(r1), "=r"(r2), "=r"(r3) : "r"(a));
}
__device__ __forceinline__ void mma16816(float* c, const uint32_t* a, const uint32_t* b) {
    asm volatile("mma.sync.aligned.m16n8k16.row.col.f32.bf16.bf16.f32 "
                 "{%0,%1,%2,%3}, {%4,%5,%6,%7}, {%8,%9}, {%0,%1,%2,%3};"
                 : "+f"(c[0]), "+f"(c[1]), "+f"(c[2]), "+f"(c[3])
                 : "r"(a[0]), "r"(a[1]), "r"(a[2]), "r"(a[3]), "r"(b[0]), "r"(b[1]));
}
__device__ __forceinline__ void cpa16(uint32_t dst, const void* src) {
    asm volatile("cp.async.cg.shared.global [%0], [%1], 16;" :: "r"(dst), "l"(src));
}
__device__ __forceinline__ void cpa_commit() { asm volatile("cp.async.commit_group;" ::: "memory"); }
__device__ __forceinline__ void cpa_wait0() { asm volatile("cp.async.wait_group 0;" ::: "memory"); }
__device__ __forceinline__ void cpa_wait1() { asm volatile("cp.async.wait_group 1;" ::: "memory"); }
__device__ __forceinline__ void cpa_wait2() { asm volatile("cp.async.wait_group 2;" ::: "memory"); }

__device__ __forceinline__ float warp_min(float v) {
    #pragma unroll
    for (int o = 16; o; o >>= 1) v = fminf(v, __shfl_xor_sync(0xffffffffu, v, o));
    return v;
}
__device__ __forceinline__ float warp_max(float v) {
    #pragma unroll
    for (int o = 16; o; o >>= 1) v = fmaxf(v, __shfl_xor_sync(0xffffffffu, v, o));
    return v;
}
__device__ __forceinline__ float warp_sum(float v) {
    #pragma unroll
    for (int o = 16; o; o >>= 1) v += __shfl_xor_sync(0xffffffffu, v, o);
    return v;
}
__device__ __forceinline__ void split_bf(float v, bf16& h, bf16& l) {
    h = __float2bfloat16(v);
    l = __float2bfloat16(v - __bfloat162float(h));
}
__device__ __forceinline__ uint32_t swz(uint32_t off) { return off ^ ((off >> 3) & 0x70); }

// ---------------- small kernels ----------------
__global__ void zero_cnt_kernel(int* __restrict__ cnt) {
    if (threadIdx.x < EE) cnt[threadIdx.x] = 0;
}

__global__ void quantw_kernel(const float* __restrict__ w, bf16* __restrict__ nq,
                              float* __restrict__ sc, int ngroups) {
    int g = blockIdx.x * 8 + (threadIdx.x >> 5);
    if (g >= ngroups) return;
    int lane = threadIdx.x & 31;
    float4 v = reinterpret_cast<const float4*>(w)[(size_t)g * 32 + lane];
    float mn = fminf(fminf(v.x, v.y), fminf(v.z, v.w));
    float mx = fmaxf(fmaxf(v.x, v.y), fmaxf(v.z, v.w));
    mn = warp_min(mn); mx = warp_max(mx);
    float scale = fmaxf(mx - mn, 1e-5f) / 15.0f;
    float sinv = 1.0f / scale;
    float base = fminf(fmaxf(rintf(-mn * sinv), 0.f), 15.f);
    // clamp(rint(v*sinv)+base, 0, 15) - base == clamp(rint(v*sinv), -base, 15-base)
    float qmin = -base, qmax = 15.0f - base;
    float r[4] = {v.x, v.y, v.z, v.w};
    bf16 n4[4];
    #pragma unroll
    for (int j = 0; j < 4; j++) {
        float q = fminf(fmaxf(rintf(r[j] * sinv), qmin), qmax);
        n4[j] = __float2bfloat16(q);  // exact integer in [-15,15]
    }
    size_t idx = (size_t)g * 128 + lane * 4;
    *reinterpret_cast<uint2*>(nq + idx) = *reinterpret_cast<uint2*>(n4);
    if (lane == 0) sc[g] = scale;
}

template<bool WF32>
__global__ void rms_split_kernel(const float* __restrict__ x, const float* __restrict__ g,
                                 float* __restrict__ f32o, bf16* __restrict__ hi,
                                 bf16* __restrict__ lo) {
    int row = blockIdx.x;
    const float* xr = x + (size_t)row * DD;
    float s = 0.f;
    for (int i = threadIdx.x; i < DD; i += 256) { float v = xr[i]; s += v * v; }
    __shared__ float sh[256];
    sh[threadIdx.x] = s; __syncthreads();
    for (int o2 = 128; o2; o2 >>= 1) {
        if (threadIdx.x < o2) sh[threadIdx.x] += sh[threadIdx.x + o2];
        __syncthreads();
    }
    float inv = rsqrtf(sh[0] * (1.0f / DD) + 1e-5f);
    for (int i = threadIdx.x; i < DD; i += 256) {
        float v = xr[i] * inv * g[i];
        if (WF32) f32o[(size_t)row * DD + i] = v;
        bf16 h, l; split_bf(v, h, l);
        hi[(size_t)row * DD + i] = h;
        lo[(size_t)row * DD + i] = l;
    }
}

// ===== bf16x2 mma.sync GEMM with exact integer weights + per-group rescale =====
// MODE 0 store f32 | 1 +resid | 2 gather-A, M=Mptr[z] | 4 gather-A, silu(resid)*acc
// split-> CH/CL | 5 direct-A slot rows, M=Mptr[z], store f32 z-strided
template<int MODE>
__global__ __launch_bounds__(256, 1) void gemm_tc(
    const bf16* __restrict__ Ahi, const bf16* __restrict__ Alo, int lda, size_t strideA,
    const bf16* __restrict__ Bn, const float* __restrict__ Bsc, int ldb,
    size_t strideB, size_t strideBs,
    float* __restrict__ C, bf16* __restrict__ CH, bf16* __restrict__ CL,
    int ldc, size_t strideC,
    int M, const int* __restrict__ Mptr, int K,
    const float* __restrict__ resid, const int* __restrict__ idx)
{
    int z = blockIdx.z;
    if (Mptr) M = Mptr[z];
    int m0 = blockIdx.y * 128;
    if (m0 >= M) return;
    int n0 = blockIdx.x * 128;
    int tid = threadIdx.x;
    int wid = tid >> 5, lid = tid & 31;

    extern __shared__ char smem[];
    uint32_t sb = smem_u32(smem);
    float* scs = reinterpret_cast<float*>(smem + SC_OFF);
    const int* idxz = (MODE == 2 || MODE == 4) ? (idx + (size_t)z * TT) : (const int*)nullptr;
    int G = K >> 7;

    for (int i = tid; i < G * 128; i += 256) {
        int g = i >> 7, c = i & 127;
        scs[i] = Bsc[strideBs * z + (size_t)(n0 + c) * G + g];
    }

    const bf16* srcA[4]; const bf16* srcB[4];
    uint32_t dstA[4], dstB[4];
    ptrdiff_t dlo = Alo - Ahi;
    #pragma unroll
    for (int ci = 0; ci < 4; ci++) {
        int gid = ci * 256 + tid;
        int r = (gid >> 3) & 127;
        int c8 = gid & 7;
        int row = m0 + r;
        if (row >= M) row = m0;
        int rg = (MODE == 2 || MODE == 4) ? idxz[row] : row;
        srcA[ci] = Ahi + strideA * (size_t)z + (size_t)rg * lda + c8 * 8;
        dstA[ci] = swz((uint32_t)(r * 128 + c8 * 16));
        int gid2 = 2048 + gid;
        int r2 = (gid2 >> 3) & 127;
        int c82 = gid2 & 7;
        srcB[ci] = Bn + strideB * (size_t)z + (size_t)(n0 + r2) * ldb + c82 * 8;
        dstB[ci] = (uint32_t)(2 * TILE_BYTES) + swz((uint32_t)(r2 * 128 + c82 * 16));
    }

    int n_kt = K / KT;
    int npro = STAGES - 1; if (npro > n_kt) npro = n_kt;
    #pragma unroll 1
    for (int p = 0; p < npro; p++) {
        uint32_t base = sb + p * STAGE_BYTES;
        size_t ko = (size_t)p * KT;
        #pragma unroll
        for (int ci = 0; ci < 4; ci++) {
            cpa16(base + dstA[ci], srcA[ci] + ko);
            cpa16(base + TILE_BYTES + dstA[ci], srcA[ci] + dlo + ko);
            cpa16(base + dstB[ci], srcB[ci] + ko);
        }
        cpa_commit();
    }

    int wr = (wid & 3) * 32;
    int wc = (wid >> 2) * 64;
    int rowm = (lid & 7) + ((lid >> 3) & 1) * 8;
    int colb = (lid >> 4) * 16;

    float acc[2][8][4] = {};
    float accg[2][8][4] = {};

    #pragma unroll 1
    for (int kt = 0; kt < n_kt; kt++) {
        int pending = n_kt - kt - 1; if (pending > STAGES - 2) pending = STAGES - 2;
        if (pending >= 2) cpa_wait2();
        else if (pending == 1) cpa_wait1();
        else cpa_wait0();
        __syncthreads();
        if (kt + STAGES - 1 < n_kt) {
            int sl = (kt + STAGES - 1) % STAGES;
            uint32_t base = sb + sl * STAGE_BYTES;
            size_t ko = (size_t)(kt + STAGES - 1) * KT;
            #pragma unroll
            for (int ci = 0; ci < 4; ci++) {
                cpa16(base + dstA[ci], srcA[ci] + ko);
                cpa16(base + TILE_BYTES + dstA[ci], srcA[ci] + dlo + ko);
                cpa16(base + dstB[ci], srcB[ci] + ko);
            }
            cpa_commit();
        }
        uint32_t sbase = sb + (kt % STAGES) * STAGE_BYTES;
        #pragma unroll
        for (int s16 = 0; s16 < 4; s16++) {
            int kb0 = s16 * 32 + colb;
            uint32_t ah[2][4], al[2][4], bn[8][2];
            #pragma unroll
            for (int i = 0; i < 2; i++) {
                uint32_t off = (uint32_t)((wr + i * 16 + rowm) * 128 + kb0);
                ldsm4(sbase + swz(off), ah[i][0], ah[i][1], ah[i][2], ah[i][3]);
                ldsm4(sbase + TILE_BYTES + swz(off), al[i][0], al[i][1], al[i][2], al[i][3]);
            }
            #pragma unroll
            for (int j = 0; j < 4; j++) {
                uint32_t off = (uint32_t)((wc + j * 16 + rowm) * 128 + kb0);
                uint32_t r0, r1, r2, r3;
                ldsm4(sbase + 2 * TILE_BYTES + swz(off), r0, r1, r2, r3);
                bn[j * 2][0] = r0; bn[j * 2][1] = r2;
                bn[j * 2 + 1][0] = r1; bn[j * 2 + 1][1] = r3;
            }
            #pragma unroll
            for (int i = 0; i < 2; i++)
                #pragma unroll
                for (int jn = 0; jn < 8; jn++) {
                    mma16816(accg[i][jn], ah[i], bn[jn]);
                    mma16816(accg[i][jn], al[i], bn[jn]);
                }
        }
        if (kt & 1) {
            int g = kt >> 1;
            #pragma unroll
            for (int jn = 0; jn < 8; jn++) {
                int c = wc + jn * 8 + (lid & 3) * 2;
                float s0 = scs[g * 128 + c];
                float s1 = scs[g * 128 + c + 1];
                #pragma unroll
                for (int i = 0; i < 2; i++) {
                    acc[i][jn][0] += s0 * accg[i][jn][0];
                    acc[i][jn][1] += s1 * accg[i][jn][1];
                    acc[i][jn][2] += s0 * accg[i][jn][2];
                    acc[i][jn][3] += s1 * accg[i][jn][3];
                    accg[i][jn][0] = 0.f; accg[i][jn][1] = 0.f;
                    accg[i][jn][2] = 0.f; accg[i][jn][3] = 0.f;
                }
            }
        }
    }

    #pragma unroll
    for (int i = 0; i < 2; i++) {
        #pragma unroll
        for (int jn = 0; jn < 8; jn++) {
            int r0 = m0 + wr + i * 16 + (lid >> 2);
            int cc = n0 + wc + jn * 8 + (lid & 3) * 2;
            #pragma unroll
            for (int half = 0; half < 2; half++) {
                int row = r0 + half * 8;
                if (row >= M) continue;
                float v0 = acc[i][jn][half * 2 + 0];
                float v1 = acc[i][jn][half * 2 + 1];
                if (MODE == 0 || MODE == 1 || MODE == 2 || MODE == 5) {
                    float* Cr = C + strideC * z + (size_t)row * ldc + cc;
                    if (MODE == 1) {
                        const float* rr = resid + (size_t)row * ldc + cc;
                        v0 += rr[0]; v1 += rr[1];
                    }
                    *reinterpret_cast<float2*>(Cr) = make_float2(v0, v1);
                } else {  // MODE 4
                    const float* ar = resid + strideC * z + (size_t)row * ldc + cc;
                    float a0 = ar[0], a1 = ar[1];
                    float gv0 = (a0 / (1.f + expf(-a0))) * v0;
                    float gv1 = (a1 / (1.f + expf(-a1))) * v1;
                    bf16 h0, l0, h1, l1;
                    split_bf(gv0, h0, l0); split_bf(gv1, h1, l1);
                    size_t o = strideC * z + (size_t)row * ldc + cc;
                    CH[o] = h0; CH[o + 1] = h1;
                    CL[o] = l0; CL[o + 1] = l1;
                }
            }
        }
    }
}

// ---------------- fused q-rope / k-quant+rope / v-quant prep ----------------
__global__ void kvprep_kernel(const float* __restrict__ qkv,
                              bf16* __restrict__ qh, bf16* __restrict__ ql,
                              bf16* __restrict__ kh, bf16* __restrict__ kl,
                              bf16* __restrict__ vn, float* __restrict__ vs) {
    int j = blockIdx.x;
    int d = threadIdx.x;
    __shared__ float smn[HDIM], smx[HDIM], sh[HDIM];
    if (j < TT * HH) {
        int t = j >> 3, hh = j & 7;
        sh[d] = qkv[(size_t)t * NQKV + hh * HDIM + d];
        __syncthreads();
        int pos = t & (SS - 1);
        int i = d & 63;
        float invf = expf(-13.815510557964274f * ((float)(2 * i) * (1.0f / HDIM)));
        float f = (float)pos * invf;
        float c = cosf(f), sn = sinf(f);
        float v = (d < 64) ? (sh[d] * c - sh[d + 64] * sn)
                           : (sh[d] * c + sh[d - 64] * sn);
        bf16 h, l; split_bf(v, h, l);
        qh[(size_t)j * HDIM + d] = h;
        ql[(size_t)j * HDIM + d] = l;
        return;
    }
    int j2 = j - TT * HH;
    bool isK = j2 < TT * KV;
    int rowid = isK ? j2 : (j2 - TT * KV);
    int t = rowid >> 1, kvh = rowid & 1;
    float v = qkv[(size_t)t * NQKV + (isK ? 1024 : 1280) + kvh * HDIM + d];
    smn[d] = v; smx[d] = v; __syncthreads();
    for (int o2 = 64; o2; o2 >>= 1) {
        if (d < o2) {
            smn[d] = fminf(smn[d], smn[d + o2]);
            smx[d] = fmaxf(smx[d], smx[d + o2]);
        }
        __syncthreads();
    }
    float scale = fmaxf(smx[0] - smn[0], 1e-5f) / 15.0f;
    float sinv = 1.0f / scale;
    float base = fminf(fmaxf(rintf(-smn[0] * sinv), 0.f), 15.f);
    float qn = fminf(fmaxf(rintf(v * sinv), -base), 15.0f - base);
    if (!isK) {
        vn[(size_t)rowid * HDIM + d] = __float2bfloat16(qn);
        if (d == 0) vs[rowid] = scale;
        return;
    }
    float q = qn * scale;
    sh[d] = q; __syncthreads();
    int pos = t & (SS - 1);
    int i = d & 63;
    float invf = expf(-13.815510557964274f * ((float)(2 * i) * (1.0f / HDIM)));
    float f = (float)pos * invf;
    float c = cosf(f), sn = sinf(f);
    q = (d < 64) ? (sh[d] * c - sh[d + 64] * sn)
                 : (sh[d] * c + sh[d - 64] * sn);
    bf16 h, l; split_bf(q, h, l);
    kh[(size_t)rowid * HDIM + d] = h;
    kl[(size_t)rowid * HDIM + d] = l;
}

// ---------------- TC scores ----------------
__global__ __launch_bounds__(256, 1) void scores_tc(
    const bf16* __restrict__ qh, const bf16* __restrict__ ql,
    const bf16* __restrict__ kh, const bf16* __restrict__ kl,
    float* __restrict__ sc)
{
    int z = blockIdx.z;
    int m0 = blockIdx.y * 128, n0 = blockIdx.x * 128;
    if (n0 > m0) return;
    int b = z >> 3, hh = z & 7, kvh = (z & 7) >> 2;
    int tid = threadIdx.x, wid = tid >> 5, lid = tid & 31;
    extern __shared__ char smem[];
    uint32_t sb = smem_u32(smem);

    const bf16* src[16]; uint32_t dst[16];
    #pragma unroll
    for (int ci = 0; ci < 16; ci++) {
        int gid = ci * 256 + tid;
        int t4 = gid >> 10;
        int r = (gid >> 3) & 127;
        int c8 = gid & 7;
        const bf16* p;
        if (t4 == 0)      p = qh + ((size_t)(b * SS + m0 + r) * HH + hh) * HDIM;
        else if (t4 == 1) p = ql + ((size_t)(b * SS + m0 + r) * HH + hh) * HDIM;
        else if (t4 == 2) p = kh + ((size_t)(b * SS + n0 + r) * KV + kvh) * HDIM;
        else              p = kl + ((size_t)(b * SS + n0 + r) * KV + kvh) * HDIM;
        src[ci] = p + c8 * 8;
        dst[ci] = (uint32_t)(t4 * TILE_BYTES) + swz((uint32_t)(r * 128 + c8 * 16));
    }
    #pragma unroll
    for (int ci = 0; ci < 16; ci++) cpa16(sb + dst[ci], src[ci]);
    cpa_commit();
    #pragma unroll
    for (int ci = 0; ci < 16; ci++) cpa16(sb + 4 * TILE_BYTES + dst[ci], src[ci] + 64);
    cpa_commit();

    int wr = (wid & 3) * 32;
    int wc = (wid >> 2) * 64;
    int rowm = (lid & 7) + ((lid >> 3) & 1) * 8;
    int colb = (lid >> 4) * 16;
    float acc[2][8][4] = {};

    #pragma unroll 1
    for (int ch = 0; ch < 2; ch++) {
        if (ch == 0) cpa_wait1(); else cpa_wait0();
        __syncthreads();
        uint32_t base = sb + ch * 4 * TILE_BYTES;
        #pragma unroll
        for (int s16 = 0; s16 < 4; s16++) {
            int kb0 = s16 * 32 + colb;
            uint32_t ah[2][4], al[2][4], bh[8][2], bl[8][2];
            #pragma unroll
            for (int i = 0; i < 2; i++) {
                uint32_t off = (uint32_t)((wr + i * 16 + rowm) * 128 + kb0);
                ldsm4(base + swz(off), ah[i][0], ah[i][1], ah[i][2], ah[i][3]);
                ldsm4(base + TILE_BYTES + swz(off), al[i][0], al[i][1], al[i][2], al[i][3]);
            }
            #pragma unroll
            for (int j = 0; j < 4; j++) {
                uint32_t off = (uint32_t)((wc + j * 16 + rowm) * 128 + kb0);
                uint32_t r0, r1, r2, r3;
                ldsm4(base + 2 * TILE_BYTES + swz(off), r0, r1, r2, r3);
                bh[j * 2][0] = r0; bh[j * 2][1] = r2;
                bh[j * 2 + 1][0] = r1; bh[j * 2 + 1][1] = r3;
                ldsm4(base + 3 * TILE_BYTES + swz(off), r0, r1, r2, r3);
                bl[j * 2][0] = r0; bl[j * 2][1] = r2;
                bl[j * 2 + 1][0] = r1; bl[j * 2 + 1][1] = r3;
            }
            #pragma unroll
            for (int i = 0; i < 2; i++)
                #pragma unroll
                for (int jn = 0; jn < 8; jn++) {
                    mma16816(acc[i][jn], ah[i], bh[jn]);
                    mma16816(acc[i][jn], ah[i], bl[jn]);
                    mma16816(acc[i][jn], al[i], bh[jn]);
                }
        }
    }
    const float scalef = 0.08838834764831845f;
    float* C = sc + (size_t)z * SS * SS;
    #pragma unroll
    for (int i = 0; i < 2; i++)
        #pragma unroll
        for (int jn = 0; jn < 8; jn++) {
            int r0 = m0 + wr + i * 16 + (lid >> 2);
            int cc = n0 + wc + jn * 8 + (lid & 3) * 2;
            #pragma unroll
            for (int half = 0; half < 2; half++) {
                int row = r0 + half * 8;
                float v0 = acc[i][jn][half * 2 + 0] * scalef;
                float v1 = acc[i][jn][half * 2 + 1] * scalef;
                *reinterpret_cast<float2*>(C + (size_t)row * SS + cc) = make_float2(v0, v1);
            }
        }
}

// ------- softmax: exp values kept in registers; sc is read-only here ----------
__global__ void softmax_kernel(const float* __restrict__ sc, const float* __restrict__ vs,
                               bf16* __restrict__ ph, bf16* __restrict__ pl) {
    int r = blockIdx.x;
    int z = r >> 10;
    int s = r & (SS - 1);
    int b = z >> 3, kvh = (z & 7) >> 2;
    const float* row = sc + (size_t)r * SS;
    int n = s + 1;
    int nlim = (s | 127) + 1;
    __shared__ float sh[256];
    float m = -INFINITY;
    #pragma unroll
    for (int j = 0; j < 4; j++) {
        int i = threadIdx.x + j * 256;
        if (i < n) m = fmaxf(m, row[i]);
    }
    sh[threadIdx.x] = m; __syncthreads();
    for (int o2 = 128; o2; o2 >>= 1) {
        if (threadIdx.x < o2) sh[threadIdx.x] = fmaxf(sh[threadIdx.x], sh[threadIdx.x + o2]);
        __syncthreads();
    }
    m = sh[0]; __syncthreads();
    float ev[4];
    float sum = 0.f;
    #pragma unroll
    for (int j = 0; j < 4; j++) {
        int i = threadIdx.x + j * 256;
        float e = (i < n) ? expf(row[i] - m) : 0.f;
        ev[j] = e; sum += e;
    }
    sh[threadIdx.x] = sum; __syncthreads();
    for (int o2 = 128; o2; o2 >>= 1) {
        if (threadIdx.x < o2) sh[threadIdx.x] += sh[threadIdx.x + o2];
        __syncthreads();
    }
    float inv = 1.0f / sh[0];
    #pragma unroll
    for (int j = 0; j < 4; j++) {
        int i = threadIdx.x + j * 256;
        if (i >= nlim) break;
        float pv = ev[j] * inv * vs[(size_t)((b * SS + i) * KV + kvh)];
        bf16 h, l; split_bf(pv, h, l);
        ph[(size_t)r * SS + i] = h;
        pl[(size_t)r * SS + i] = l;
    }
}

// ---------------- TC AV ----------------
__global__ __launch_bounds__(256, 1) void av_tc(
    const bf16* __restrict__ ph, const bf16* __restrict__ pl,
    const bf16* __restrict__ vn, bf16* __restrict__ oh, bf16* __restrict__ ol)
{
    int z = blockIdx.z;
    int b = z >> 3, hh = z & 7, kvh = (z & 7) >> 2;
    int m0 = blockIdx.y * 128;
    int tid = threadIdx.x, wid = tid >> 5, lid = tid & 31;
    extern __shared__ char smem[];
    uint32_t sb = smem_u32(smem);

    const bf16* srcP[4]; const bf16* srcV[4];
    uint32_t dstP[4], dstV[4];
    ptrdiff_t dpl = pl - ph;
    #pragma unroll
    for (int ci = 0; ci < 4; ci++) {
        int gid = ci * 256 + tid;
        int r = (gid >> 3) & 127;
        int c8 = gid & 7;
        srcP[ci] = ph + (size_t)z * SS * SS + (size_t)(m0 + r) * SS + c8 * 8;
        dstP[ci] = swz((uint32_t)(r * 128 + c8 * 16));
        int gid2 = 2048 + gid;
        int vrow = (gid2 >> 4) & 63;
        int c16 = gid2 & 15;
        int plane = c16 >> 3, cc8 = c16 & 7;
        srcV[ci] = vn + ((size_t)(b * SS + vrow) * KV + kvh) * HDIM + plane * 64 + cc8 * 8;
        dstV[ci] = (uint32_t)(2 * TILE_BYTES + plane * 8192) + swz((uint32_t)(vrow * 128 + cc8 * 16));
    }

    int n_ch = (m0 >> 6) + 2;
    #pragma unroll 1
    for (int p = 0; p < 2 && p < n_ch; p++) {
        uint32_t base = sb + p * AV_STAGE;
        #pragma unroll
        for (int ci = 0; ci < 4; ci++) {
            size_t ko = (size_t)p * KT;
            cpa16(base + dstP[ci], srcP[ci] + ko);
            cpa16(base + TILE_BYTES + dstP[ci], srcP[ci] + dpl + ko);
            cpa16(base + dstV[ci], srcV[ci] + ko * (KV * HDIM));
        }
        cpa_commit();
    }

    int wr = (wid & 3) * 32;
    int wc = (wid >> 2) * 64;
    int vplane = wc >> 6;
    int rowm = (lid & 7) + ((lid >> 3) & 1) * 8;
    int colb = (lid >> 4) * 16;
    float acc[2][8][4] = {};

    #pragma unroll 1
    for (int kt = 0; kt < n_ch; kt++) {
        cpa_wait1();
        __syncthreads();
        if (kt + 2 < n_ch) {
            int sl = (kt + 2) % 3;
            uint32_t base = sb + sl * AV_STAGE;
            size_t ko = (size_t)(kt + 2) * KT;
            #pragma unroll
            for (int ci = 0; ci < 4; ci++) {
                cpa16(base + dstP[ci], srcP[ci] + ko);
                cpa16(base + TILE_BYTES + dstP[ci], srcP[ci] + dpl + ko);
                cpa16(base + dstV[ci], srcV[ci] + ko * (KV * HDIM));
            }
            cpa_commit();
        }
        uint32_t sbase = sb + (kt % 3) * AV_STAGE;
        uint32_t vbase = sbase + 2 * TILE_BYTES + vplane * 8192;
        #pragma unroll
        for (int s16 = 0; s16 < 4; s16++) {
            int kb0 = s16 * 32 + colb;
            uint32_t ah[2][4], al[2][4], bv[8][2];
            #pragma unroll
            for (int i = 0; i < 2; i++) {
                uint32_t off = (uint32_t)((wr + i * 16 + rowm) * 128 + kb0);
                ldsm4(sbase + swz(off), ah[i][0], ah[i][1], ah[i][2], ah[i][3]);
                ldsm4(sbase + TILE_BYTES + swz(off), al[i][0], al[i][1], al[i][2], al[i][3]);
            }
            #pragma unroll
            for (int j16 = 0; j16 < 4; j16++) {
                uint32_t krow = (uint32_t)(s16 * 16 + (lid & 7) + 8 * ((lid >> 3) & 1));
                uint32_t off = krow * 128 + (uint32_t)(j16 * 32 + 16 * (lid >> 4));
                uint32_t r0, r1, r2, r3;
                ldsm4t(vbase + swz(off), r0, r1, r2, r3);
                bv[j16 * 2][0] = r0; bv[j16 * 2][1] = r1;
                bv[j16 * 2 + 1][0] = r2; bv[j16 * 2 + 1][1] = r3;
            }
            #pragma unroll
            for (int i = 0; i < 2; i++)
                #pragma unroll
                for (int jn = 0; jn < 8; jn++) {
                    mma16816(acc[i][jn], ah[i], bv[jn]);
                    mma16816(acc[i][jn], al[i], bv[jn]);
                }
        }
    }

    #pragma unroll
    for (int i = 0; i < 2; i++)
        #pragma unroll
        for (int jn = 0; jn < 8; jn++) {
            int r0 = m0 + wr + i * 16 + (lid >> 2);
            int cc = wc + jn * 8 + (lid & 3) * 2;
            #pragma unroll
            for (int half = 0; half < 2; half++) {
                int row = r0 + half * 8;
                float v0 = acc[i][jn][half * 2 + 0];
                float v1 = acc[i][jn][half * 2 + 1];
                size_t o = ((size_t)(b * SS + row) * HH + hh) * HDIM + cc;
                bf16 h0, l0, h1, l1;
                split_bf(v0, h0, l0); split_bf(v1, h1, l1);
                oh[o] = h0; oh[o + 1] = h1;
                ol[o] = l0; ol[o + 1] = l1;
            }
        }
}

// ---------------- router (also records per-token slot ids) ----------------
__global__ __launch_bounds__(256) void router_kernel(
    const float* __restrict__ hn, const float* __restrict__ wg)
{
    int tkn = blockIdx.x;
    int w = threadIdx.x >> 5, lane = threadIdx.x & 31;
    const float* x = hn + (size_t)tkn * DD;
    const float* g = wg + (size_t)w * DD;
    float s = 0.f;
    for (int i = lane; i < DD; i += 32) s += x[i] * g[i];
    s = warp_sum(s);
    __shared__ float lg[EE];
    if (lane == 0) lg[w] = s;
    __syncthreads();
    if (threadIdx.x == 0) {
        float m = -INFINITY;
        #pragma unroll
        for (int e = 0; e < EE; e++) m = fmaxf(m, lg[e]);
        float ex[EE];
        #pragma unroll
        for (int e = 0; e < EE; e++) ex[e] = expf(lg[e] - m);
        int i1 = 0; float m1 = ex[0];
        #pragma unroll
        for (int e = 1; e < EE; e++) if (ex[e] > m1) { m1 = ex[e]; i1 = e; }
        int i2 = -1; float m2 = -1.f;
        #pragma unroll
        for (int e = 0; e < EE; e++) if (e != i1 && ex[e] > m2) { m2 = ex[e]; i2 = e; }
        float inv = 1.0f / (m1 + m2);
        int p1 = atomicAdd(&g_cnt[i1], 1);
        g_tok[i1 * TT + p1] = tkn; g_twt[i1 * TT + p1] = m1 * inv;
        int p2 = atomicAdd(&g_cnt[i2], 1);
        g_tok[i2 * TT + p2] = tkn; g_twt[i2 * TT + p2] = m2 * inv;
        g_tslot[tkn * 2 + 0] = i1 * TT + p1;
        g_tslot[tkn * 2 + 1] = i2 * TT + p2;
    }
}

// ---------------- final: out = h + w0*moeX[s0] + w1*moeX[s1] ----------------
__global__ void final_gather_kernel(const float* __restrict__ h,
                                    const float* __restrict__ moeX,
                                    const int* __restrict__ tsl,
                                    const float* __restrict__ twt,
                                    float* __restrict__ out) {
    int t = blockIdx.x;
    int s0 = tsl[t * 2], s1 = tsl[t * 2 + 1];
    float w0 = twt[s0], w1 = twt[s1];
    const float* b0 = moeX + (size_t)s0 * DD;
    const float* b1 = moeX + (size_t)s1 * DD;
    const float* hr = h + (size_t)t * DD;
    float* o = out + (size_t)t * DD;
    for (int d = threadIdx.x; d < DD; d += 256)
        o[d] = hr[d] + w0 * b0[d] + w1 * b1[d];
}

// ======================= host =======================
extern "C" void kernel_launch(void* const* d_in, const int* in_sizes, int n_in,
                              void* d_out, int out_size) {
    const float* hidden = (const float*)d_in[0];
    const float* w_q    = (const float*)d_in[1];
    const float* w_k    = (const float*)d_in[2];
    const float* w_v    = (const float*)d_in[3];
    const float* w_o    = (const float*)d_in[4];
    const float* g1     = (const float*)d_in[5];
    const float* g2     = (const float*)d_in[6];
    const float* w_gate = (const float*)d_in[7];
    const float* w1     = (const float*)d_in[8];
    const float* w3     = (const float*)d_in[9];
    const float* w2     = (const float*)d_in[10];
    float* out = (float*)d_out;

    bf16 *p_wqkvn, *p_won, *p_w1n, *p_w3n, *p_w2n;
    float *p_wqkvs, *p_wos, *p_w1s, *p_w3s, *p_w2s;
    bf16 *p_hnh, *p_hnl, *p_oh, *p_ol, *p_uph, *p_upl;
    bf16 *p_xnh, *p_xnl;
    bf16 *p_qh, *p_ql, *p_kh, *p_kl, *p_vn, *p_ph, *p_pl;
    float *p_qkv, *p_vs, *p_sc, *p_h, *p_hn, *p_up1, *p_moeX, *p_twt;
    int *p_cnt, *p_tok, *p_tslot;
    cudaGetSymbolAddress((void**)&p_wqkvn, g_wqkvn); cudaGetSymbolAddress((void**)&p_wqkvs, g_wqkvs);
    cudaGetSymbolAddress((void**)&p_won, g_won); cudaGetSymbolAddress((void**)&p_wos, g_wos);
    cudaGetSymbolAddress((void**)&p_w1n, g_w1n); cudaGetSymbolAddress((void**)&p_w1s, g_w1s);
    cudaGetSymbolAddress((void**)&p_w3n, g_w3n); cudaGetSymbolAddress((void**)&p_w3s, g_w3s);
    cudaGetSymbolAddress((void**)&p_w2n, g_w2n); cudaGetSymbolAddress((void**)&p_w2s, g_w2s);
    cudaGetSymbolAddress((void**)&p_xnh, g_xnh); cudaGetSymbolAddress((void**)&p_xnl, g_xnl);
    cudaGetSymbolAddress((void**)&p_hnh, g_hnh); cudaGetSymbolAddress((void**)&p_hnl, g_hnl);
    cudaGetSymbolAddress((void**)&p_oh, g_oh);   cudaGetSymbolAddress((void**)&p_ol, g_ol);
    cudaGetSymbolAddress((void**)&p_uph, g_uph); cudaGetSymbolAddress((void**)&p_upl, g_upl);
    cudaGetSymbolAddress((void**)&p_qkv, g_qkv);
    cudaGetSymbolAddress((void**)&p_qh, g_qh);   cudaGetSymbolAddress((void**)&p_ql, g_ql);
    cudaGetSymbolAddress((void**)&p_kh, g_kh);   cudaGetSymbolAddress((void**)&p_kl, g_kl);
    cudaGetSymbolAddress((void**)&p_vn, g_vn);   cudaGetSymbolAddress((void**)&p_vs, g_vs);
    cudaGetSymbolAddress((void**)&p_sc, g_sc);
    cudaGetSymbolAddress((void**)&p_ph, g_ph);   cudaGetSymbolAddress((void**)&p_pl, g_pl);
    cudaGetSymbolAddress((void**)&p_h, g_h);     cudaGetSymbolAddress((void**)&p_hn, g_hn);
    cudaGetSymbolAddress((void**)&p_up1, g_up1); cudaGetSymbolAddress((void**)&p_moeX, g_moeX);
    cudaGetSymbolAddress((void**)&p_cnt, g_cnt); cudaGetSymbolAddress((void**)&p_tok, g_tok);
    cudaGetSymbolAddress((void**)&p_twt, g_twt); cudaGetSymbolAddress((void**)&p_tslot, g_tslot);

    cudaFuncSetAttribute(gemm_tc<0>, cudaFuncAttributeMaxDynamicSharedMemorySize, SMEM_SZ);
    cudaFuncSetAttribute(gemm_tc<1>, cudaFuncAttributeMaxDynamicSharedMemorySize, SMEM_SZ);
    cudaFuncSetAttribute(gemm_tc<2>, cudaFuncAttributeMaxDynamicSharedMemorySize, SMEM_SZ);
    cudaFuncSetAttribute(gemm_tc<4>, cudaFuncAttributeMaxDynamicSharedMemorySize, SMEM_SZ);
    cudaFuncSetAttribute(gemm_tc<5>, cudaFuncAttributeMaxDynamicSharedMemorySize, SMEM_SZ);
    cudaFuncSetAttribute(scores_tc, cudaFuncAttributeMaxDynamicSharedMemorySize, SCR_SMEM);
    cudaFuncSetAttribute(av_tc, cudaFuncAttributeMaxDynamicSharedMemorySize, AV_SMEM);

    static cudaStream_t s2 = nullptr;
    static cudaEvent_t ev_fork = nullptr, ev_join = nullptr;
    if (!s2) {
        cudaStreamCreateWithFlags(&s2, cudaStreamNonBlocking);
        cudaEventCreateWithFlags(&ev_fork, cudaEventDisableTiming);
        cudaEventCreateWithFlags(&ev_join, cudaEventDisableTiming);
    }

    zero_cnt_kernel<<<1, 32>>>(p_cnt);

    cudaEventRecord(ev_fork, 0);
    cudaStreamWaitEvent(s2, ev_fork, 0);
    quantw_kernel<<<28672, 256, 0, s2>>>(w1, p_w1n, p_w1s, EE * FFND * DD / 128);
    quantw_kernel<<<28672, 256, 0, s2>>>(w3, p_w3n, p_w3s, EE * FFND * DD / 128);
    quantw_kernel<<<28672, 256, 0, s2>>>(w2, p_w2n, p_w2s, EE * DD * FFND / 128);
    cudaEventRecord(ev_join, s2);

    quantw_kernel<<<1024, 256>>>(w_q, p_wqkvn, p_wqkvs, DD * DD / 128);
    quantw_kernel<<<256, 256>>>(w_k, p_wqkvn + 1024 * DD, p_wqkvs + 1024 * 8, KV * HDIM * DD / 128);
    quantw_kernel<<<256, 256>>>(w_v, p_wqkvn + 1280 * DD, p_wqkvs + 1280 * 8, KV * HDIM * DD / 128);
    quantw_kernel<<<1024, 256>>>(w_o, p_won, p_wos, DD * DD / 128);

    // ---- attention ----
    rms_split_kernel<false><<<TT, 256>>>(hidden, g1, nullptr, p_xnh, p_xnl);
    gemm_tc<0><<<dim3(12, 16, 1), 256, SMEM_SZ>>>(p_xnh, p_xnl, DD, 0,
        p_wqkvn, p_wqkvs, DD, 0, 0,
        p_qkv, nullptr, nullptr, NQKV, 0, TT, nullptr, DD, nullptr, nullptr);
    kvprep_kernel<<<TT * (HH + KV + KV), HDIM>>>(p_qkv, p_qh, p_ql, p_kh, p_kl, p_vn, p_vs);
    scores_tc<<<dim3(8, 8, BB * HH), 256, SCR_SMEM>>>(p_qh, p_ql, p_kh, p_kl, p_sc);
    softmax_kernel<<<BB * HH * SS, 256>>>(p_sc, p_vs, p_ph, p_pl);
    av_tc<<<dim3(1, 8, BB * HH), 256, AV_SMEM>>>(p_ph, p_pl, p_vn, p_oh, p_ol);
    gemm_tc<1><<<dim3(8, 16, 1), 256, SMEM_SZ>>>(p_oh, p_ol, DD, 0,
        p_won, p_wos, DD, 0, 0,
        p_h, nullptr, nullptr, DD, 0, TT, nullptr, DD, hidden, nullptr);

    // ---- MoE ----
    rms_split_kernel<true><<<TT, 256>>>(p_h, g2, p_hn, p_hnh, p_hnl);
    router_kernel<<<TT, 256>>>(p_hn, w_gate);
    cudaStreamWaitEvent(0, ev_join, 0);
    gemm_tc<2><<<dim3(28, 16, EE), 256, SMEM_SZ>>>(p_hnh, p_hnl, DD, 0,
        p_w1n, p_w1s, DD, (size_t)FFND * DD, (size_t)FFND * 8,
        p_up1, nullptr, nullptr, FFND, (size_t)TT * FFND,
        0, p_cnt, DD, nullptr, p_tok);
    gemm_tc<4><<<dim3(28, 16, EE), 256, SMEM_SZ>>>(p_hnh, p_hnl, DD, 0,
        p_w3n, p_w3s, DD, (size_t)FFND * DD, (size_t)FFND * 8,
        nullptr, p_uph, p_upl, FFND, (size_t)TT * FFND,
        0, p_cnt, DD, p_up1, p_tok);
    gemm_tc<5><<<dim3(8, 16, EE), 256, SMEM_SZ>>>(p_uph, p_upl, FFND, (size_t)TT * FFND,
        p_w2n, p_w2s, FFND, (size_t)DD * FFND, (size_t)DD * 28,
        p_moeX, nullptr, nullptr, DD, (size_t)TT * DD,
        0, p_cnt, FFND, nullptr, nullptr);
    final_gather_kernel<<<TT, 256>>>(p_h, p_moeX, p_tslot, p_twt, out);
}

// round 15
// speedup vs baseline: 1.9643x; 1.0220x over previous
#include <cuda_runtime.h>
#include <cuda_bf16.h>
#include <math.h>
#include <stdint.h>

#define BB 2
#define SS 1024
#define TT 2048
#define DD 1024
#define HH 8
#define KV 2
#define HDIM 128
#define EE 8
#define FFND 3584
#define NQKV 1536

#define KT 64
#define STAGES 4
#define TILE_BYTES 16384
#define STAGE_BYTES (3 * TILE_BYTES)
#define SC_OFF (STAGES * STAGE_BYTES)
#define SMEM_SZ (SC_OFF + 28 * 128 * 4)
#define SCR_SMEM (2 * 4 * TILE_BYTES)
#define AV_STAGE (3 * TILE_BYTES)
#define AV_SMEM (3 * AV_STAGE)

typedef __nv_bfloat16 bf16;

// weights: integer bf16 + per-group fp32 scale
__device__ bf16  g_wqkvn[NQKV * DD];       __device__ float g_wqkvs[NQKV * DD / 128];
__device__ bf16  g_won[DD * DD];           __device__ float g_wos[DD * DD / 128];
__device__ bf16  g_w1n[EE * FFND * DD];    __device__ float g_w1s[EE * FFND * DD / 128];
__device__ bf16  g_w3n[EE * FFND * DD];    __device__ float g_w3s[EE * FFND * DD / 128];
__device__ bf16  g_w2n[EE * DD * FFND];    __device__ float g_w2s[EE * DD * FFND / 128];
// activations
__device__ bf16 g_xnh[TT * DD];        __device__ bf16 g_xnl[TT * DD];
__device__ bf16 g_hnh[TT * DD];        __device__ bf16 g_hnl[TT * DD];
__device__ bf16 g_oh[TT * DD];         __device__ bf16 g_ol[TT * DD];
__device__ bf16 g_uph[EE * TT * FFND]; __device__ bf16 g_upl[EE * TT * FFND];
__device__ float g_qkv[TT * NQKV];
__device__ bf16 g_qh[TT * DD];         __device__ bf16 g_ql[TT * DD];
__device__ bf16 g_kh[TT * KV * HDIM];  __device__ bf16 g_kl[TT * KV * HDIM];
__device__ bf16 g_vn[TT * KV * HDIM];  __device__ float g_vs[TT * KV];
__device__ float g_sc[BB * HH * SS * SS];
__device__ bf16 g_ph[BB * HH * SS * SS];
__device__ bf16 g_pl[BB * HH * SS * SS];
__device__ float g_h[TT * DD];
__device__ float g_hn[TT * DD];
__device__ float g_up1[EE * TT * FFND];
__device__ float g_moeX[EE * TT * DD];
__device__ int   g_cnt[EE];
__device__ int   g_tok[EE * TT];
__device__ float g_twt[EE * TT];
__device__ int   g_tslot[TT * 2];

// ---------------- ptx helpers ----------------
__device__ __forceinline__ uint32_t smem_u32(const void* p) {
    uint32_t a;
    asm("{ .reg .u64 t; cvta.to.shared.u64 t, %1; cvt.u32.u64 %0, t; }" : "=r"(a) : "l"(p));
    return a;
}
__device__ __forceinline__ void ldsm4(uint32_t a, uint32_t& r0, uint32_t& r1,
                                      uint32_t& r2, uint32_t& r3) {
    asm volatile("ldmatrix.sync.aligned.m8n8.x4.shared.b16 {%0,%1,%2,%3}, [%4];"
                 : "=r"(r0), "=r"(r1), "=r"(r2), "=r"(r3) : "r"(a));
}
__device__ __forceinline__ void ldsm4t(uint32_t a, uint32_t& r0, uint32_t& r1,
                                       uint32_t& r2, uint32_t& r3) {
    asm volatile("ldmatrix.sync.aligned.m8n8.x4.trans.shared.b16 {%0,%1,%2,%3}, [%4];"
                 : "=r"(r0), "=r"(r1), "=r"(r2), "=r"(r3) : "r"(a));
}
__device__ __forceinline__ void mma16816(float* c, const uint32_t* a, const uint32_t* b) {
    asm volatile("mma.sync.aligned.m16n8k16.row.col.f32.bf16.bf16.f32 "
                 "{%0,%1,%2,%3}, {%4,%5,%6,%7}, {%8,%9}, {%0,%1,%2,%3};"
                 : "+f"(c[0]), "+f"(c[1]), "+f"(c[2]), "+f"(c[3])
                 : "r"(a[0]), "r"(a[1]), "r"(a[2]), "r"(a[3]), "r"(b[0]), "r"(b[1]));
}
__device__ __forceinline__ void cpa16(uint32_t dst, const void* src) {
    asm volatile("cp.async.cg.shared.global [%0], [%1], 16;" :: "r"(dst), "l"(src));
}
__device__ __forceinline__ void cpa_commit() { asm volatile("cp.async.commit_group;" ::: "memory"); }
__device__ __forceinline__ void cpa_wait0() { asm volatile("cp.async.wait_group 0;" ::: "memory"); }
__device__ __forceinline__ void cpa_wait1() { asm volatile("cp.async.wait_group 1;" ::: "memory"); }
__device__ __forceinline__ void cpa_wait2() { asm volatile("cp.async.wait_group 2;" ::: "memory"); }

__device__ __forceinline__ float warp_sum(float v) {
    #pragma unroll
    for (int o = 16; o; o >>= 1) v += __shfl_xor_sync(0xffffffffu, v, o);
    return v;
}
__device__ __forceinline__ void split_bf(float v, bf16& h, bf16& l) {
    h = __float2bfloat16(v);
    l = __float2bfloat16(v - __bfloat162float(h));
}
__device__ __forceinline__ uint32_t swz(uint32_t off) { return off ^ ((off >> 3) & 0x70); }

// ---------------- small kernels ----------------
__global__ void zero_cnt_kernel(int* __restrict__ cnt) {
    if (threadIdx.x < EE) cnt[threadIdx.x] = 0;
}

// one 128-group per 16-lane half; 8 elems/lane; packed bf16x2 converts.
__device__ __forceinline__ void quant_group(const float* __restrict__ w,
                                            bf16* __restrict__ nq,
                                            float* __restrict__ sc,
                                            int g, int l16) {
    const float4* src = reinterpret_cast<const float4*>(w) + (size_t)g * 32 + l16 * 2;
    float4 v0 = src[0], v1 = src[1];
    float mn = fminf(fminf(fminf(v0.x, v0.y), fminf(v0.z, v0.w)),
                     fminf(fminf(v1.x, v1.y), fminf(v1.z, v1.w)));
    float mx = fmaxf(fmaxf(fmaxf(v0.x, v0.y), fmaxf(v0.z, v0.w)),
                     fmaxf(fmaxf(v1.x, v1.y), fmaxf(v1.z, v1.w)));
    #pragma unroll
    for (int o = 8; o; o >>= 1) {
        mn = fminf(mn, __shfl_xor_sync(0xffffffffu, mn, o, 16));
        mx = fmaxf(mx, __shfl_xor_sync(0xffffffffu, mx, o, 16));
    }
    float scale = fmaxf(mx - mn, 1e-5f) / 15.0f;
    float sinv = 1.0f / scale;
    float base = fminf(fmaxf(rintf(-mn * sinv), 0.f), 15.f);
    float qmin = -base, qmax = 15.0f - base;
    float q[8];
    q[0] = v0.x; q[1] = v0.y; q[2] = v0.z; q[3] = v0.w;
    q[4] = v1.x; q[5] = v1.y; q[6] = v1.z; q[7] = v1.w;
    #pragma unroll
    for (int j = 0; j < 8; j++)
        q[j] = fminf(fmaxf(rintf(q[j] * sinv), qmin), qmax);
    __nv_bfloat162 p[4];
    #pragma unroll
    for (int j = 0; j < 4; j++)
        p[j] = __floats2bfloat162_rn(q[2 * j], q[2 * j + 1]);
    *reinterpret_cast<uint4*>(nq + (size_t)g * 128 + l16 * 8) =
        *reinterpret_cast<uint4*>(p);
    if (l16 == 0) sc[g] = scale;
}

// single-tensor quant (small weights)
__global__ void quantw_kernel(const float* __restrict__ w, bf16* __restrict__ nq,
                              float* __restrict__ sc, int ngroups) {
    int g = blockIdx.x * 16 + (threadIdx.x >> 4);
    if (g >= ngroups) return;
    quant_group(w, nq, sc, g, threadIdx.x & 15);
}

// fused 3-tensor quant (w1/w3/w2, equal sizes) — grid.z selects tensor
__global__ void quantw3_kernel(const float* __restrict__ wa, const float* __restrict__ wb,
                               const float* __restrict__ wc,
                               bf16* __restrict__ na, bf16* __restrict__ nb,
                               bf16* __restrict__ nc,
                               float* __restrict__ sa, float* __restrict__ sb,
                               float* __restrict__ scc, int ngroups) {
    int g = blockIdx.x * 16 + (threadIdx.x >> 4);
    if (g >= ngroups) return;
    const float* w;
    bf16* nq;
    float* sc;
    if (blockIdx.z == 0)      { w = wa; nq = na; sc = sa; }
    else if (blockIdx.z == 1) { w = wb; nq = nb; sc = sb; }
    else                      { w = wc; nq = nc; sc = scc; }
    quant_group(w, nq, sc, g, threadIdx.x & 15);
}

template<bool WF32>
__global__ void rms_split_kernel(const float* __restrict__ x, const float* __restrict__ g,
                                 float* __restrict__ f32o, bf16* __restrict__ hi,
                                 bf16* __restrict__ lo) {
    int row = blockIdx.x;
    const float* xr = x + (size_t)row * DD;
    float s = 0.f;
    for (int i = threadIdx.x; i < DD; i += 256) { float v = xr[i]; s += v * v; }
    __shared__ float sh[256];
    sh[threadIdx.x] = s; __syncthreads();
    for (int o2 = 128; o2; o2 >>= 1) {
        if (threadIdx.x < o2) sh[threadIdx.x] += sh[threadIdx.x + o2];
        __syncthreads();
    }
    float inv = rsqrtf(sh[0] * (1.0f / DD) + 1e-5f);
    for (int i = threadIdx.x; i < DD; i += 256) {
        float v = xr[i] * inv * g[i];
        if (WF32) f32o[(size_t)row * DD + i] = v;
        bf16 h, l; split_bf(v, h, l);
        hi[(size_t)row * DD + i] = h;
        lo[(size_t)row * DD + i] = l;
    }
}

// ===== bf16x2 mma.sync GEMM with exact integer weights + per-group rescale =====
// MODE 0 store f32 | 1 +resid | 2 gather-A, M=Mptr[z] | 4 gather-A, silu(resid)*acc
// split-> CH/CL | 5 direct-A slot rows, M=Mptr[z], store f32 z-strided
template<int MODE>
__global__ __launch_bounds__(256, 1) void gemm_tc(
    const bf16* __restrict__ Ahi, const bf16* __restrict__ Alo, int lda, size_t strideA,
    const bf16* __restrict__ Bn, const float* __restrict__ Bsc, int ldb,
    size_t strideB, size_t strideBs,
    float* __restrict__ C, bf16* __restrict__ CH, bf16* __restrict__ CL,
    int ldc, size_t strideC,
    int M, const int* __restrict__ Mptr, int K,
    const float* __restrict__ resid, const int* __restrict__ idx)
{
    int z = blockIdx.z;
    if (Mptr) M = Mptr[z];
    int m0 = blockIdx.y * 128;
    if (m0 >= M) return;
    int n0 = blockIdx.x * 128;
    int tid = threadIdx.x;
    int wid = tid >> 5, lid = tid & 31;

    extern __shared__ char smem[];
    uint32_t sb = smem_u32(smem);
    float* scs = reinterpret_cast<float*>(smem + SC_OFF);
    const int* idxz = (MODE == 2 || MODE == 4) ? (idx + (size_t)z * TT) : (const int*)nullptr;
    int G = K >> 7;

    for (int i = tid; i < G * 128; i += 256) {
        int g = i >> 7, c = i & 127;
        scs[i] = Bsc[strideBs * z + (size_t)(n0 + c) * G + g];
    }

    const bf16* srcA[4]; const bf16* srcB[4];
    uint32_t dstA[4], dstB[4];
    ptrdiff_t dlo = Alo - Ahi;
    #pragma unroll
    for (int ci = 0; ci < 4; ci++) {
        int gid = ci * 256 + tid;
        int r = (gid >> 3) & 127;
        int c8 = gid & 7;
        int row = m0 + r;
        if (row >= M) row = m0;
        int rg = (MODE == 2 || MODE == 4) ? idxz[row] : row;
        srcA[ci] = Ahi + strideA * (size_t)z + (size_t)rg * lda + c8 * 8;
        dstA[ci] = swz((uint32_t)(r * 128 + c8 * 16));
        int gid2 = 2048 + gid;
        int r2 = (gid2 >> 3) & 127;
        int c82 = gid2 & 7;
        srcB[ci] = Bn + strideB * (size_t)z + (size_t)(n0 + r2) * ldb + c82 * 8;
        dstB[ci] = (uint32_t)(2 * TILE_BYTES) + swz((uint32_t)(r2 * 128 + c82 * 16));
    }

    int n_kt = K / KT;
    int npro = STAGES - 1; if (npro > n_kt) npro = n_kt;
    #pragma unroll 1
    for (int p = 0; p < npro; p++) {
        uint32_t base = sb + p * STAGE_BYTES;
        size_t ko = (size_t)p * KT;
        #pragma unroll
        for (int ci = 0; ci < 4; ci++) {
            cpa16(base + dstA[ci], srcA[ci] + ko);
            cpa16(base + TILE_BYTES + dstA[ci], srcA[ci] + dlo + ko);
            cpa16(base + dstB[ci], srcB[ci] + ko);
        }
        cpa_commit();
    }

    int wr = (wid & 3) * 32;
    int wc = (wid >> 2) * 64;
    int rowm = (lid & 7) + ((lid >> 3) & 1) * 8;
    int colb = (lid >> 4) * 16;

    float acc[2][8][4] = {};
    float accg[2][8][4] = {};

    #pragma unroll 1
    for (int kt = 0; kt < n_kt; kt++) {
        int pending = n_kt - kt - 1; if (pending > STAGES - 2) pending = STAGES - 2;
        if (pending >= 2) cpa_wait2();
        else if (pending == 1) cpa_wait1();
        else cpa_wait0();
        __syncthreads();
        if (kt + STAGES - 1 < n_kt) {
            int sl = (kt + STAGES - 1) % STAGES;
            uint32_t base = sb + sl * STAGE_BYTES;
            size_t ko = (size_t)(kt + STAGES - 1) * KT;
            #pragma unroll
            for (int ci = 0; ci < 4; ci++) {
                cpa16(base + dstA[ci], srcA[ci] + ko);
                cpa16(base + TILE_BYTES + dstA[ci], srcA[ci] + dlo + ko);
                cpa16(base + dstB[ci], srcB[ci] + ko);
            }
            cpa_commit();
        }
        uint32_t sbase = sb + (kt % STAGES) * STAGE_BYTES;
        #pragma unroll
        for (int s16 = 0; s16 < 4; s16++) {
            int kb0 = s16 * 32 + colb;
            uint32_t ah[2][4], al[2][4], bn[8][2];
            #pragma unroll
            for (int i = 0; i < 2; i++) {
                uint32_t off = (uint32_t)((wr + i * 16 + rowm) * 128 + kb0);
                ldsm4(sbase + swz(off), ah[i][0], ah[i][1], ah[i][2], ah[i][3]);
                ldsm4(sbase + TILE_BYTES + swz(off), al[i][0], al[i][1], al[i][2], al[i][3]);
            }
            #pragma unroll
            for (int j = 0; j < 4; j++) {
                uint32_t off = (uint32_t)((wc + j * 16 + rowm) * 128 + kb0);
                uint32_t r0, r1, r2, r3;
                ldsm4(sbase + 2 * TILE_BYTES + swz(off), r0, r1, r2, r3);
                bn[j * 2][0] = r0; bn[j * 2][1] = r2;
                bn[j * 2 + 1][0] = r1; bn[j * 2 + 1][1] = r3;
            }
            #pragma unroll
            for (int i = 0; i < 2; i++)
                #pragma unroll
                for (int jn = 0; jn < 8; jn++) {
                    mma16816(accg[i][jn], ah[i], bn[jn]);
                    mma16816(accg[i][jn], al[i], bn[jn]);
                }
        }
        if (kt & 1) {
            int g = kt >> 1;
            #pragma unroll
            for (int jn = 0; jn < 8; jn++) {
                int c = wc + jn * 8 + (lid & 3) * 2;
                float s0 = scs[g * 128 + c];
                float s1 = scs[g * 128 + c + 1];
                #pragma unroll
                for (int i = 0; i < 2; i++) {
                    acc[i][jn][0] += s0 * accg[i][jn][0];
                    acc[i][jn][1] += s1 * accg[i][jn][1];
                    acc[i][jn][2] += s0 * accg[i][jn][2];
                    acc[i][jn][3] += s1 * accg[i][jn][3];
                    accg[i][jn][0] = 0.f; accg[i][jn][1] = 0.f;
                    accg[i][jn][2] = 0.f; accg[i][jn][3] = 0.f;
                }
            }
        }
    }

    #pragma unroll
    for (int i = 0; i < 2; i++) {
        #pragma unroll
        for (int jn = 0; jn < 8; jn++) {
            int r0 = m0 + wr + i * 16 + (lid >> 2);
            int cc = n0 + wc + jn * 8 + (lid & 3) * 2;
            #pragma unroll
            for (int half = 0; half < 2; half++) {
                int row = r0 + half * 8;
                if (row >= M) continue;
                float v0 = acc[i][jn][half * 2 + 0];
                float v1 = acc[i][jn][half * 2 + 1];
                if (MODE == 0 || MODE == 1 || MODE == 2 || MODE == 5) {
                    float* Cr = C + strideC * z + (size_t)row * ldc + cc;
                    if (MODE == 1) {
                        const float* rr = resid + (size_t)row * ldc + cc;
                        v0 += rr[0]; v1 += rr[1];
                    }
                    *reinterpret_cast<float2*>(Cr) = make_float2(v0, v1);
                } else {  // MODE 4
                    const float* ar = resid + strideC * z + (size_t)row * ldc + cc;
                    float a0 = ar[0], a1 = ar[1];
                    float gv0 = (a0 / (1.f + expf(-a0))) * v0;
                    float gv1 = (a1 / (1.f + expf(-a1))) * v1;
                    bf16 h0, l0, h1, l1;
                    split_bf(gv0, h0, l0); split_bf(gv1, h1, l1);
                    size_t o = strideC * z + (size_t)row * ldc + cc;
                    CH[o] = h0; CH[o + 1] = h1;
                    CL[o] = l0; CL[o + 1] = l1;
                }
            }
        }
    }
}

// ---------------- fused q-rope / k-quant+rope / v-quant prep ----------------
__global__ void kvprep_kernel(const float* __restrict__ qkv,
                              bf16* __restrict__ qh, bf16* __restrict__ ql,
                              bf16* __restrict__ kh, bf16* __restrict__ kl,
                              bf16* __restrict__ vn, float* __restrict__ vs) {
    int j = blockIdx.x;
    int d = threadIdx.x;
    __shared__ float smn[HDIM], smx[HDIM], sh[HDIM];
    if (j < TT * HH) {
        int t = j >> 3, hh = j & 7;
        sh[d] = qkv[(size_t)t * NQKV + hh * HDIM + d];
        __syncthreads();
        int pos = t & (SS - 1);
        int i = d & 63;
        float invf = expf(-13.815510557964274f * ((float)(2 * i) * (1.0f / HDIM)));
        float f = (float)pos * invf;
        float c = cosf(f), sn = sinf(f);
        float v = (d < 64) ? (sh[d] * c - sh[d + 64] * sn)
                           : (sh[d] * c + sh[d - 64] * sn);
        bf16 h, l; split_bf(v, h, l);
        qh[(size_t)j * HDIM + d] = h;
        ql[(size_t)j * HDIM + d] = l;
        return;
    }
    int j2 = j - TT * HH;
    bool isK = j2 < TT * KV;
    int rowid = isK ? j2 : (j2 - TT * KV);
    int t = rowid >> 1, kvh = rowid & 1;
    float v = qkv[(size_t)t * NQKV + (isK ? 1024 : 1280) + kvh * HDIM + d];
    smn[d] = v; smx[d] = v; __syncthreads();
    for (int o2 = 64; o2; o2 >>= 1) {
        if (d < o2) {
            smn[d] = fminf(smn[d], smn[d + o2]);
            smx[d] = fmaxf(smx[d], smx[d + o2]);
        }
        __syncthreads();
    }
    float scale = fmaxf(smx[0] - smn[0], 1e-5f) / 15.0f;
    float sinv = 1.0f / scale;
    float base = fminf(fmaxf(rintf(-smn[0] * sinv), 0.f), 15.f);
    float qn = fminf(fmaxf(rintf(v * sinv), -base), 15.0f - base);
    if (!isK) {
        vn[(size_t)rowid * HDIM + d] = __float2bfloat16(qn);
        if (d == 0) vs[rowid] = scale;
        return;
    }
    float q = qn * scale;
    sh[d] = q; __syncthreads();
    int pos = t & (SS - 1);
    int i = d & 63;
    float invf = expf(-13.815510557964274f * ((float)(2 * i) * (1.0f / HDIM)));
    float f = (float)pos * invf;
    float c = cosf(f), sn = sinf(f);
    q = (d < 64) ? (sh[d] * c - sh[d + 64] * sn)
                 : (sh[d] * c + sh[d - 64] * sn);
    bf16 h, l; split_bf(q, h, l);
    kh[(size_t)rowid * HDIM + d] = h;
    kl[(size_t)rowid * HDIM + d] = l;
}

// ---------------- TC scores ----------------
__global__ __launch_bounds__(256, 1) void scores_tc(
    const bf16* __restrict__ qh, const bf16* __restrict__ ql,
    const bf16* __restrict__ kh, const bf16* __restrict__ kl,
    float* __restrict__ sc)
{
    int z = blockIdx.z;
    int m0 = blockIdx.y * 128, n0 = blockIdx.x * 128;
    if (n0 > m0) return;
    int b = z >> 3, hh = z & 7, kvh = (z & 7) >> 2;
    int tid = threadIdx.x, wid = tid >> 5, lid = tid & 31;
    extern __shared__ char smem[];
    uint32_t sb = smem_u32(smem);

    const bf16* src[16]; uint32_t dst[16];
    #pragma unroll
    for (int ci = 0; ci < 16; ci++) {
        int gid = ci * 256 + tid;
        int t4 = gid >> 10;
        int r = (gid >> 3) & 127;
        int c8 = gid & 7;
        const bf16* p;
        if (t4 == 0)      p = qh + ((size_t)(b * SS + m0 + r) * HH + hh) * HDIM;
        else if (t4 == 1) p = ql + ((size_t)(b * SS + m0 + r) * HH + hh) * HDIM;
        else if (t4 == 2) p = kh + ((size_t)(b * SS + n0 + r) * KV + kvh) * HDIM;
        else              p = kl + ((size_t)(b * SS + n0 + r) * KV + kvh) * HDIM;
        src[ci] = p + c8 * 8;
        dst[ci] = (uint32_t)(t4 * TILE_BYTES) + swz((uint32_t)(r * 128 + c8 * 16));
    }
    #pragma unroll
    for (int ci = 0; ci < 16; ci++) cpa16(sb + dst[ci], src[ci]);
    cpa_commit();
    #pragma unroll
    for (int ci = 0; ci < 16; ci++) cpa16(sb + 4 * TILE_BYTES + dst[ci], src[ci] + 64);
    cpa_commit();

    int wr = (wid & 3) * 32;
    int wc = (wid >> 2) * 64;
    int rowm = (lid & 7) + ((lid >> 3) & 1) * 8;
    int colb = (lid >> 4) * 16;
    float acc[2][8][4] = {};

    #pragma unroll 1
    for (int ch = 0; ch < 2; ch++) {
        if (ch == 0) cpa_wait1(); else cpa_wait0();
        __syncthreads();
        uint32_t base = sb + ch * 4 * TILE_BYTES;
        #pragma unroll
        for (int s16 = 0; s16 < 4; s16++) {
            int kb0 = s16 * 32 + colb;
            uint32_t ah[2][4], al[2][4], bh[8][2], bl[8][2];
            #pragma unroll
            for (int i = 0; i < 2; i++) {
                uint32_t off = (uint32_t)((wr + i * 16 + rowm) * 128 + kb0);
                ldsm4(base + swz(off), ah[i][0], ah[i][1], ah[i][2], ah[i][3]);
                ldsm4(base + TILE_BYTES + swz(off), al[i][0], al[i][1], al[i][2], al[i][3]);
            }
            #pragma unroll
            for (int j = 0; j < 4; j++) {
                uint32_t off = (uint32_t)((wc + j * 16 + rowm) * 128 + kb0);
                uint32_t r0, r1, r2, r3;
                ldsm4(base + 2 * TILE_BYTES + swz(off), r0, r1, r2, r3);
                bh[j * 2][0] = r0; bh[j * 2][1] = r2;
                bh[j * 2 + 1][0] = r1; bh[j * 2 + 1][1] = r3;
                ldsm4(base + 3 * TILE_BYTES + swz(off), r0, r1, r2, r3);
                bl[j * 2][0] = r0; bl[j * 2][1] = r2;
                bl[j * 2 + 1][0] = r1; bl[j * 2 + 1][1] = r3;
            }
            #pragma unroll
            for (int i = 0; i < 2; i++)
                #pragma unroll
                for (int jn = 0; jn < 8; jn++) {
                    mma16816(acc[i][jn], ah[i], bh[jn]);
                    mma16816(acc[i][jn], ah[i], bl[jn]);
                    mma16816(acc[i][jn], al[i], bh[jn]);
                }
        }
    }
    const float scalef = 0.08838834764831845f;
    float* C = sc + (size_t)z * SS * SS;
    #pragma unroll
    for (int i = 0; i < 2; i++)
        #pragma unroll
        for (int jn = 0; jn < 8; jn++) {
            int r0 = m0 + wr + i * 16 + (lid >> 2);
            int cc = n0 + wc + jn * 8 + (lid & 3) * 2;
            #pragma unroll
            for (int half = 0; half < 2; half++) {
                int row = r0 + half * 8;
                float v0 = acc[i][jn][half * 2 + 0] * scalef;
                float v1 = acc[i][jn][half * 2 + 1] * scalef;
                *reinterpret_cast<float2*>(C + (size_t)row * SS + cc) = make_float2(v0, v1);
            }
        }
}

// ------- softmax: exp values kept in registers; sc is read-only here ----------
__global__ void softmax_kernel(const float* __restrict__ sc, const float* __restrict__ vs,
                               bf16* __restrict__ ph, bf16* __restrict__ pl) {
    int r = blockIdx.x;
    int z = r >> 10;
    int s = r & (SS - 1);
    int b = z >> 3, kvh = (z & 7) >> 2;
    const float* row = sc + (size_t)r * SS;
    int n = s + 1;
    int nlim = (s | 127) + 1;
    __shared__ float sh[256];
    float m = -INFINITY;
    #pragma unroll
    for (int j = 0; j < 4; j++) {
        int i = threadIdx.x + j * 256;
        if (i < n) m = fmaxf(m, row[i]);
    }
    sh[threadIdx.x] = m; __syncthreads();
    for (int o2 = 128; o2; o2 >>= 1) {
        if (threadIdx.x < o2) sh[threadIdx.x] = fmaxf(sh[threadIdx.x], sh[threadIdx.x + o2]);
        __syncthreads();
    }
    m = sh[0]; __syncthreads();
    float ev[4];
    float sum = 0.f;
    #pragma unroll
    for (int j = 0; j < 4; j++) {
        int i = threadIdx.x + j * 256;
        float e = (i < n) ? expf(row[i] - m) : 0.f;
        ev[j] = e; sum += e;
    }
    sh[threadIdx.x] = sum; __syncthreads();
    for (int o2 = 128; o2; o2 >>= 1) {
        if (threadIdx.x < o2) sh[threadIdx.x] += sh[threadIdx.x + o2];
        __syncthreads();
    }
    float inv = 1.0f / sh[0];
    #pragma unroll
    for (int j = 0; j < 4; j++) {
        int i = threadIdx.x + j * 256;
        if (i >= nlim) break;
        float pv = ev[j] * inv * vs[(size_t)((b * SS + i) * KV + kvh)];
        bf16 h, l; split_bf(pv, h, l);
        ph[(size_t)r * SS + i] = h;
        pl[(size_t)r * SS + i] = l;
    }
}

// ---------------- TC AV ----------------
__global__ __launch_bounds__(256, 1) void av_tc(
    const bf16* __restrict__ ph, const bf16* __restrict__ pl,
    const bf16* __restrict__ vn, bf16* __restrict__ oh, bf16* __restrict__ ol)
{
    int z = blockIdx.z;
    int b = z >> 3, hh = z & 7, kvh = (z & 7) >> 2;
    int m0 = blockIdx.y * 128;
    int tid = threadIdx.x, wid = tid >> 5, lid = tid & 31;
    extern __shared__ char smem[];
    uint32_t sb = smem_u32(smem);

    const bf16* srcP[4]; const bf16* srcV[4];
    uint32_t dstP[4], dstV[4];
    ptrdiff_t dpl = pl - ph;
    #pragma unroll
    for (int ci = 0; ci < 4; ci++) {
        int gid = ci * 256 + tid;
        int r = (gid >> 3) & 127;
        int c8 = gid & 7;
        srcP[ci] = ph + (size_t)z * SS * SS + (size_t)(m0 + r) * SS + c8 * 8;
        dstP[ci] = swz((uint32_t)(r * 128 + c8 * 16));
        int gid2 = 2048 + gid;
        int vrow = (gid2 >> 4) & 63;
        int c16 = gid2 & 15;
        int plane = c16 >> 3, cc8 = c16 & 7;
        srcV[ci] = vn + ((size_t)(b * SS + vrow) * KV + kvh) * HDIM + plane * 64 + cc8 * 8;
        dstV[ci] = (uint32_t)(2 * TILE_BYTES + plane * 8192) + swz((uint32_t)(vrow * 128 + cc8 * 16));
    }

    int n_ch = (m0 >> 6) + 2;
    #pragma unroll 1
    for (int p = 0; p < 2 && p < n_ch; p++) {
        uint32_t base = sb + p * AV_STAGE;
        #pragma unroll
        for (int ci = 0; ci < 4; ci++) {
            size_t ko = (size_t)p * KT;
            cpa16(base + dstP[ci], srcP[ci] + ko);
            cpa16(base + TILE_BYTES + dstP[ci], srcP[ci] + dpl + ko);
            cpa16(base + dstV[ci], srcV[ci] + ko * (KV * HDIM));
        }
        cpa_commit();
    }

    int wr = (wid & 3) * 32;
    int wc = (wid >> 2) * 64;
    int vplane = wc >> 6;
    int rowm = (lid & 7) + ((lid >> 3) & 1) * 8;
    int colb = (lid >> 4) * 16;
    float acc[2][8][4] = {};

    #pragma unroll 1
    for (int kt = 0; kt < n_ch; kt++) {
        cpa_wait1();
        __syncthreads();
        if (kt + 2 < n_ch) {
            int sl = (kt + 2) % 3;
            uint32_t base = sb + sl * AV_STAGE;
            size_t ko = (size_t)(kt + 2) * KT;
            #pragma unroll
            for (int ci = 0; ci < 4; ci++) {
                cpa16(base + dstP[ci], srcP[ci] + ko);
                cpa16(base + TILE_BYTES + dstP[ci], srcP[ci] + dpl + ko);
                cpa16(base + dstV[ci], srcV[ci] + ko * (KV * HDIM));
            }
            cpa_commit();
        }
        uint32_t sbase = sb + (kt % 3) * AV_STAGE;
        uint32_t vbase = sbase + 2 * TILE_BYTES + vplane * 8192;
        #pragma unroll
        for (int s16 = 0; s16 < 4; s16++) {
            int kb0 = s16 * 32 + colb;
            uint32_t ah[2][4], al[2][4], bv[8][2];
            #pragma unroll
            for (int i = 0; i < 2; i++) {
                uint32_t off = (uint32_t)((wr + i * 16 + rowm) * 128 + kb0);
                ldsm4(sbase + swz(off), ah[i][0], ah[i][1], ah[i][2], ah[i][3]);
                ldsm4(sbase + TILE_BYTES + swz(off), al[i][0], al[i][1], al[i][2], al[i][3]);
            }
            #pragma unroll
            for (int j16 = 0; j16 < 4; j16++) {
                uint32_t krow = (uint32_t)(s16 * 16 + (lid & 7) + 8 * ((lid >> 3) & 1));
                uint32_t off = krow * 128 + (uint32_t)(j16 * 32 + 16 * (lid >> 4));
                uint32_t r0, r1, r2, r3;
                ldsm4t(vbase + swz(off), r0, r1, r2, r3);
                bv[j16 * 2][0] = r0; bv[j16 * 2][1] = r1;
                bv[j16 * 2 + 1][0] = r2; bv[j16 * 2 + 1][1] = r3;
            }
            #pragma unroll
            for (int i = 0; i < 2; i++)
                #pragma unroll
                for (int jn = 0; jn < 8; jn++) {
                    mma16816(acc[i][jn], ah[i], bv[jn]);
                    mma16816(acc[i][jn], al[i], bv[jn]);
                }
        }
    }

    #pragma unroll
    for (int i = 0; i < 2; i++)
        #pragma unroll
        for (int jn = 0; jn < 8; jn++) {
            int r0 = m0 + wr + i * 16 + (lid >> 2);
            int cc = wc + jn * 8 + (lid & 3) * 2;
            #pragma unroll
            for (int half = 0; half < 2; half++) {
                int row = r0 + half * 8;
                float v0 = acc[i][jn][half * 2 + 0];
                float v1 = acc[i][jn][half * 2 + 1];
                size_t o = ((size_t)(b * SS + row) * HH + hh) * HDIM + cc;
                bf16 h0, l0, h1, l1;
                split_bf(v0, h0, l0); split_bf(v1, h1, l1);
                oh[o] = h0; oh[o + 1] = h1;
                ol[o] = l0; ol[o + 1] = l1;
            }
        }
}

// ---------------- router (also records per-token slot ids) ----------------
__global__ __launch_bounds__(256) void router_kernel(
    const float* __restrict__ hn, const float* __restrict__ wg)
{
    int tkn = blockIdx.x;
    int w = threadIdx.x >> 5, lane = threadIdx.x & 31;
    const float* x = hn + (size_t)tkn * DD;
    const float* g = wg + (size_t)w * DD;
    float s = 0.f;
    for (int i = lane; i < DD; i += 32) s += x[i] * g[i];
    s = warp_sum(s);
    __shared__ float lg[EE];
    if (lane == 0) lg[w] = s;
    __syncthreads();
    if (threadIdx.x == 0) {
        float m = -INFINITY;
        #pragma unroll
        for (int e = 0; e < EE; e++) m = fmaxf(m, lg[e]);
        float ex[EE];
        #pragma unroll
        for (int e = 0; e < EE; e++) ex[e] = expf(lg[e] - m);
        int i1 = 0; float m1 = ex[0];
        #pragma unroll
        for (int e = 1; e < EE; e++) if (ex[e] > m1) { m1 = ex[e]; i1 = e; }
        int i2 = -1; float m2 = -1.f;
        #pragma unroll
        for (int e = 0; e < EE; e++) if (e != i1 && ex[e] > m2) { m2 = ex[e]; i2 = e; }
        float inv = 1.0f / (m1 + m2);
        int p1 = atomicAdd(&g_cnt[i1], 1);
        g_tok[i1 * TT + p1] = tkn; g_twt[i1 * TT + p1] = m1 * inv;
        int p2 = atomicAdd(&g_cnt[i2], 1);
        g_tok[i2 * TT + p2] = tkn; g_twt[i2 * TT + p2] = m2 * inv;
        g_tslot[tkn * 2 + 0] = i1 * TT + p1;
        g_tslot[tkn * 2 + 1] = i2 * TT + p2;
    }
}

// ---------------- final: out = h + w0*moeX[s0] + w1*moeX[s1] ----------------
__global__ void final_gather_kernel(const float* __restrict__ h,
                                    const float* __restrict__ moeX,
                                    const int* __restrict__ tsl,
                                    const float* __restrict__ twt,
                                    float* __restrict__ out) {
    int t = blockIdx.x;
    int s0 = tsl[t * 2], s1 = tsl[t * 2 + 1];
    float w0 = twt[s0], w1 = twt[s1];
    const float* b0 = moeX + (size_t)s0 * DD;
    const float* b1 = moeX + (size_t)s1 * DD;
    const float* hr = h + (size_t)t * DD;
    float* o = out + (size_t)t * DD;
    for (int d = threadIdx.x; d < DD; d += 256)
        o[d] = hr[d] + w0 * b0[d] + w1 * b1[d];
}

// ======================= host =======================
extern "C" void kernel_launch(void* const* d_in, const int* in_sizes, int n_in,
                              void* d_out, int out_size) {
    const float* hidden = (const float*)d_in[0];
    const float* w_q    = (const float*)d_in[1];
    const float* w_k    = (const float*)d_in[2];
    const float* w_v    = (const float*)d_in[3];
    const float* w_o    = (const float*)d_in[4];
    const float* g1     = (const float*)d_in[5];
    const float* g2     = (const float*)d_in[6];
    const float* w_gate = (const float*)d_in[7];
    const float* w1     = (const float*)d_in[8];
    const float* w3     = (const float*)d_in[9];
    const float* w2     = (const float*)d_in[10];
    float* out = (float*)d_out;

    bf16 *p_wqkvn, *p_won, *p_w1n, *p_w3n, *p_w2n;
    float *p_wqkvs, *p_wos, *p_w1s, *p_w3s, *p_w2s;
    bf16 *p_hnh, *p_hnl, *p_oh, *p_ol, *p_uph, *p_upl;
    bf16 *p_xnh, *p_xnl;
    bf16 *p_qh, *p_ql, *p_kh, *p_kl, *p_vn, *p_ph, *p_pl;
    float *p_qkv, *p_vs, *p_sc, *p_h, *p_hn, *p_up1, *p_moeX, *p_twt;
    int *p_cnt, *p_tok, *p_tslot;
    cudaGetSymbolAddress((void**)&p_wqkvn, g_wqkvn); cudaGetSymbolAddress((void**)&p_wqkvs, g_wqkvs);
    cudaGetSymbolAddress((void**)&p_won, g_won); cudaGetSymbolAddress((void**)&p_wos, g_wos);
    cudaGetSymbolAddress((void**)&p_w1n, g_w1n); cudaGetSymbolAddress((void**)&p_w1s, g_w1s);
    cudaGetSymbolAddress((void**)&p_w3n, g_w3n); cudaGetSymbolAddress((void**)&p_w3s, g_w3s);
    cudaGetSymbolAddress((void**)&p_w2n, g_w2n); cudaGetSymbolAddress((void**)&p_w2s, g_w2s);
    cudaGetSymbolAddress((void**)&p_xnh, g_xnh); cudaGetSymbolAddress((void**)&p_xnl, g_xnl);
    cudaGetSymbolAddress((void**)&p_hnh, g_hnh); cudaGetSymbolAddress((void**)&p_hnl, g_hnl);
    cudaGetSymbolAddress((void**)&p_oh, g_oh);   cudaGetSymbolAddress((void**)&p_ol, g_ol);
    cudaGetSymbolAddress((void**)&p_uph, g_uph); cudaGetSymbolAddress((void**)&p_upl, g_upl);
    cudaGetSymbolAddress((void**)&p_qkv, g_qkv);
    cudaGetSymbolAddress((void**)&p_qh, g_qh);   cudaGetSymbolAddress((void**)&p_ql, g_ql);
    cudaGetSymbolAddress((void**)&p_kh, g_kh);   cudaGetSymbolAddress((void**)&p_kl, g_kl);
    cudaGetSymbolAddress((void**)&p_vn, g_vn);   cudaGetSymbolAddress((void**)&p_vs, g_vs);
    cudaGetSymbolAddress((void**)&p_sc, g_sc);
    cudaGetSymbolAddress((void**)&p_ph, g_ph);   cudaGetSymbolAddress((void**)&p_pl, g_pl);
    cudaGetSymbolAddress((void**)&p_h, g_h);     cudaGetSymbolAddress((void**)&p_hn, g_hn);
    cudaGetSymbolAddress((void**)&p_up1, g_up1); cudaGetSymbolAddress((void**)&p_moeX, g_moeX);
    cudaGetSymbolAddress((void**)&p_cnt, g_cnt); cudaGetSymbolAddress((void**)&p_tok, g_tok);
    cudaGetSymbolAddress((void**)&p_twt, g_twt); cudaGetSymbolAddress((void**)&p_tslot, g_tslot);

    cudaFuncSetAttribute(gemm_tc<0>, cudaFuncAttributeMaxDynamicSharedMemorySize, SMEM_SZ);
    cudaFuncSetAttribute(gemm_tc<1>, cudaFuncAttributeMaxDynamicSharedMemorySize, SMEM_SZ);
    cudaFuncSetAttribute(gemm_tc<2>, cudaFuncAttributeMaxDynamicSharedMemorySize, SMEM_SZ);
    cudaFuncSetAttribute(gemm_tc<4>, cudaFuncAttributeMaxDynamicSharedMemorySize, SMEM_SZ);
    cudaFuncSetAttribute(gemm_tc<5>, cudaFuncAttributeMaxDynamicSharedMemorySize, SMEM_SZ);
    cudaFuncSetAttribute(scores_tc, cudaFuncAttributeMaxDynamicSharedMemorySize, SCR_SMEM);
    cudaFuncSetAttribute(av_tc, cudaFuncAttributeMaxDynamicSharedMemorySize, AV_SMEM);

    static cudaStream_t s2 = nullptr;
    static cudaEvent_t ev_fork = nullptr, ev_join = nullptr;
    if (!s2) {
        cudaStreamCreateWithFlags(&s2, cudaStreamNonBlocking);
        cudaEventCreateWithFlags(&ev_fork, cudaEventDisableTiming);
        cudaEventCreateWithFlags(&ev_join, cudaEventDisableTiming);
    }

    zero_cnt_kernel<<<1, 32>>>(p_cnt);

    // fork: fused big MoE weight quants on s2 (grid.z selects w1/w3/w2)
    const int NG_BIG = EE * FFND * DD / 128;  // 229376 groups each
    cudaEventRecord(ev_fork, 0);
    cudaStreamWaitEvent(s2, ev_fork, 0);
    quantw3_kernel<<<dim3(NG_BIG / 16, 1, 3), 256, 0, s2>>>(
        w1, w3, w2, p_w1n, p_w3n, p_w2n, p_w1s, p_w3s, p_w2s, NG_BIG);
    cudaEventRecord(ev_join, s2);

    quantw_kernel<<<DD * DD / 128 / 16, 256>>>(w_q, p_wqkvn, p_wqkvs, DD * DD / 128);
    quantw_kernel<<<KV * HDIM * DD / 128 / 16, 256>>>(w_k, p_wqkvn + 1024 * DD,
        p_wqkvs + 1024 * 8, KV * HDIM * DD / 128);
    quantw_kernel<<<KV * HDIM * DD / 128 / 16, 256>>>(w_v, p_wqkvn + 1280 * DD,
        p_wqkvs + 1280 * 8, KV * HDIM * DD / 128);
    quantw_kernel<<<DD * DD / 128 / 16, 256>>>(w_o, p_won, p_wos, DD * DD / 128);

    // ---- attention ----
    rms_split_kernel<false><<<TT, 256>>>(hidden, g1, nullptr, p_xnh, p_xnl);
    gemm_tc<0><<<dim3(12, 16, 1), 256, SMEM_SZ>>>(p_xnh, p_xnl, DD, 0,
        p_wqkvn, p_wqkvs, DD, 0, 0,
        p_qkv, nullptr, nullptr, NQKV, 0, TT, nullptr, DD, nullptr, nullptr);
    kvprep_kernel<<<TT * (HH + KV + KV), HDIM>>>(p_qkv, p_qh, p_ql, p_kh, p_kl, p_vn, p_vs);
    scores_tc<<<dim3(8, 8, BB * HH), 256, SCR_SMEM>>>(p_qh, p_ql, p_kh, p_kl, p_sc);
    softmax_kernel<<<BB * HH * SS, 256>>>(p_sc, p_vs, p_ph, p_pl);
    av_tc<<<dim3(1, 8, BB * HH), 256, AV_SMEM>>>(p_ph, p_pl, p_vn, p_oh, p_ol);
    gemm_tc<1><<<dim3(8, 16, 1), 256, SMEM_SZ>>>(p_oh, p_ol, DD, 0,
        p_won, p_wos, DD, 0, 0,
        p_h, nullptr, nullptr, DD, 0, TT, nullptr, DD, hidden, nullptr);

    // ---- MoE ----
    rms_split_kernel<true><<<TT, 256>>>(p_h, g2, p_hn, p_hnh, p_hnl);
    router_kernel<<<TT, 256>>>(p_hn, w_gate);
    cudaStreamWaitEvent(0, ev_join, 0);
    gemm_tc<2><<<dim3(28, 16, EE), 256, SMEM_SZ>>>(p_hnh, p_hnl, DD, 0,
        p_w1n, p_w1s, DD, (size_t)FFND * DD, (size_t)FFND * 8,
        p_up1, nullptr, nullptr, FFND, (size_t)TT * FFND,
        0, p_cnt, DD, nullptr, p_tok);
    gemm_tc<4><<<dim3(28, 16, EE), 256, SMEM_SZ>>>(p_hnh, p_hnl, DD, 0,
        p_w3n, p_w3s, DD, (size_t)FFND * DD, (size_t)FFND * 8,
        nullptr, p_uph, p_upl, FFND, (size_t)TT * FFND,
        0, p_cnt, DD, p_up1, p_tok);
    gemm_tc<5><<<dim3(8, 16, EE), 256, SMEM_SZ>>>(p_uph, p_upl, FFND, (size_t)TT * FFND,
        p_w2n, p_w2s, FFND, (size_t)DD * FFND, (size_t)DD * 28,
        p_moeX, nullptr, nullptr, DD, (size_t)TT * DD,
        0, p_cnt, FFND, nullptr, nullptr);
    final_gather_kernel<<<TT, 256>>>(p_h, p_moeX, p_tslot, p_twt, out);
}

// round 16
// speedup vs baseline: 2.0852x; 1.0616x over previous
#include <cuda_runtime.h>
#include <cuda_bf16.h>
#include <math.h>
#include <stdint.h>

#define BB 2
#define SS 1024
#define TT 2048
#define DD 1024
#define HH 8
#define KV 2
#define HDIM 128
#define EE 8
#define FFND 3584
#define NQKV 1536

#define KT 64
#define STAGES 4
#define TILE_BYTES 16384
#define STAGE_BYTES (3 * TILE_BYTES)
#define SC_OFF (STAGES * STAGE_BYTES)
#define SMEM_SZ (SC_OFF + 28 * 128 * 4)
#define SCR_SMEM (2 * 4 * TILE_BYTES)
#define AV_STAGE (3 * TILE_BYTES)
#define AV_SMEM (3 * AV_STAGE)
// w13 fused kernel: 3 stages + dual scales + acc scratch
#define W13_STAGES 3
#define W13_SC_OFF (W13_STAGES * STAGE_BYTES)          // 147456
#define W13_ACC_OFF (W13_SC_OFF + 2 * 8 * 128 * 4)     // +8KB = 155648
#define W13_SMEM (W13_ACC_OFF + 256 * 64 * 4)          // +64KB = 221184

typedef __nv_bfloat16 bf16;

// weights: integer bf16 + per-group fp32 scale
__device__ bf16  g_wqkvn[NQKV * DD];       __device__ float g_wqkvs[NQKV * DD / 128];
__device__ bf16  g_won[DD * DD];           __device__ float g_wos[DD * DD / 128];
__device__ bf16  g_w1n[EE * FFND * DD];    __device__ float g_w1s[EE * FFND * DD / 128];
__device__ bf16  g_w3n[EE * FFND * DD];    __device__ float g_w3s[EE * FFND * DD / 128];
__device__ bf16  g_w2n[EE * DD * FFND];    __device__ float g_w2s[EE * DD * FFND / 128];
// activations
__device__ bf16 g_xnh[TT * DD];        __device__ bf16 g_xnl[TT * DD];
__device__ bf16 g_hnh[TT * DD];        __device__ bf16 g_hnl[TT * DD];
__device__ bf16 g_oh[TT * DD];         __device__ bf16 g_ol[TT * DD];
__device__ bf16 g_uph[EE * TT * FFND]; __device__ bf16 g_upl[EE * TT * FFND];
__device__ float g_qkv[TT * NQKV];
__device__ bf16 g_qh[TT * DD];         __device__ bf16 g_ql[TT * DD];
__device__ bf16 g_kh[TT * KV * HDIM];  __device__ bf16 g_kl[TT * KV * HDIM];
__device__ bf16 g_vn[TT * KV * HDIM];  __device__ float g_vs[TT * KV];
__device__ float g_sc[BB * HH * SS * SS];
__device__ bf16 g_ph[BB * HH * SS * SS];
__device__ bf16 g_pl[BB * HH * SS * SS];
__device__ float g_h[TT * DD];
__device__ float g_hn[TT * DD];
__device__ float g_moeX[EE * TT * DD];
__device__ int   g_cnt[EE];
__device__ int   g_tok[EE * TT];
__device__ float g_twt[EE * TT];
__device__ int   g_tslot[TT * 2];

// ---------------- ptx helpers ----------------
__device__ __forceinline__ uint32_t smem_u32(const void* p) {
    uint32_t a;
    asm("{ .reg .u64 t; cvta.to.shared.u64 t, %1; cvt.u32.u64 %0, t; }" : "=r"(a) : "l"(p));
    return a;
}
__device__ __forceinline__ void ldsm4(uint32_t a, uint32_t& r0, uint32_t& r1,
                                      uint32_t& r2, uint32_t& r3) {
    asm volatile("ldmatrix.sync.aligned.m8n8.x4.shared.b16 {%0,%1,%2,%3}, [%4];"
                 : "=r"(r0), "=r"(r1), "=r"(r2), "=r"(r3) : "r"(a));
}
__device__ __forceinline__ void ldsm4t(uint32_t a, uint32_t& r0, uint32_t& r1,
                                       uint32_t& r2, uint32_t& r3) {
    asm volatile("ldmatrix.sync.aligned.m8n8.x4.trans.shared.b16 {%0,%1,%2,%3}, [%4];"
                 : "=r"(r0), "=r"(r1), "=r"(r2), "=r"(r3) : "r"(a));
}
__device__ __forceinline__ void mma16816(float* c, const uint32_t* a, const uint32_t* b) {
    asm volatile("mma.sync.aligned.m16n8k16.row.col.f32.bf16.bf16.f32 "
                 "{%0,%1,%2,%3}, {%4,%5,%6,%7}, {%8,%9}, {%0,%1,%2,%3};"
                 : "+f"(c[0]), "+f"(c[1]), "+f"(c[2]), "+f"(c[3])
                 : "r"(a[0]), "r"(a[1]), "r"(a[2]), "r"(a[3]), "r"(b[0]), "r"(b[1]));
}
__device__ __forceinline__ void cpa16(uint32_t dst, const void* src) {
    asm volatile("cp.async.cg.shared.global [%0], [%1], 16;" :: "r"(dst), "l"(src));
}
__device__ __forceinline__ void cpa_commit() { asm volatile("cp.async.commit_group;" ::: "memory"); }
__device__ __forceinline__ void cpa_wait0() { asm volatile("cp.async.wait_group 0;" ::: "memory"); }
__device__ __forceinline__ void cpa_wait1() { asm volatile("cp.async.wait_group 1;" ::: "memory"); }
__device__ __forceinline__ void cpa_wait2() { asm volatile("cp.async.wait_group 2;" ::: "memory"); }

__device__ __forceinline__ float warp_sum(float v) {
    #pragma unroll
    for (int o = 16; o; o >>= 1) v += __shfl_xor_sync(0xffffffffu, v, o);
    return v;
}
__device__ __forceinline__ void split_bf(float v, bf16& h, bf16& l) {
    h = __float2bfloat16(v);
    l = __float2bfloat16(v - __bfloat162float(h));
}
__device__ __forceinline__ uint32_t swz(uint32_t off) { return off ^ ((off >> 3) & 0x70); }

// ---------------- small kernels ----------------
__global__ void zero_cnt_kernel(int* __restrict__ cnt) {
    if (threadIdx.x < EE) cnt[threadIdx.x] = 0;
}

// one 128-group per 16-lane half; 8 elems/lane; packed bf16x2 converts.
__device__ __forceinline__ void quant_group(const float* __restrict__ w,
                                            bf16* __restrict__ nq,
                                            float* __restrict__ sc,
                                            int g, int l16) {
    const float4* src = reinterpret_cast<const float4*>(w) + (size_t)g * 32 + l16 * 2;
    float4 v0 = src[0], v1 = src[1];
    float mn = fminf(fminf(fminf(v0.x, v0.y), fminf(v0.z, v0.w)),
                     fminf(fminf(v1.x, v1.y), fminf(v1.z, v1.w)));
    float mx = fmaxf(fmaxf(fmaxf(v0.x, v0.y), fmaxf(v0.z, v0.w)),
                     fmaxf(fmaxf(v1.x, v1.y), fmaxf(v1.z, v1.w)));
    #pragma unroll
    for (int o = 8; o; o >>= 1) {
        mn = fminf(mn, __shfl_xor_sync(0xffffffffu, mn, o, 16));
        mx = fmaxf(mx, __shfl_xor_sync(0xffffffffu, mx, o, 16));
    }
    float scale = fmaxf(mx - mn, 1e-5f) / 15.0f;
    float sinv = 1.0f / scale;
    float base = fminf(fmaxf(rintf(-mn * sinv), 0.f), 15.f);
    float qmin = -base, qmax = 15.0f - base;
    float q[8];
    q[0] = v0.x; q[1] = v0.y; q[2] = v0.z; q[3] = v0.w;
    q[4] = v1.x; q[5] = v1.y; q[6] = v1.z; q[7] = v1.w;
    #pragma unroll
    for (int j = 0; j < 8; j++)
        q[j] = fminf(fmaxf(rintf(q[j] * sinv), qmin), qmax);
    __nv_bfloat162 p[4];
    #pragma unroll
    for (int j = 0; j < 4; j++)
        p[j] = __floats2bfloat162_rn(q[2 * j], q[2 * j + 1]);
    *reinterpret_cast<uint4*>(nq + (size_t)g * 128 + l16 * 8) =
        *reinterpret_cast<uint4*>(p);
    if (l16 == 0) sc[g] = scale;
}

__global__ void quantw_kernel(const float* __restrict__ w, bf16* __restrict__ nq,
                              float* __restrict__ sc, int ngroups) {
    int g = blockIdx.x * 16 + (threadIdx.x >> 4);
    if (g >= ngroups) return;
    quant_group(w, nq, sc, g, threadIdx.x & 15);
}

__global__ void quantw3_kernel(const float* __restrict__ wa, const float* __restrict__ wb,
                               const float* __restrict__ wc,
                               bf16* __restrict__ na, bf16* __restrict__ nb,
                               bf16* __restrict__ nc,
                               float* __restrict__ sa, float* __restrict__ sb,
                               float* __restrict__ scc, int ngroups) {
    int g = blockIdx.x * 16 + (threadIdx.x >> 4);
    if (g >= ngroups) return;
    const float* w;
    bf16* nq;
    float* sc;
    if (blockIdx.z == 0)      { w = wa; nq = na; sc = sa; }
    else if (blockIdx.z == 1) { w = wb; nq = nb; sc = sb; }
    else                      { w = wc; nq = nc; sc = scc; }
    quant_group(w, nq, sc, g, threadIdx.x & 15);
}

template<bool WF32>
__global__ void rms_split_kernel(const float* __restrict__ x, const float* __restrict__ g,
                                 float* __restrict__ f32o, bf16* __restrict__ hi,
                                 bf16* __restrict__ lo) {
    int row = blockIdx.x;
    const float* xr = x + (size_t)row * DD;
    float s = 0.f;
    for (int i = threadIdx.x; i < DD; i += 256) { float v = xr[i]; s += v * v; }
    __shared__ float sh[256];
    sh[threadIdx.x] = s; __syncthreads();
    for (int o2 = 128; o2; o2 >>= 1) {
        if (threadIdx.x < o2) sh[threadIdx.x] += sh[threadIdx.x + o2];
        __syncthreads();
    }
    float inv = rsqrtf(sh[0] * (1.0f / DD) + 1e-5f);
    for (int i = threadIdx.x; i < DD; i += 256) {
        float v = xr[i] * inv * g[i];
        if (WF32) f32o[(size_t)row * DD + i] = v;
        bf16 h, l; split_bf(v, h, l);
        hi[(size_t)row * DD + i] = h;
        lo[(size_t)row * DD + i] = l;
    }
}

// ===== bf16x2 mma.sync GEMM with exact integer weights + per-group rescale =====
// MODE 0 store f32 | 1 +resid | 5 direct-A slot rows, M=Mptr[z], store f32 z-strided
template<int MODE>
__global__ __launch_bounds__(256, 1) void gemm_tc(
    const bf16* __restrict__ Ahi, const bf16* __restrict__ Alo, int lda, size_t strideA,
    const bf16* __restrict__ Bn, const float* __restrict__ Bsc, int ldb,
    size_t strideB, size_t strideBs,
    float* __restrict__ C, int ldc, size_t strideC,
    int M, const int* __restrict__ Mptr, int K,
    const float* __restrict__ resid)
{
    int z = blockIdx.z;
    if (Mptr) M = Mptr[z];
    int m0 = blockIdx.y * 128;
    if (m0 >= M) return;
    int n0 = blockIdx.x * 128;
    int tid = threadIdx.x;
    int wid = tid >> 5, lid = tid & 31;

    extern __shared__ char smem[];
    uint32_t sb = smem_u32(smem);
    float* scs = reinterpret_cast<float*>(smem + SC_OFF);
    int G = K >> 7;

    for (int i = tid; i < G * 128; i += 256) {
        int g = i >> 7, c = i & 127;
        scs[i] = Bsc[strideBs * z + (size_t)(n0 + c) * G + g];
    }

    const bf16* srcA[4]; const bf16* srcB[4];
    uint32_t dstA[4], dstB[4];
    ptrdiff_t dlo = Alo - Ahi;
    #pragma unroll
    for (int ci = 0; ci < 4; ci++) {
        int gid = ci * 256 + tid;
        int r = (gid >> 3) & 127;
        int c8 = gid & 7;
        int row = m0 + r;
        if (row >= M) row = m0;
        srcA[ci] = Ahi + strideA * (size_t)z + (size_t)row * lda + c8 * 8;
        dstA[ci] = swz((uint32_t)(r * 128 + c8 * 16));
        int gid2 = 2048 + gid;
        int r2 = (gid2 >> 3) & 127;
        int c82 = gid2 & 7;
        srcB[ci] = Bn + strideB * (size_t)z + (size_t)(n0 + r2) * ldb + c82 * 8;
        dstB[ci] = (uint32_t)(2 * TILE_BYTES) + swz((uint32_t)(r2 * 128 + c82 * 16));
    }

    int n_kt = K / KT;
    int npro = STAGES - 1; if (npro > n_kt) npro = n_kt;
    #pragma unroll 1
    for (int p = 0; p < npro; p++) {
        uint32_t base = sb + p * STAGE_BYTES;
        size_t ko = (size_t)p * KT;
        #pragma unroll
        for (int ci = 0; ci < 4; ci++) {
            cpa16(base + dstA[ci], srcA[ci] + ko);
            cpa16(base + TILE_BYTES + dstA[ci], srcA[ci] + dlo + ko);
            cpa16(base + dstB[ci], srcB[ci] + ko);
        }
        cpa_commit();
    }

    int wr = (wid & 3) * 32;
    int wc = (wid >> 2) * 64;
    int rowm = (lid & 7) + ((lid >> 3) & 1) * 8;
    int colb = (lid >> 4) * 16;

    float acc[2][8][4] = {};
    float accg[2][8][4] = {};

    #pragma unroll 1
    for (int kt = 0; kt < n_kt; kt++) {
        int pending = n_kt - kt - 1; if (pending > STAGES - 2) pending = STAGES - 2;
        if (pending >= 2) cpa_wait2();
        else if (pending == 1) cpa_wait1();
        else cpa_wait0();
        __syncthreads();
        if (kt + STAGES - 1 < n_kt) {
            int sl = (kt + STAGES - 1) % STAGES;
            uint32_t base = sb + sl * STAGE_BYTES;
            size_t ko = (size_t)(kt + STAGES - 1) * KT;
            #pragma unroll
            for (int ci = 0; ci < 4; ci++) {
                cpa16(base + dstA[ci], srcA[ci] + ko);
                cpa16(base + TILE_BYTES + dstA[ci], srcA[ci] + dlo + ko);
                cpa16(base + dstB[ci], srcB[ci] + ko);
            }
            cpa_commit();
        }
        uint32_t sbase = sb + (kt % STAGES) * STAGE_BYTES;
        #pragma unroll
        for (int s16 = 0; s16 < 4; s16++) {
            int kb0 = s16 * 32 + colb;
            uint32_t ah[2][4], al[2][4], bn[8][2];
            #pragma unroll
            for (int i = 0; i < 2; i++) {
                uint32_t off = (uint32_t)((wr + i * 16 + rowm) * 128 + kb0);
                ldsm4(sbase + swz(off), ah[i][0], ah[i][1], ah[i][2], ah[i][3]);
                ldsm4(sbase + TILE_BYTES + swz(off), al[i][0], al[i][1], al[i][2], al[i][3]);
            }
            #pragma unroll
            for (int j = 0; j < 4; j++) {
                uint32_t off = (uint32_t)((wc + j * 16 + rowm) * 128 + kb0);
                uint32_t r0, r1, r2, r3;
                ldsm4(sbase + 2 * TILE_BYTES + swz(off), r0, r1, r2, r3);
                bn[j * 2][0] = r0; bn[j * 2][1] = r2;
                bn[j * 2 + 1][0] = r1; bn[j * 2 + 1][1] = r3;
            }
            #pragma unroll
            for (int i = 0; i < 2; i++)
                #pragma unroll
                for (int jn = 0; jn < 8; jn++) {
                    mma16816(accg[i][jn], ah[i], bn[jn]);
                    mma16816(accg[i][jn], al[i], bn[jn]);
                }
        }
        if (kt & 1) {
            int g = kt >> 1;
            #pragma unroll
            for (int jn = 0; jn < 8; jn++) {
                int c = wc + jn * 8 + (lid & 3) * 2;
                float s0 = scs[g * 128 + c];
                float s1 = scs[g * 128 + c + 1];
                #pragma unroll
                for (int i = 0; i < 2; i++) {
                    acc[i][jn][0] += s0 * accg[i][jn][0];
                    acc[i][jn][1] += s1 * accg[i][jn][1];
                    acc[i][jn][2] += s0 * accg[i][jn][2];
                    acc[i][jn][3] += s1 * accg[i][jn][3];
                    accg[i][jn][0] = 0.f; accg[i][jn][1] = 0.f;
                    accg[i][jn][2] = 0.f; accg[i][jn][3] = 0.f;
                }
            }
        }
    }

    #pragma unroll
    for (int i = 0; i < 2; i++) {
        #pragma unroll
        for (int jn = 0; jn < 8; jn++) {
            int r0 = m0 + wr + i * 16 + (lid >> 2);
            int cc = n0 + wc + jn * 8 + (lid & 3) * 2;
            #pragma unroll
            for (int half = 0; half < 2; half++) {
                int row = r0 + half * 8;
                if (row >= M) continue;
                float v0 = acc[i][jn][half * 2 + 0];
                float v1 = acc[i][jn][half * 2 + 1];
                float* Cr = C + strideC * z + (size_t)row * ldc + cc;
                if (MODE == 1) {
                    const float* rr = resid + (size_t)row * ldc + cc;
                    v0 += rr[0]; v1 += rr[1];
                }
                *reinterpret_cast<float2*>(Cr) = make_float2(v0, v1);
            }
        }
    }
}

// ===== fused w1+w3 GEMM: two passes over B sharing gathered A; epilogue =====
// silu(acc_w1)*acc_w3 split-stored to CH/CL. Pass-0 acc parked in smem scratch.
__global__ __launch_bounds__(256, 1) void gemm_w13(
    const bf16* __restrict__ Ahi, const bf16* __restrict__ Alo, int lda,
    const bf16* __restrict__ B1, const float* __restrict__ S1,
    const bf16* __restrict__ B3, const float* __restrict__ S3,
    int ldb, size_t strideB, size_t strideBs,
    bf16* __restrict__ CH, bf16* __restrict__ CL, int ldc, size_t strideC,
    const int* __restrict__ Mptr, int K, const int* __restrict__ idx)
{
    int z = blockIdx.z;
    int M = Mptr[z];
    int m0 = blockIdx.y * 128;
    if (m0 >= M) return;
    int n0 = blockIdx.x * 128;
    int tid = threadIdx.x;
    int wid = tid >> 5, lid = tid & 31;

    extern __shared__ char smem[];
    uint32_t sb = smem_u32(smem);
    float* scs = reinterpret_cast<float*>(smem + W13_SC_OFF);
    float* accs = reinterpret_cast<float*>(smem + W13_ACC_OFF);
    const int* idxz = idx + (size_t)z * TT;
    int G = K >> 7;

    // dual scale sets: [0..G*128) w1, [G*128..) w3
    for (int i = tid; i < G * 128; i += 256) {
        int g = i >> 7, c = i & 127;
        scs[i] = S1[strideBs * z + (size_t)(n0 + c) * G + g];
        scs[G * 128 + i] = S3[strideBs * z + (size_t)(n0 + c) * G + g];
    }

    const bf16* srcA[4];
    uint32_t dstA[4], dstB[4];
    int bRow[4], bC8[4];
    ptrdiff_t dlo = Alo - Ahi;
    #pragma unroll
    for (int ci = 0; ci < 4; ci++) {
        int gid = ci * 256 + tid;
        int r = (gid >> 3) & 127;
        int c8 = gid & 7;
        int row = m0 + r;
        if (row >= M) row = m0;
        int rg = idxz[row];
        srcA[ci] = Ahi + (size_t)rg * lda + c8 * 8;
        dstA[ci] = swz((uint32_t)(r * 128 + c8 * 16));
        int gid2 = 2048 + gid;
        int r2 = (gid2 >> 3) & 127;
        int c82 = gid2 & 7;
        bRow[ci] = n0 + r2; bC8[ci] = c82;
        dstB[ci] = (uint32_t)(2 * TILE_BYTES) + swz((uint32_t)(r2 * 128 + c82 * 16));
    }

    int wr = (wid & 3) * 32;
    int wc = (wid >> 2) * 64;
    int rowm = (lid & 7) + ((lid >> 3) & 1) * 8;
    int colb = (lid >> 4) * 16;
    int n_kt = K / KT;

    float acc[2][8][4];
    float accg[2][8][4] = {};

    #pragma unroll 1
    for (int p13 = 0; p13 < 2; p13++) {
        const bf16* Bbase = p13 ? B3 : B1;
        const bf16* srcB[4];
        #pragma unroll
        for (int ci = 0; ci < 4; ci++)
            srcB[ci] = Bbase + strideB * (size_t)z + (size_t)bRow[ci] * ldb + bC8[ci] * 8;
        if (p13) __syncthreads();  // stage buffers must be drained before reuse

        #pragma unroll
        for (int i = 0; i < 2; i++)
            #pragma unroll
            for (int jn = 0; jn < 8; jn++)
                #pragma unroll
                for (int q = 0; q < 4; q++) acc[i][jn][q] = 0.f;

        int npro = W13_STAGES - 1; if (npro > n_kt) npro = n_kt;
        #pragma unroll 1
        for (int p = 0; p < npro; p++) {
            uint32_t base = sb + p * STAGE_BYTES;
            size_t ko = (size_t)p * KT;
            #pragma unroll
            for (int ci = 0; ci < 4; ci++) {
                cpa16(base + dstA[ci], srcA[ci] + ko);
                cpa16(base + TILE_BYTES + dstA[ci], srcA[ci] + dlo + ko);
                cpa16(base + dstB[ci], srcB[ci] + ko);
            }
            cpa_commit();
        }

        #pragma unroll 1
        for (int kt = 0; kt < n_kt; kt++) {
            int pending = n_kt - kt - 1;
            if (pending > W13_STAGES - 2) pending = W13_STAGES - 2;
            if (pending >= 1) cpa_wait1();
            else cpa_wait0();
            __syncthreads();
            if (kt + W13_STAGES - 1 < n_kt) {
                int sl = (kt + W13_STAGES - 1) % W13_STAGES;
                uint32_t base = sb + sl * STAGE_BYTES;
                size_t ko = (size_t)(kt + W13_STAGES - 1) * KT;
                #pragma unroll
                for (int ci = 0; ci < 4; ci++) {
                    cpa16(base + dstA[ci], srcA[ci] + ko);
                    cpa16(base + TILE_BYTES + dstA[ci], srcA[ci] + dlo + ko);
                    cpa16(base + dstB[ci], srcB[ci] + ko);
                }
                cpa_commit();
            }
            uint32_t sbase = sb + (kt % W13_STAGES) * STAGE_BYTES;
            #pragma unroll
            for (int s16 = 0; s16 < 4; s16++) {
                int kb0 = s16 * 32 + colb;
                uint32_t ah[2][4], al[2][4], bn[8][2];
                #pragma unroll
                for (int i = 0; i < 2; i++) {
                    uint32_t off = (uint32_t)((wr + i * 16 + rowm) * 128 + kb0);
                    ldsm4(sbase + swz(off), ah[i][0], ah[i][1], ah[i][2], ah[i][3]);
                    ldsm4(sbase + TILE_BYTES + swz(off), al[i][0], al[i][1], al[i][2], al[i][3]);
                }
                #pragma unroll
                for (int j = 0; j < 4; j++) {
                    uint32_t off = (uint32_t)((wc + j * 16 + rowm) * 128 + kb0);
                    uint32_t r0, r1, r2, r3;
                    ldsm4(sbase + 2 * TILE_BYTES + swz(off), r0, r1, r2, r3);
                    bn[j * 2][0] = r0; bn[j * 2][1] = r2;
                    bn[j * 2 + 1][0] = r1; bn[j * 2 + 1][1] = r3;
                }
                #pragma unroll
                for (int i = 0; i < 2; i++)
                    #pragma unroll
                    for (int jn = 0; jn < 8; jn++) {
                        mma16816(accg[i][jn], ah[i], bn[jn]);
                        mma16816(accg[i][jn], al[i], bn[jn]);
                    }
            }
            if (kt & 1) {
                int g = kt >> 1;
                const float* scp = scs + p13 * (G * 128);
                #pragma unroll
                for (int jn = 0; jn < 8; jn++) {
                    int c = wc + jn * 8 + (lid & 3) * 2;
                    float s0 = scp[g * 128 + c];
                    float s1 = scp[g * 128 + c + 1];
                    #pragma unroll
                    for (int i = 0; i < 2; i++) {
                        acc[i][jn][0] += s0 * accg[i][jn][0];
                        acc[i][jn][1] += s1 * accg[i][jn][1];
                        acc[i][jn][2] += s0 * accg[i][jn][2];
                        acc[i][jn][3] += s1 * accg[i][jn][3];
                        accg[i][jn][0] = 0.f; accg[i][jn][1] = 0.f;
                        accg[i][jn][2] = 0.f; accg[i][jn][3] = 0.f;
                    }
                }
            }
        }

        if (p13 == 0) {
            // park w1 acc in smem scratch (stride-256 layout, conflict-free)
            #pragma unroll
            for (int i = 0; i < 2; i++)
                #pragma unroll
                for (int jn = 0; jn < 8; jn++)
                    #pragma unroll
                    for (int q = 0; q < 4; q++)
                        accs[((i * 8 + jn) * 4 + q) * 256 + tid] = acc[i][jn][q];
        }
    }

    // epilogue: gv = silu(w1) * w3, split to bf16 hi/lo
    #pragma unroll
    for (int i = 0; i < 2; i++) {
        #pragma unroll
        for (int jn = 0; jn < 8; jn++) {
            int r0 = m0 + wr + i * 16 + (lid >> 2);
            int cc = n0 + wc + jn * 8 + (lid & 3) * 2;
            #pragma unroll
            for (int half = 0; half < 2; half++) {
                int row = r0 + half * 8;
                if (row >= M) continue;
                float a0 = accs[((i * 8 + jn) * 4 + half * 2 + 0) * 256 + tid];
                float a1 = accs[((i * 8 + jn) * 4 + half * 2 + 1) * 256 + tid];
                float v0 = acc[i][jn][half * 2 + 0];
                float v1 = acc[i][jn][half * 2 + 1];
                float gv0 = (a0 / (1.f + expf(-a0))) * v0;
                float gv1 = (a1 / (1.f + expf(-a1))) * v1;
                bf16 h0, l0, h1, l1;
                split_bf(gv0, h0, l0); split_bf(gv1, h1, l1);
                size_t o = strideC * z + (size_t)row * ldc + cc;
                CH[o] = h0; CH[o + 1] = h1;
                CL[o] = l0; CL[o + 1] = l1;
            }
        }
    }
}

// ---------------- fused q-rope / k-quant+rope / v-quant prep ----------------
__global__ void kvprep_kernel(const float* __restrict__ qkv,
                              bf16* __restrict__ qh, bf16* __restrict__ ql,
                              bf16* __restrict__ kh, bf16* __restrict__ kl,
                              bf16* __restrict__ vn, float* __restrict__ vs) {
    int j = blockIdx.x;
    int d = threadIdx.x;
    __shared__ float smn[HDIM], smx[HDIM], sh[HDIM];
    if (j < TT * HH) {
        int t = j >> 3, hh = j & 7;
        sh[d] = qkv[(size_t)t * NQKV + hh * HDIM + d];
        __syncthreads();
        int pos = t & (SS - 1);
        int i = d & 63;
        float invf = expf(-13.815510557964274f * ((float)(2 * i) * (1.0f / HDIM)));
        float f = (float)pos * invf;
        float c = cosf(f), sn = sinf(f);
        float v = (d < 64) ? (sh[d] * c - sh[d + 64] * sn)
                           : (sh[d] * c + sh[d - 64] * sn);
        bf16 h, l; split_bf(v, h, l);
        qh[(size_t)j * HDIM + d] = h;
        ql[(size_t)j * HDIM + d] = l;
        return;
    }
    int j2 = j - TT * HH;
    bool isK = j2 < TT * KV;
    int rowid = isK ? j2 : (j2 - TT * KV);
    int t = rowid >> 1, kvh = rowid & 1;
    float v = qkv[(size_t)t * NQKV + (isK ? 1024 : 1280) + kvh * HDIM + d];
    smn[d] = v; smx[d] = v; __syncthreads();
    for (int o2 = 64; o2; o2 >>= 1) {
        if (d < o2) {
            smn[d] = fminf(smn[d], smn[d + o2]);
            smx[d] = fmaxf(smx[d], smx[d + o2]);
        }
        __syncthreads();
    }
    float scale = fmaxf(smx[0] - smn[0], 1e-5f) / 15.0f;
    float sinv = 1.0f / scale;
    float base = fminf(fmaxf(rintf(-smn[0] * sinv), 0.f), 15.f);
    float qn = fminf(fmaxf(rintf(v * sinv), -base), 15.0f - base);
    if (!isK) {
        vn[(size_t)rowid * HDIM + d] = __float2bfloat16(qn);
        if (d == 0) vs[rowid] = scale;
        return;
    }
    float q = qn * scale;
    sh[d] = q; __syncthreads();
    int pos = t & (SS - 1);
    int i = d & 63;
    float invf = expf(-13.815510557964274f * ((float)(2 * i) * (1.0f / HDIM)));
    float f = (float)pos * invf;
    float c = cosf(f), sn = sinf(f);
    q = (d < 64) ? (sh[d] * c - sh[d + 64] * sn)
                 : (sh[d] * c + sh[d - 64] * sn);
    bf16 h, l; split_bf(q, h, l);
    kh[(size_t)rowid * HDIM + d] = h;
    kl[(size_t)rowid * HDIM + d] = l;
}

// ---------------- TC scores ----------------
__global__ __launch_bounds__(256, 1) void scores_tc(
    const bf16* __restrict__ qh, const bf16* __restrict__ ql,
    const bf16* __restrict__ kh, const bf16* __restrict__ kl,
    float* __restrict__ sc)
{
    int z = blockIdx.z;
    int m0 = blockIdx.y * 128, n0 = blockIdx.x * 128;
    if (n0 > m0) return;
    int b = z >> 3, hh = z & 7, kvh = (z & 7) >> 2;
    int tid = threadIdx.x, wid = tid >> 5, lid = tid & 31;
    extern __shared__ char smem[];
    uint32_t sb = smem_u32(smem);

    const bf16* src[16]; uint32_t dst[16];
    #pragma unroll
    for (int ci = 0; ci < 16; ci++) {
        int gid = ci * 256 + tid;
        int t4 = gid >> 10;
        int r = (gid >> 3) & 127;
        int c8 = gid & 7;
        const bf16* p;
        if (t4 == 0)      p = qh + ((size_t)(b * SS + m0 + r) * HH + hh) * HDIM;
        else if (t4 == 1) p = ql + ((size_t)(b * SS + m0 + r) * HH + hh) * HDIM;
        else if (t4 == 2) p = kh + ((size_t)(b * SS + n0 + r) * KV + kvh) * HDIM;
        else              p = kl + ((size_t)(b * SS + n0 + r) * KV + kvh) * HDIM;
        src[ci] = p + c8 * 8;
        dst[ci] = (uint32_t)(t4 * TILE_BYTES) + swz((uint32_t)(r * 128 + c8 * 16));
    }
    #pragma unroll
    for (int ci = 0; ci < 16; ci++) cpa16(sb + dst[ci], src[ci]);
    cpa_commit();
    #pragma unroll
    for (int ci = 0; ci < 16; ci++) cpa16(sb + 4 * TILE_BYTES + dst[ci], src[ci] + 64);
    cpa_commit();

    int wr = (wid & 3) * 32;
    int wc = (wid >> 2) * 64;
    int rowm = (lid & 7) + ((lid >> 3) & 1) * 8;
    int colb = (lid >> 4) * 16;
    float acc[2][8][4] = {};

    #pragma unroll 1
    for (int ch = 0; ch < 2; ch++) {
        if (ch == 0) cpa_wait1(); else cpa_wait0();
        __syncthreads();
        uint32_t base = sb + ch * 4 * TILE_BYTES;
        #pragma unroll
        for (int s16 = 0; s16 < 4; s16++) {
            int kb0 = s16 * 32 + colb;
            uint32_t ah[2][4], al[2][4], bh[8][2], bl[8][2];
            #pragma unroll
            for (int i = 0; i < 2; i++) {
                uint32_t off = (uint32_t)((wr + i * 16 + rowm) * 128 + kb0);
                ldsm4(base + swz(off), ah[i][0], ah[i][1], ah[i][2], ah[i][3]);
                ldsm4(base + TILE_BYTES + swz(off), al[i][0], al[i][1], al[i][2], al[i][3]);
            }
            #pragma unroll
            for (int j = 0; j < 4; j++) {
                uint32_t off = (uint32_t)((wc + j * 16 + rowm) * 128 + kb0);
                uint32_t r0, r1, r2, r3;
                ldsm4(base + 2 * TILE_BYTES + swz(off), r0, r1, r2, r3);
                bh[j * 2][0] = r0; bh[j * 2][1] = r2;
                bh[j * 2 + 1][0] = r1; bh[j * 2 + 1][1] = r3;
                ldsm4(base + 3 * TILE_BYTES + swz(off), r0, r1, r2, r3);
                bl[j * 2][0] = r0; bl[j * 2][1] = r2;
                bl[j * 2 + 1][0] = r1; bl[j * 2 + 1][1] = r3;
            }
            #pragma unroll
            for (int i = 0; i < 2; i++)
                #pragma unroll
                for (int jn = 0; jn < 8; jn++) {
                    mma16816(acc[i][jn], ah[i], bh[jn]);
                    mma16816(acc[i][jn], ah[i], bl[jn]);
                    mma16816(acc[i][jn], al[i], bh[jn]);
                }
        }
    }
    const float scalef = 0.08838834764831845f;
    float* C = sc + (size_t)z * SS * SS;
    #pragma unroll
    for (int i = 0; i < 2; i++)
        #pragma unroll
        for (int jn = 0; jn < 8; jn++) {
            int r0 = m0 + wr + i * 16 + (lid >> 2);
            int cc = n0 + wc + jn * 8 + (lid & 3) * 2;
            #pragma unroll
            for (int half = 0; half < 2; half++) {
                int row = r0 + half * 8;
                float v0 = acc[i][jn][half * 2 + 0] * scalef;
                float v1 = acc[i][jn][half * 2 + 1] * scalef;
                *reinterpret_cast<float2*>(C + (size_t)row * SS + cc) = make_float2(v0, v1);
            }
        }
}

// ------- softmax: exp values kept in registers; sc is read-only here ----------
__global__ void softmax_kernel(const float* __restrict__ sc, const float* __restrict__ vs,
                               bf16* __restrict__ ph, bf16* __restrict__ pl) {
    int r = blockIdx.x;
    int z = r >> 10;
    int s = r & (SS - 1);
    int b = z >> 3, kvh = (z & 7) >> 2;
    const float* row = sc + (size_t)r * SS;
    int n = s + 1;
    int nlim = (s | 127) + 1;
    __shared__ float sh[256];
    float m = -INFINITY;
    #pragma unroll
    for (int j = 0; j < 4; j++) {
        int i = threadIdx.x + j * 256;
        if (i < n) m = fmaxf(m, row[i]);
    }
    sh[threadIdx.x] = m; __syncthreads();
    for (int o2 = 128; o2; o2 >>= 1) {
        if (threadIdx.x < o2) sh[threadIdx.x] = fmaxf(sh[threadIdx.x], sh[threadIdx.x + o2]);
        __syncthreads();
    }
    m = sh[0]; __syncthreads();
    float ev[4];
    float sum = 0.f;
    #pragma unroll
    for (int j = 0; j < 4; j++) {
        int i = threadIdx.x + j * 256;
        float e = (i < n) ? expf(row[i] - m) : 0.f;
        ev[j] = e; sum += e;
    }
    sh[threadIdx.x] = sum; __syncthreads();
    for (int o2 = 128; o2; o2 >>= 1) {
        if (threadIdx.x < o2) sh[threadIdx.x] += sh[threadIdx.x + o2];
        __syncthreads();
    }
    float inv = 1.0f / sh[0];
    #pragma unroll
    for (int j = 0; j < 4; j++) {
        int i = threadIdx.x + j * 256;
        if (i >= nlim) break;
        float pv = ev[j] * inv * vs[(size_t)((b * SS + i) * KV + kvh)];
        bf16 h, l; split_bf(pv, h, l);
        ph[(size_t)r * SS + i] = h;
        pl[(size_t)r * SS + i] = l;
    }
}

// ---------------- TC AV ----------------
__global__ __launch_bounds__(256, 1) void av_tc(
    const bf16* __restrict__ ph, const bf16* __restrict__ pl,
    const bf16* __restrict__ vn, bf16* __restrict__ oh, bf16* __restrict__ ol)
{
    int z = blockIdx.z;
    int b = z >> 3, hh = z & 7, kvh = (z & 7) >> 2;
    int m0 = blockIdx.y * 128;
    int tid = threadIdx.x, wid = tid >> 5, lid = tid & 31;
    extern __shared__ char smem[];
    uint32_t sb = smem_u32(smem);

    const bf16* srcP[4]; const bf16* srcV[4];
    uint32_t dstP[4], dstV[4];
    ptrdiff_t dpl = pl - ph;
    #pragma unroll
    for (int ci = 0; ci < 4; ci++) {
        int gid = ci * 256 + tid;
        int r = (gid >> 3) & 127;
        int c8 = gid & 7;
        srcP[ci] = ph + (size_t)z * SS * SS + (size_t)(m0 + r) * SS + c8 * 8;
        dstP[ci] = swz((uint32_t)(r * 128 + c8 * 16));
        int gid2 = 2048 + gid;
        int vrow = (gid2 >> 4) & 63;
        int c16 = gid2 & 15;
        int plane = c16 >> 3, cc8 = c16 & 7;
        srcV[ci] = vn + ((size_t)(b * SS + vrow) * KV + kvh) * HDIM + plane * 64 + cc8 * 8;
        dstV[ci] = (uint32_t)(2 * TILE_BYTES + plane * 8192) + swz((uint32_t)(vrow * 128 + cc8 * 16));
    }

    int n_ch = (m0 >> 6) + 2;
    #pragma unroll 1
    for (int p = 0; p < 2 && p < n_ch; p++) {
        uint32_t base = sb + p * AV_STAGE;
        #pragma unroll
        for (int ci = 0; ci < 4; ci++) {
            size_t ko = (size_t)p * KT;
            cpa16(base + dstP[ci], srcP[ci] + ko);
            cpa16(base + TILE_BYTES + dstP[ci], srcP[ci] + dpl + ko);
            cpa16(base + dstV[ci], srcV[ci] + ko * (KV * HDIM));
        }
        cpa_commit();
    }

    int wr = (wid & 3) * 32;
    int wc = (wid >> 2) * 64;
    int vplane = wc >> 6;
    int rowm = (lid & 7) + ((lid >> 3) & 1) * 8;
    int colb = (lid >> 4) * 16;
    float acc[2][8][4] = {};

    #pragma unroll 1
    for (int kt = 0; kt < n_ch; kt++) {
        cpa_wait1();
        __syncthreads();
        if (kt + 2 < n_ch) {
            int sl = (kt + 2) % 3;
            uint32_t base = sb + sl * AV_STAGE;
            size_t ko = (size_t)(kt + 2) * KT;
            #pragma unroll
            for (int ci = 0; ci < 4; ci++) {
                cpa16(base + dstP[ci], srcP[ci] + ko);
                cpa16(base + TILE_BYTES + dstP[ci], srcP[ci] + dpl + ko);
                cpa16(base + dstV[ci], srcV[ci] + ko * (KV * HDIM));
            }
            cpa_commit();
        }
        uint32_t sbase = sb + (kt % 3) * AV_STAGE;
        uint32_t vbase = sbase + 2 * TILE_BYTES + vplane * 8192;
        #pragma unroll
        for (int s16 = 0; s16 < 4; s16++) {
            int kb0 = s16 * 32 + colb;
            uint32_t ah[2][4], al[2][4], bv[8][2];
            #pragma unroll
            for (int i = 0; i < 2; i++) {
                uint32_t off = (uint32_t)((wr + i * 16 + rowm) * 128 + kb0);
                ldsm4(sbase + swz(off), ah[i][0], ah[i][1], ah[i][2], ah[i][3]);
                ldsm4(sbase + TILE_BYTES + swz(off), al[i][0], al[i][1], al[i][2], al[i][3]);
            }
            #pragma unroll
            for (int j16 = 0; j16 < 4; j16++) {
                uint32_t krow = (uint32_t)(s16 * 16 + (lid & 7) + 8 * ((lid >> 3) & 1));
                uint32_t off = krow * 128 + (uint32_t)(j16 * 32 + 16 * (lid >> 4));
                uint32_t r0, r1, r2, r3;
                ldsm4t(vbase + swz(off), r0, r1, r2, r3);
                bv[j16 * 2][0] = r0; bv[j16 * 2][1] = r1;
                bv[j16 * 2 + 1][0] = r2; bv[j16 * 2 + 1][1] = r3;
            }
            #pragma unroll
            for (int i = 0; i < 2; i++)
                #pragma unroll
                for (int jn = 0; jn < 8; jn++) {
                    mma16816(acc[i][jn], ah[i], bv[jn]);
                    mma16816(acc[i][jn], al[i], bv[jn]);
                }
        }
    }

    #pragma unroll
    for (int i = 0; i < 2; i++)
        #pragma unroll
        for (int jn = 0; jn < 8; jn++) {
            int r0 = m0 + wr + i * 16 + (lid >> 2);
            int cc = wc + jn * 8 + (lid & 3) * 2;
            #pragma unroll
            for (int half = 0; half < 2; half++) {
                int row = r0 + half * 8;
                float v0 = acc[i][jn][half * 2 + 0];
                float v1 = acc[i][jn][half * 2 + 1];
                size_t o = ((size_t)(b * SS + row) * HH + hh) * HDIM + cc;
                bf16 h0, l0, h1, l1;
                split_bf(v0, h0, l0); split_bf(v1, h1, l1);
                oh[o] = h0; oh[o + 1] = h1;
                ol[o] = l0; ol[o + 1] = l1;
            }
        }
}

// ---------------- router (also records per-token slot ids) ----------------
__global__ __launch_bounds__(256) void router_kernel(
    const float* __restrict__ hn, const float* __restrict__ wg)
{
    int tkn = blockIdx.x;
    int w = threadIdx.x >> 5, lane = threadIdx.x & 31;
    const float* x = hn + (size_t)tkn * DD;
    const float* g = wg + (size_t)w * DD;
    float s = 0.f;
    for (int i = lane; i < DD; i += 32) s += x[i] * g[i];
    s = warp_sum(s);
    __shared__ float lg[EE];
    if (lane == 0) lg[w] = s;
    __syncthreads();
    if (threadIdx.x == 0) {
        float m = -INFINITY;
        #pragma unroll
        for (int e = 0; e < EE; e++) m = fmaxf(m, lg[e]);
        float ex[EE];
        #pragma unroll
        for (int e = 0; e < EE; e++) ex[e] = expf(lg[e] - m);
        int i1 = 0; float m1 = ex[0];
        #pragma unroll
        for (int e = 1; e < EE; e++) if (ex[e] > m1) { m1 = ex[e]; i1 = e; }
        int i2 = -1; float m2 = -1.f;
        #pragma unroll
        for (int e = 0; e < EE; e++) if (e != i1 && ex[e] > m2) { m2 = ex[e]; i2 = e; }
        float inv = 1.0f / (m1 + m2);
        int p1 = atomicAdd(&g_cnt[i1], 1);
        g_tok[i1 * TT + p1] = tkn; g_twt[i1 * TT + p1] = m1 * inv;
        int p2 = atomicAdd(&g_cnt[i2], 1);
        g_tok[i2 * TT + p2] = tkn; g_twt[i2 * TT + p2] = m2 * inv;
        g_tslot[tkn * 2 + 0] = i1 * TT + p1;
        g_tslot[tkn * 2 + 1] = i2 * TT + p2;
    }
}

// ---------------- final: out = h + w0*moeX[s0] + w1*moeX[s1] ----------------
__global__ void final_gather_kernel(const float* __restrict__ h,
                                    const float* __restrict__ moeX,
                                    const int* __restrict__ tsl,
                                    const float* __restrict__ twt,
                                    float* __restrict__ out) {
    int t = blockIdx.x;
    int s0 = tsl[t * 2], s1 = tsl[t * 2 + 1];
    float w0 = twt[s0], w1 = twt[s1];
    const float4* b0 = reinterpret_cast<const float4*>(moeX + (size_t)s0 * DD);
    const float4* b1 = reinterpret_cast<const float4*>(moeX + (size_t)s1 * DD);
    const float4* hr = reinterpret_cast<const float4*>(h + (size_t)t * DD);
    float4* o = reinterpret_cast<float4*>(out + (size_t)t * DD);
    int d = threadIdx.x;
    float4 a = hr[d], x0 = b0[d], x1 = b1[d];
    a.x += w0 * x0.x + w1 * x1.x;
    a.y += w0 * x0.y + w1 * x1.y;
    a.z += w0 * x0.z + w1 * x1.z;
    a.w += w0 * x0.w + w1 * x1.w;
    o[d] = a;
}

// ======================= host =======================
extern "C" void kernel_launch(void* const* d_in, const int* in_sizes, int n_in,
                              void* d_out, int out_size) {
    const float* hidden = (const float*)d_in[0];
    const float* w_q    = (const float*)d_in[1];
    const float* w_k    = (const float*)d_in[2];
    const float* w_v    = (const float*)d_in[3];
    const float* w_o    = (const float*)d_in[4];
    const float* g1     = (const float*)d_in[5];
    const float* g2     = (const float*)d_in[6];
    const float* w_gate = (const float*)d_in[7];
    const float* w1     = (const float*)d_in[8];
    const float* w3     = (const float*)d_in[9];
    const float* w2     = (const float*)d_in[10];
    float* out = (float*)d_out;

    bf16 *p_wqkvn, *p_won, *p_w1n, *p_w3n, *p_w2n;
    float *p_wqkvs, *p_wos, *p_w1s, *p_w3s, *p_w2s;
    bf16 *p_hnh, *p_hnl, *p_oh, *p_ol, *p_uph, *p_upl;
    bf16 *p_xnh, *p_xnl;
    bf16 *p_qh, *p_ql, *p_kh, *p_kl, *p_vn, *p_ph, *p_pl;
    float *p_qkv, *p_vs, *p_sc, *p_h, *p_hn, *p_moeX, *p_twt;
    int *p_cnt, *p_tok, *p_tslot;
    cudaGetSymbolAddress((void**)&p_wqkvn, g_wqkvn); cudaGetSymbolAddress((void**)&p_wqkvs, g_wqkvs);
    cudaGetSymbolAddress((void**)&p_won, g_won); cudaGetSymbolAddress((void**)&p_wos, g_wos);
    cudaGetSymbolAddress((void**)&p_w1n, g_w1n); cudaGetSymbolAddress((void**)&p_w1s, g_w1s);
    cudaGetSymbolAddress((void**)&p_w3n, g_w3n); cudaGetSymbolAddress((void**)&p_w3s, g_w3s);
    cudaGetSymbolAddress((void**)&p_w2n, g_w2n); cudaGetSymbolAddress((void**)&p_w2s, g_w2s);
    cudaGetSymbolAddress((void**)&p_xnh, g_xnh); cudaGetSymbolAddress((void**)&p_xnl, g_xnl);
    cudaGetSymbolAddress((void**)&p_hnh, g_hnh); cudaGetSymbolAddress((void**)&p_hnl, g_hnl);
    cudaGetSymbolAddress((void**)&p_oh, g_oh);   cudaGetSymbolAddress((void**)&p_ol, g_ol);
    cudaGetSymbolAddress((void**)&p_uph, g_uph); cudaGetSymbolAddress((void**)&p_upl, g_upl);
    cudaGetSymbolAddress((void**)&p_qkv, g_qkv);
    cudaGetSymbolAddress((void**)&p_qh, g_qh);   cudaGetSymbolAddress((void**)&p_ql, g_ql);
    cudaGetSymbolAddress((void**)&p_kh, g_kh);   cudaGetSymbolAddress((void**)&p_kl, g_kl);
    cudaGetSymbolAddress((void**)&p_vn, g_vn);   cudaGetSymbolAddress((void**)&p_vs, g_vs);
    cudaGetSymbolAddress((void**)&p_sc, g_sc);
    cudaGetSymbolAddress((void**)&p_ph, g_ph);   cudaGetSymbolAddress((void**)&p_pl, g_pl);
    cudaGetSymbolAddress((void**)&p_h, g_h);     cudaGetSymbolAddress((void**)&p_hn, g_hn);
    cudaGetSymbolAddress((void**)&p_moeX, g_moeX);
    cudaGetSymbolAddress((void**)&p_cnt, g_cnt); cudaGetSymbolAddress((void**)&p_tok, g_tok);
    cudaGetSymbolAddress((void**)&p_twt, g_twt); cudaGetSymbolAddress((void**)&p_tslot, g_tslot);

    cudaFuncSetAttribute(gemm_tc<0>, cudaFuncAttributeMaxDynamicSharedMemorySize, SMEM_SZ);
    cudaFuncSetAttribute(gemm_tc<1>, cudaFuncAttributeMaxDynamicSharedMemorySize, SMEM_SZ);
    cudaFuncSetAttribute(gemm_tc<5>, cudaFuncAttributeMaxDynamicSharedMemorySize, SMEM_SZ);
    cudaFuncSetAttribute(gemm_w13, cudaFuncAttributeMaxDynamicSharedMemorySize, W13_SMEM);
    cudaFuncSetAttribute(scores_tc, cudaFuncAttributeMaxDynamicSharedMemorySize, SCR_SMEM);
    cudaFuncSetAttribute(av_tc, cudaFuncAttributeMaxDynamicSharedMemorySize, AV_SMEM);

    static cudaStream_t s2 = nullptr;
    static cudaEvent_t ev_fork = nullptr, ev_join = nullptr;
    if (!s2) {
        cudaStreamCreateWithFlags(&s2, cudaStreamNonBlocking);
        cudaEventCreateWithFlags(&ev_fork, cudaEventDisableTiming);
        cudaEventCreateWithFlags(&ev_join, cudaEventDisableTiming);
    }

    zero_cnt_kernel<<<1, 32>>>(p_cnt);

    // fork: fused big MoE weight quants on s2 (grid.z selects w1/w3/w2)
    const int NG_BIG = EE * FFND * DD / 128;
    cudaEventRecord(ev_fork, 0);
    cudaStreamWaitEvent(s2, ev_fork, 0);
    quantw3_kernel<<<dim3(NG_BIG / 16, 1, 3), 256, 0, s2>>>(
        w1, w3, w2, p_w1n, p_w3n, p_w2n, p_w1s, p_w3s, p_w2s, NG_BIG);
    cudaEventRecord(ev_join, s2);

    quantw_kernel<<<DD * DD / 128 / 16, 256>>>(w_q, p_wqkvn, p_wqkvs, DD * DD / 128);
    quantw_kernel<<<KV * HDIM * DD / 128 / 16, 256>>>(w_k, p_wqkvn + 1024 * DD,
        p_wqkvs + 1024 * 8, KV * HDIM * DD / 128);
    quantw_kernel<<<KV * HDIM * DD / 128 / 16, 256>>>(w_v, p_wqkvn + 1280 * DD,
        p_wqkvs + 1280 * 8, KV * HDIM * DD / 128);
    quantw_kernel<<<DD * DD / 128 / 16, 256>>>(w_o, p_won, p_wos, DD * DD / 128);

    // ---- attention ----
    rms_split_kernel<false><<<TT, 256>>>(hidden, g1, nullptr, p_xnh, p_xnl);
    gemm_tc<0><<<dim3(12, 16, 1), 256, SMEM_SZ>>>(p_xnh, p_xnl, DD, 0,
        p_wqkvn, p_wqkvs, DD, 0, 0,
        p_qkv, NQKV, 0, TT, nullptr, DD, nullptr);
    kvprep_kernel<<<TT * (HH + KV + KV), HDIM>>>(p_qkv, p_qh, p_ql, p_kh, p_kl, p_vn, p_vs);
    scores_tc<<<dim3(8, 8, BB * HH), 256, SCR_SMEM>>>(p_qh, p_ql, p_kh, p_kl, p_sc);
    softmax_kernel<<<BB * HH * SS, 256>>>(p_sc, p_vs, p_ph, p_pl);
    av_tc<<<dim3(1, 8, BB * HH), 256, AV_SMEM>>>(p_ph, p_pl, p_vn, p_oh, p_ol);
    gemm_tc<1><<<dim3(8, 16, 1), 256, SMEM_SZ>>>(p_oh, p_ol, DD, 0,
        p_won, p_wos, DD, 0, 0,
        p_h, DD, 0, TT, nullptr, DD, hidden);

    // ---- MoE ----
    rms_split_kernel<true><<<TT, 256>>>(p_h, g2, p_hn, p_hnh, p_hnl);
    router_kernel<<<TT, 256>>>(p_hn, w_gate);
    cudaStreamWaitEvent(0, ev_join, 0);
    gemm_w13<<<dim3(28, 16, EE), 256, W13_SMEM>>>(p_hnh, p_hnl, DD,
        p_w1n, p_w1s, p_w3n, p_w3s, DD, (size_t)FFND * DD, (size_t)FFND * 8,
        p_uph, p_upl, FFND, (size_t)TT * FFND,
        p_cnt, DD, p_tok);
    gemm_tc<5><<<dim3(8, 16, EE), 256, SMEM_SZ>>>(p_uph, p_upl, FFND, (size_t)TT * FFND,
        p_w2n, p_w2s, FFND, (size_t)DD * FFND, (size_t)DD * 28,
        p_moeX, DD, (size_t)TT * DD,
        0, p_cnt, FFND, nullptr);
    final_gather_kernel<<<TT, 256>>>(p_h, p_moeX, p_tslot, p_twt, out);
}

// round 17
// speedup vs baseline: 2.4133x; 1.1573x over previous
#include <cuda_runtime.h>
#include <cuda_bf16.h>
#include <cuda_fp16.h>
#include <math.h>
#include <stdint.h>

#define BB 2
#define SS 1024
#define TT 2048
#define DD 1024
#define HH 8
#define KV 2
#define HDIM 128
#define EE 8
#define FFND 3584
#define NQKV 1536

#define KT 64
#define STAGES 4
#define TILE_BYTES 16384
#define STAGE_BYTES (3 * TILE_BYTES)
#define SC_OFF (STAGES * STAGE_BYTES)
#define SMEM_SZ (SC_OFF + 28 * 128 * 4)
#define SCR_SMEM (2 * 4 * TILE_BYTES)
#define AV_STAGE (3 * TILE_BYTES)
#define AV_SMEM (3 * AV_STAGE)
// w13 fused kernel
#define W13_STAGES 3
#define W13_SC_OFF (W13_STAGES * STAGE_BYTES)
#define W13_ACC_OFF (W13_SC_OFF + 2 * 8 * 128 * 4)
#define W13_SMEM (W13_ACC_OFF + 256 * 64 * 4)
// w2 fp16-single kernel: 4 stages x 2 tiles
#define W2_STAGES 4
#define W2_STAGE_B (2 * TILE_BYTES)
#define W2_SC_OFF (W2_STAGES * W2_STAGE_B)
#define W2_SMEM (W2_SC_OFF + 28 * 128 * 4)

typedef __nv_bfloat16 bf16;
typedef __half f16;

// weights: integer + per-group fp32 scale
__device__ bf16  g_wqkvn[NQKV * DD];       __device__ float g_wqkvs[NQKV * DD / 128];
__device__ bf16  g_won[DD * DD];           __device__ float g_wos[DD * DD / 128];
__device__ bf16  g_w1n[EE * FFND * DD];    __device__ float g_w1s[EE * FFND * DD / 128];
__device__ bf16  g_w3n[EE * FFND * DD];    __device__ float g_w3s[EE * FFND * DD / 128];
__device__ f16   g_w2n[EE * DD * FFND];    __device__ float g_w2s[EE * DD * FFND / 128];
// activations
__device__ bf16 g_xnh[TT * DD];        __device__ bf16 g_xnl[TT * DD];
__device__ bf16 g_hnh[TT * DD];        __device__ bf16 g_hnl[TT * DD];
__device__ bf16 g_oh[TT * DD];         __device__ bf16 g_ol[TT * DD];
__device__ f16  g_upf[EE * TT * FFND];
__device__ float g_qkv[TT * NQKV];
__device__ bf16 g_qh[TT * DD];         __device__ bf16 g_ql[TT * DD];
__device__ bf16 g_kh[TT * KV * HDIM];  __device__ bf16 g_kl[TT * KV * HDIM];
__device__ bf16 g_vn[TT * KV * HDIM];  __device__ float g_vs[TT * KV];
__device__ float g_sc[BB * HH * SS * SS];
__device__ bf16 g_ph[BB * HH * SS * SS];
__device__ bf16 g_pl[BB * HH * SS * SS];
__device__ float g_h[TT * DD];
__device__ float g_hn[TT * DD];
__device__ float g_moeX[EE * TT * DD];
__device__ int   g_cnt[EE];
__device__ int   g_tok[EE * TT];
__device__ float g_twt[EE * TT];
__device__ int   g_tslot[TT * 2];

// ---------------- ptx helpers ----------------
__device__ __forceinline__ uint32_t smem_u32(const void* p) {
    uint32_t a;
    asm("{ .reg .u64 t; cvta.to.shared.u64 t, %1; cvt.u32.u64 %0, t; }" : "=r"(a) : "l"(p));
    return a;
}
__device__ __forceinline__ void ldsm4(uint32_t a, uint32_t& r0, uint32_t& r1,
                                      uint32_t& r2, uint32_t& r3) {
    asm volatile("ldmatrix.sync.aligned.m8n8.x4.shared.b16 {%0,%1,%2,%3}, [%4];"
                 : "=r"(r0), "=r"(r1), "=r"(r2), "=r"(r3) : "r"(a));
}
__device__ __forceinline__ void ldsm4t(uint32_t a, uint32_t& r0, uint32_t& r1,
                                       uint32_t& r2, uint32_t& r3) {
    asm volatile("ldmatrix.sync.aligned.m8n8.x4.trans.shared.b16 {%0,%1,%2,%3}, [%4];"
                 : "=r"(r0), "=r"(r1), "=r"(r2), "=r"(r3) : "r"(a));
}
__device__ __forceinline__ void mma16816(float* c, const uint32_t* a, const uint32_t* b) {
    asm volatile("mma.sync.aligned.m16n8k16.row.col.f32.bf16.bf16.f32 "
                 "{%0,%1,%2,%3}, {%4,%5,%6,%7}, {%8,%9}, {%0,%1,%2,%3};"
                 : "+f"(c[0]), "+f"(c[1]), "+f"(c[2]), "+f"(c[3])
                 : "r"(a[0]), "r"(a[1]), "r"(a[2]), "r"(a[3]), "r"(b[0]), "r"(b[1]));
}
__device__ __forceinline__ void mma_fp16(float* c, const uint32_t* a, const uint32_t* b) {
    asm volatile("mma.sync.aligned.m16n8k16.row.col.f32.f16.f16.f32 "
                 "{%0,%1,%2,%3}, {%4,%5,%6,%7}, {%8,%9}, {%0,%1,%2,%3};"
                 : "+f"(c[0]), "+f"(c[1]), "+f"(c[2]), "+f"(c[3])
                 : "r"(a[0]), "r"(a[1]), "r"(a[2]), "r"(a[3]), "r"(b[0]), "r"(b[1]));
}
__device__ __forceinline__ void cpa16(uint32_t dst, const void* src) {
    asm volatile("cp.async.cg.shared.global [%0], [%1], 16;" :: "r"(dst), "l"(src));
}
__device__ __forceinline__ void cpa_commit() { asm volatile("cp.async.commit_group;" ::: "memory"); }
__device__ __forceinline__ void cpa_wait0() { asm volatile("cp.async.wait_group 0;" ::: "memory"); }
__device__ __forceinline__ void cpa_wait1() { asm volatile("cp.async.wait_group 1;" ::: "memory"); }
__device__ __forceinline__ void cpa_wait2() { asm volatile("cp.async.wait_group 2;" ::: "memory"); }

__device__ __forceinline__ float warp_sum(float v) {
    #pragma unroll
    for (int o = 16; o; o >>= 1) v += __shfl_xor_sync(0xffffffffu, v, o);
    return v;
}
__device__ __forceinline__ void split_bf(float v, bf16& h, bf16& l) {
    h = __float2bfloat16(v);
    l = __float2bfloat16(v - __bfloat162float(h));
}
__device__ __forceinline__ uint32_t swz(uint32_t off) { return off ^ ((off >> 3) & 0x70); }

__device__ __forceinline__ uint32_t pack2f(float a, float b, bf16*) {
    __nv_bfloat162 t = __floats2bfloat162_rn(a, b);
    return *reinterpret_cast<uint32_t*>(&t);
}
__device__ __forceinline__ uint32_t pack2f(float a, float b, f16*) {
    __half2 t = __floats2half2_rn(a, b);
    return *reinterpret_cast<uint32_t*>(&t);
}

// ---------------- small kernels ----------------
__global__ void zero_cnt_kernel(int* __restrict__ cnt) {
    if (threadIdx.x < EE) cnt[threadIdx.x] = 0;
}

template<typename T>
__device__ __forceinline__ void quant_group(const float* __restrict__ w,
                                            T* __restrict__ nq,
                                            float* __restrict__ sc,
                                            int g, int l16) {
    const float4* src = reinterpret_cast<const float4*>(w) + (size_t)g * 32 + l16 * 2;
    float4 v0 = src[0], v1 = src[1];
    float mn = fminf(fminf(fminf(v0.x, v0.y), fminf(v0.z, v0.w)),
                     fminf(fminf(v1.x, v1.y), fminf(v1.z, v1.w)));
    float mx = fmaxf(fmaxf(fmaxf(v0.x, v0.y), fmaxf(v0.z, v0.w)),
                     fmaxf(fmaxf(v1.x, v1.y), fmaxf(v1.z, v1.w)));
    #pragma unroll
    for (int o = 8; o; o >>= 1) {
        mn = fminf(mn, __shfl_xor_sync(0xffffffffu, mn, o, 16));
        mx = fmaxf(mx, __shfl_xor_sync(0xffffffffu, mx, o, 16));
    }
    float scale = fmaxf(mx - mn, 1e-5f) / 15.0f;
    float sinv = 1.0f / scale;
    float base = fminf(fmaxf(rintf(-mn * sinv), 0.f), 15.f);
    float qmin = -base, qmax = 15.0f - base;
    float q[8];
    q[0] = v0.x; q[1] = v0.y; q[2] = v0.z; q[3] = v0.w;
    q[4] = v1.x; q[5] = v1.y; q[6] = v1.z; q[7] = v1.w;
    #pragma unroll
    for (int j = 0; j < 8; j++)
        q[j] = fminf(fmaxf(rintf(q[j] * sinv), qmin), qmax);
    uint32_t p[4];
    #pragma unroll
    for (int j = 0; j < 4; j++)
        p[j] = pack2f(q[2 * j], q[2 * j + 1], (T*)nullptr);
    *reinterpret_cast<uint4*>(nq + (size_t)g * 128 + l16 * 8) =
        *reinterpret_cast<uint4*>(p);
    if (l16 == 0) sc[g] = scale;
}

__global__ void quantw_kernel(const float* __restrict__ w, bf16* __restrict__ nq,
                              float* __restrict__ sc, int ngroups) {
    int g = blockIdx.x * 16 + (threadIdx.x >> 4);
    if (g >= ngroups) return;
    quant_group<bf16>(w, nq, sc, g, threadIdx.x & 15);
}

// fused 3-tensor quant: w1/w3 -> bf16, w2 -> fp16 (grid.z selects)
__global__ void quantw3_kernel(const float* __restrict__ wa, const float* __restrict__ wb,
                               const float* __restrict__ wc,
                               bf16* __restrict__ na, bf16* __restrict__ nb,
                               f16* __restrict__ nc,
                               float* __restrict__ sa, float* __restrict__ sb,
                               float* __restrict__ scc, int ngroups) {
    int g = blockIdx.x * 16 + (threadIdx.x >> 4);
    if (g >= ngroups) return;
    int l16 = threadIdx.x & 15;
    if (blockIdx.z == 0)      quant_group<bf16>(wa, na, sa, g, l16);
    else if (blockIdx.z == 1) quant_group<bf16>(wb, nb, sb, g, l16);
    else                      quant_group<f16>(wc, nc, scc, g, l16);
}

template<bool WF32>
__global__ void rms_split_kernel(const float* __restrict__ x, const float* __restrict__ g,
                                 float* __restrict__ f32o, bf16* __restrict__ hi,
                                 bf16* __restrict__ lo) {
    int row = blockIdx.x;
    const float* xr = x + (size_t)row * DD;
    float s = 0.f;
    for (int i = threadIdx.x; i < DD; i += 256) { float v = xr[i]; s += v * v; }
    __shared__ float sh[256];
    sh[threadIdx.x] = s; __syncthreads();
    for (int o2 = 128; o2; o2 >>= 1) {
        if (threadIdx.x < o2) sh[threadIdx.x] += sh[threadIdx.x + o2];
        __syncthreads();
    }
    float inv = rsqrtf(sh[0] * (1.0f / DD) + 1e-5f);
    for (int i = threadIdx.x; i < DD; i += 256) {
        float v = xr[i] * inv * g[i];
        if (WF32) f32o[(size_t)row * DD + i] = v;
        bf16 h, l; split_bf(v, h, l);
        hi[(size_t)row * DD + i] = h;
        lo[(size_t)row * DD + i] = l;
    }
}

// ===== bf16x2 mma.sync GEMM (exact integer weights + per-group rescale) =====
// MODE 0 store f32 | 1 +resid
template<int MODE>
__global__ __launch_bounds__(256, 1) void gemm_tc(
    const bf16* __restrict__ Ahi, const bf16* __restrict__ Alo, int lda,
    const bf16* __restrict__ Bn, const float* __restrict__ Bsc, int ldb,
    float* __restrict__ C, int ldc,
    int M, int K, const float* __restrict__ resid)
{
    int m0 = blockIdx.y * 128;
    if (m0 >= M) return;
    int n0 = blockIdx.x * 128;
    int tid = threadIdx.x;
    int wid = tid >> 5, lid = tid & 31;

    extern __shared__ char smem[];
    uint32_t sb = smem_u32(smem);
    float* scs = reinterpret_cast<float*>(smem + SC_OFF);
    int G = K >> 7;

    for (int i = tid; i < G * 128; i += 256) {
        int g = i >> 7, c = i & 127;
        scs[i] = Bsc[(size_t)(n0 + c) * G + g];
    }

    const bf16* srcA[4]; const bf16* srcB[4];
    uint32_t dstA[4], dstB[4];
    ptrdiff_t dlo = Alo - Ahi;
    #pragma unroll
    for (int ci = 0; ci < 4; ci++) {
        int gid = ci * 256 + tid;
        int r = (gid >> 3) & 127;
        int c8 = gid & 7;
        int row = m0 + r;
        if (row >= M) row = m0;
        srcA[ci] = Ahi + (size_t)row * lda + c8 * 8;
        dstA[ci] = swz((uint32_t)(r * 128 + c8 * 16));
        int gid2 = 2048 + gid;
        int r2 = (gid2 >> 3) & 127;
        int c82 = gid2 & 7;
        srcB[ci] = Bn + (size_t)(n0 + r2) * ldb + c82 * 8;
        dstB[ci] = (uint32_t)(2 * TILE_BYTES) + swz((uint32_t)(r2 * 128 + c82 * 16));
    }

    int n_kt = K / KT;
    int npro = STAGES - 1; if (npro > n_kt) npro = n_kt;
    #pragma unroll 1
    for (int p = 0; p < npro; p++) {
        uint32_t base = sb + p * STAGE_BYTES;
        size_t ko = (size_t)p * KT;
        #pragma unroll
        for (int ci = 0; ci < 4; ci++) {
            cpa16(base + dstA[ci], srcA[ci] + ko);
            cpa16(base + TILE_BYTES + dstA[ci], srcA[ci] + dlo + ko);
            cpa16(base + dstB[ci], srcB[ci] + ko);
        }
        cpa_commit();
    }

    int wr = (wid & 3) * 32;
    int wc = (wid >> 2) * 64;
    int rowm = (lid & 7) + ((lid >> 3) & 1) * 8;
    int colb = (lid >> 4) * 16;

    float acc[2][8][4] = {};
    float accg[2][8][4] = {};

    #pragma unroll 1
    for (int kt = 0; kt < n_kt; kt++) {
        int pending = n_kt - kt - 1; if (pending > STAGES - 2) pending = STAGES - 2;
        if (pending >= 2) cpa_wait2();
        else if (pending == 1) cpa_wait1();
        else cpa_wait0();
        __syncthreads();
        if (kt + STAGES - 1 < n_kt) {
            int sl = (kt + STAGES - 1) % STAGES;
            uint32_t base = sb + sl * STAGE_BYTES;
            size_t ko = (size_t)(kt + STAGES - 1) * KT;
            #pragma unroll
            for (int ci = 0; ci < 4; ci++) {
                cpa16(base + dstA[ci], srcA[ci] + ko);
                cpa16(base + TILE_BYTES + dstA[ci], srcA[ci] + dlo + ko);
                cpa16(base + dstB[ci], srcB[ci] + ko);
            }
            cpa_commit();
        }
        uint32_t sbase = sb + (kt % STAGES) * STAGE_BYTES;
        #pragma unroll
        for (int s16 = 0; s16 < 4; s16++) {
            int kb0 = s16 * 32 + colb;
            uint32_t ah[2][4], al[2][4], bn[8][2];
            #pragma unroll
            for (int i = 0; i < 2; i++) {
                uint32_t off = (uint32_t)((wr + i * 16 + rowm) * 128 + kb0);
                ldsm4(sbase + swz(off), ah[i][0], ah[i][1], ah[i][2], ah[i][3]);
                ldsm4(sbase + TILE_BYTES + swz(off), al[i][0], al[i][1], al[i][2], al[i][3]);
            }
            #pragma unroll
            for (int j = 0; j < 4; j++) {
                uint32_t off = (uint32_t)((wc + j * 16 + rowm) * 128 + kb0);
                uint32_t r0, r1, r2, r3;
                ldsm4(sbase + 2 * TILE_BYTES + swz(off), r0, r1, r2, r3);
                bn[j * 2][0] = r0; bn[j * 2][1] = r2;
                bn[j * 2 + 1][0] = r1; bn[j * 2 + 1][1] = r3;
            }
            #pragma unroll
            for (int i = 0; i < 2; i++)
                #pragma unroll
                for (int jn = 0; jn < 8; jn++) {
                    mma16816(accg[i][jn], ah[i], bn[jn]);
                    mma16816(accg[i][jn], al[i], bn[jn]);
                }
        }
        if (kt & 1) {
            int g = kt >> 1;
            #pragma unroll
            for (int jn = 0; jn < 8; jn++) {
                int c = wc + jn * 8 + (lid & 3) * 2;
                float s0 = scs[g * 128 + c];
                float s1 = scs[g * 128 + c + 1];
                #pragma unroll
                for (int i = 0; i < 2; i++) {
                    acc[i][jn][0] += s0 * accg[i][jn][0];
                    acc[i][jn][1] += s1 * accg[i][jn][1];
                    acc[i][jn][2] += s0 * accg[i][jn][2];
                    acc[i][jn][3] += s1 * accg[i][jn][3];
                    accg[i][jn][0] = 0.f; accg[i][jn][1] = 0.f;
                    accg[i][jn][2] = 0.f; accg[i][jn][3] = 0.f;
                }
            }
        }
    }

    #pragma unroll
    for (int i = 0; i < 2; i++) {
        #pragma unroll
        for (int jn = 0; jn < 8; jn++) {
            int r0 = m0 + wr + i * 16 + (lid >> 2);
            int cc = n0 + wc + jn * 8 + (lid & 3) * 2;
            #pragma unroll
            for (int half = 0; half < 2; half++) {
                int row = r0 + half * 8;
                if (row >= M) continue;
                float v0 = acc[i][jn][half * 2 + 0];
                float v1 = acc[i][jn][half * 2 + 1];
                if (MODE == 1) {
                    const float* rr = resid + (size_t)row * ldc + cc;
                    v0 += rr[0]; v1 += rr[1];
                }
                *reinterpret_cast<float2*>(C + (size_t)row * ldc + cc) = make_float2(v0, v1);
            }
        }
    }
}

// ===== fused w1+w3 GEMM; epilogue silu(acc1)*acc3 -> fp16 upf =====
__global__ __launch_bounds__(256, 1) void gemm_w13(
    const bf16* __restrict__ Ahi, const bf16* __restrict__ Alo, int lda,
    const bf16* __restrict__ B1, const float* __restrict__ S1,
    const bf16* __restrict__ B3, const float* __restrict__ S3,
    int ldb, size_t strideB, size_t strideBs,
    f16* __restrict__ CF, int ldc, size_t strideC,
    const int* __restrict__ Mptr, int K, const int* __restrict__ idx)
{
    int z = blockIdx.z;
    int M = Mptr[z];
    int m0 = blockIdx.y * 128;
    if (m0 >= M) return;
    int n0 = blockIdx.x * 128;
    int tid = threadIdx.x;
    int wid = tid >> 5, lid = tid & 31;

    extern __shared__ char smem[];
    uint32_t sb = smem_u32(smem);
    float* scs = reinterpret_cast<float*>(smem + W13_SC_OFF);
    float* accs = reinterpret_cast<float*>(smem + W13_ACC_OFF);
    const int* idxz = idx + (size_t)z * TT;
    int G = K >> 7;

    for (int i = tid; i < G * 128; i += 256) {
        int g = i >> 7, c = i & 127;
        scs[i] = S1[strideBs * z + (size_t)(n0 + c) * G + g];
        scs[G * 128 + i] = S3[strideBs * z + (size_t)(n0 + c) * G + g];
    }

    const bf16* srcA[4];
    uint32_t dstA[4], dstB[4];
    int bRow[4], bC8[4];
    ptrdiff_t dlo = Alo - Ahi;
    #pragma unroll
    for (int ci = 0; ci < 4; ci++) {
        int gid = ci * 256 + tid;
        int r = (gid >> 3) & 127;
        int c8 = gid & 7;
        int row = m0 + r;
        if (row >= M) row = m0;
        int rg = idxz[row];
        srcA[ci] = Ahi + (size_t)rg * lda + c8 * 8;
        dstA[ci] = swz((uint32_t)(r * 128 + c8 * 16));
        int gid2 = 2048 + gid;
        int r2 = (gid2 >> 3) & 127;
        int c82 = gid2 & 7;
        bRow[ci] = n0 + r2; bC8[ci] = c82;
        dstB[ci] = (uint32_t)(2 * TILE_BYTES) + swz((uint32_t)(r2 * 128 + c82 * 16));
    }

    int wr = (wid & 3) * 32;
    int wc = (wid >> 2) * 64;
    int rowm = (lid & 7) + ((lid >> 3) & 1) * 8;
    int colb = (lid >> 4) * 16;
    int n_kt = K / KT;

    float acc[2][8][4];
    float accg[2][8][4] = {};

    #pragma unroll 1
    for (int p13 = 0; p13 < 2; p13++) {
        const bf16* Bbase = p13 ? B3 : B1;
        const bf16* srcB[4];
        #pragma unroll
        for (int ci = 0; ci < 4; ci++)
            srcB[ci] = Bbase + strideB * (size_t)z + (size_t)bRow[ci] * ldb + bC8[ci] * 8;
        if (p13) __syncthreads();

        #pragma unroll
        for (int i = 0; i < 2; i++)
            #pragma unroll
            for (int jn = 0; jn < 8; jn++)
                #pragma unroll
                for (int q = 0; q < 4; q++) acc[i][jn][q] = 0.f;

        int npro = W13_STAGES - 1; if (npro > n_kt) npro = n_kt;
        #pragma unroll 1
        for (int p = 0; p < npro; p++) {
            uint32_t base = sb + p * STAGE_BYTES;
            size_t ko = (size_t)p * KT;
            #pragma unroll
            for (int ci = 0; ci < 4; ci++) {
                cpa16(base + dstA[ci], srcA[ci] + ko);
                cpa16(base + TILE_BYTES + dstA[ci], srcA[ci] + dlo + ko);
                cpa16(base + dstB[ci], srcB[ci] + ko);
            }
            cpa_commit();
        }

        #pragma unroll 1
        for (int kt = 0; kt < n_kt; kt++) {
            int pending = n_kt - kt - 1;
            if (pending > W13_STAGES - 2) pending = W13_STAGES - 2;
            if (pending >= 1) cpa_wait1();
            else cpa_wait0();
            __syncthreads();
            if (kt + W13_STAGES - 1 < n_kt) {
                int sl = (kt + W13_STAGES - 1) % W13_STAGES;
                uint32_t base = sb + sl * STAGE_BYTES;
                size_t ko = (size_t)(kt + W13_STAGES - 1) * KT;
                #pragma unroll
                for (int ci = 0; ci < 4; ci++) {
                    cpa16(base + dstA[ci], srcA[ci] + ko);
                    cpa16(base + TILE_BYTES + dstA[ci], srcA[ci] + dlo + ko);
                    cpa16(base + dstB[ci], srcB[ci] + ko);
                }
                cpa_commit();
            }
            uint32_t sbase = sb + (kt % W13_STAGES) * STAGE_BYTES;
            #pragma unroll
            for (int s16 = 0; s16 < 4; s16++) {
                int kb0 = s16 * 32 + colb;
                uint32_t ah[2][4], al[2][4], bn[8][2];
                #pragma unroll
                for (int i = 0; i < 2; i++) {
                    uint32_t off = (uint32_t)((wr + i * 16 + rowm) * 128 + kb0);
                    ldsm4(sbase + swz(off), ah[i][0], ah[i][1], ah[i][2], ah[i][3]);
                    ldsm4(sbase + TILE_BYTES + swz(off), al[i][0], al[i][1], al[i][2], al[i][3]);
                }
                #pragma unroll
                for (int j = 0; j < 4; j++) {
                    uint32_t off = (uint32_t)((wc + j * 16 + rowm) * 128 + kb0);
                    uint32_t r0, r1, r2, r3;
                    ldsm4(sbase + 2 * TILE_BYTES + swz(off), r0, r1, r2, r3);
                    bn[j * 2][0] = r0; bn[j * 2][1] = r2;
                    bn[j * 2 + 1][0] = r1; bn[j * 2 + 1][1] = r3;
                }
                #pragma unroll
                for (int i = 0; i < 2; i++)
                    #pragma unroll
                    for (int jn = 0; jn < 8; jn++) {
                        mma16816(accg[i][jn], ah[i], bn[jn]);
                        mma16816(accg[i][jn], al[i], bn[jn]);
                    }
            }
            if (kt & 1) {
                int g = kt >> 1;
                const float* scp = scs + p13 * (G * 128);
                #pragma unroll
                for (int jn = 0; jn < 8; jn++) {
                    int c = wc + jn * 8 + (lid & 3) * 2;
                    float s0 = scp[g * 128 + c];
                    float s1 = scp[g * 128 + c + 1];
                    #pragma unroll
                    for (int i = 0; i < 2; i++) {
                        acc[i][jn][0] += s0 * accg[i][jn][0];
                        acc[i][jn][1] += s1 * accg[i][jn][1];
                        acc[i][jn][2] += s0 * accg[i][jn][2];
                        acc[i][jn][3] += s1 * accg[i][jn][3];
                        accg[i][jn][0] = 0.f; accg[i][jn][1] = 0.f;
                        accg[i][jn][2] = 0.f; accg[i][jn][3] = 0.f;
                    }
                }
            }
        }

        if (p13 == 0) {
            #pragma unroll
            for (int i = 0; i < 2; i++)
                #pragma unroll
                for (int jn = 0; jn < 8; jn++)
                    #pragma unroll
                    for (int q = 0; q < 4; q++)
                        accs[((i * 8 + jn) * 4 + q) * 256 + tid] = acc[i][jn][q];
        }
    }

    // epilogue: gv = silu(w1) * w3 -> fp16 single
    #pragma unroll
    for (int i = 0; i < 2; i++) {
        #pragma unroll
        for (int jn = 0; jn < 8; jn++) {
            int r0 = m0 + wr + i * 16 + (lid >> 2);
            int cc = n0 + wc + jn * 8 + (lid & 3) * 2;
            #pragma unroll
            for (int half = 0; half < 2; half++) {
                int row = r0 + half * 8;
                if (row >= M) continue;
                float a0 = accs[((i * 8 + jn) * 4 + half * 2 + 0) * 256 + tid];
                float a1 = accs[((i * 8 + jn) * 4 + half * 2 + 1) * 256 + tid];
                float v0 = acc[i][jn][half * 2 + 0];
                float v1 = acc[i][jn][half * 2 + 1];
                float gv0 = (a0 / (1.f + expf(-a0))) * v0;
                float gv1 = (a1 / (1.f + expf(-a1))) * v1;
                size_t o = strideC * z + (size_t)row * ldc + cc;
                __half2 hv = __floats2half2_rn(gv0, gv1);
                *reinterpret_cast<__half2*>(CF + o) = hv;
            }
        }
    }
}

// ===== w2 GEMM: fp16 single-A (1 MMA per k16), fp16 integer weights =====
__global__ __launch_bounds__(256, 1) void gemm_w2(
    const f16* __restrict__ A, int lda, size_t strideA,
    const f16* __restrict__ Bn, const float* __restrict__ Bsc, int ldb,
    size_t strideB, size_t strideBs,
    float* __restrict__ C, int ldc, size_t strideC,
    const int* __restrict__ Mptr, int K)
{
    int z = blockIdx.z;
    int M = Mptr[z];
    int m0 = blockIdx.y * 128;
    if (m0 >= M) return;
    int n0 = blockIdx.x * 128;
    int tid = threadIdx.x;
    int wid = tid >> 5, lid = tid & 31;

    extern __shared__ char smem[];
    uint32_t sb = smem_u32(smem);
    float* scs = reinterpret_cast<float*>(smem + W2_SC_OFF);
    int G = K >> 7;  // 28

    for (int i = tid; i < G * 128; i += 256) {
        int g = i >> 7, c = i & 127;
        scs[i] = Bsc[strideBs * z + (size_t)(n0 + c) * G + g];
    }

    const f16* srcA[4]; const f16* srcB[4];
    uint32_t dstA[4], dstB[4];
    #pragma unroll
    for (int ci = 0; ci < 4; ci++) {
        int gid = ci * 256 + tid;      // A: 1024 chunks
        int r = (gid >> 3) & 127;
        int c8 = gid & 7;
        int row = m0 + r;
        if (row >= M) row = m0;
        srcA[ci] = A + strideA * (size_t)z + (size_t)row * lda + c8 * 8;
        dstA[ci] = swz((uint32_t)(r * 128 + c8 * 16));
        int gid2 = 1024 + gid;         // B: next 1024 chunks
        int r2 = (gid2 >> 3) & 127;
        int c82 = gid2 & 7;
        srcB[ci] = Bn + strideB * (size_t)z + (size_t)(n0 + r2) * ldb + c82 * 8;
        dstB[ci] = (uint32_t)TILE_BYTES + swz((uint32_t)(r2 * 128 + c82 * 16));
    }

    int n_kt = K / KT;  // 56
    int npro = W2_STAGES - 1; if (npro > n_kt) npro = n_kt;
    #pragma unroll 1
    for (int p = 0; p < npro; p++) {
        uint32_t base = sb + p * W2_STAGE_B;
        size_t ko = (size_t)p * KT;
        #pragma unroll
        for (int ci = 0; ci < 4; ci++) {
            cpa16(base + dstA[ci], srcA[ci] + ko);
            cpa16(base + dstB[ci], srcB[ci] + ko);
        }
        cpa_commit();
    }

    int wr = (wid & 3) * 32;
    int wc = (wid >> 2) * 64;
    int rowm = (lid & 7) + ((lid >> 3) & 1) * 8;
    int colb = (lid >> 4) * 16;

    float acc[2][8][4] = {};
    float accg[2][8][4] = {};

    #pragma unroll 1
    for (int kt = 0; kt < n_kt; kt++) {
        int pending = n_kt - kt - 1; if (pending > W2_STAGES - 2) pending = W2_STAGES - 2;
        if (pending >= 2) cpa_wait2();
        else if (pending == 1) cpa_wait1();
        else cpa_wait0();
        __syncthreads();
        if (kt + W2_STAGES - 1 < n_kt) {
            int sl = (kt + W2_STAGES - 1) % W2_STAGES;
            uint32_t base = sb + sl * W2_STAGE_B;
            size_t ko = (size_t)(kt + W2_STAGES - 1) * KT;
            #pragma unroll
            for (int ci = 0; ci < 4; ci++) {
                cpa16(base + dstA[ci], srcA[ci] + ko);
                cpa16(base + dstB[ci], srcB[ci] + ko);
            }
            cpa_commit();
        }
        uint32_t sbase = sb + (kt % W2_STAGES) * W2_STAGE_B;
        #pragma unroll
        for (int s16 = 0; s16 < 4; s16++) {
            int kb0 = s16 * 32 + colb;
            uint32_t ah[2][4], bn[8][2];
            #pragma unroll
            for (int i = 0; i < 2; i++) {
                uint32_t off = (uint32_t)((wr + i * 16 + rowm) * 128 + kb0);
                ldsm4(sbase + swz(off), ah[i][0], ah[i][1], ah[i][2], ah[i][3]);
            }
            #pragma unroll
            for (int j = 0; j < 4; j++) {
                uint32_t off = (uint32_t)((wc + j * 16 + rowm) * 128 + kb0);
                uint32_t r0, r1, r2, r3;
                ldsm4(sbase + TILE_BYTES + swz(off), r0, r1, r2, r3);
                bn[j * 2][0] = r0; bn[j * 2][1] = r2;
                bn[j * 2 + 1][0] = r1; bn[j * 2 + 1][1] = r3;
            }
            #pragma unroll
            for (int i = 0; i < 2; i++)
                #pragma unroll
                for (int jn = 0; jn < 8; jn++)
                    mma_fp16(accg[i][jn], ah[i], bn[jn]);
        }
        if (kt & 1) {
            int g = kt >> 1;
            #pragma unroll
            for (int jn = 0; jn < 8; jn++) {
                int c = wc + jn * 8 + (lid & 3) * 2;
                float s0 = scs[g * 128 + c];
                float s1 = scs[g * 128 + c + 1];
                #pragma unroll
                for (int i = 0; i < 2; i++) {
                    acc[i][jn][0] += s0 * accg[i][jn][0];
                    acc[i][jn][1] += s1 * accg[i][jn][1];
                    acc[i][jn][2] += s0 * accg[i][jn][2];
                    acc[i][jn][3] += s1 * accg[i][jn][3];
                    accg[i][jn][0] = 0.f; accg[i][jn][1] = 0.f;
                    accg[i][jn][2] = 0.f; accg[i][jn][3] = 0.f;
                }
            }
        }
    }

    #pragma unroll
    for (int i = 0; i < 2; i++) {
        #pragma unroll
        for (int jn = 0; jn < 8; jn++) {
            int r0 = m0 + wr + i * 16 + (lid >> 2);
            int cc = n0 + wc + jn * 8 + (lid & 3) * 2;
            #pragma unroll
            for (int half = 0; half < 2; half++) {
                int row = r0 + half * 8;
                if (row >= M) continue;
                float v0 = acc[i][jn][half * 2 + 0];
                float v1 = acc[i][jn][half * 2 + 1];
                *reinterpret_cast<float2*>(C + strideC * z + (size_t)row * ldc + cc) =
                    make_float2(v0, v1);
            }
        }
    }
}

// ---------------- fused q-rope / k-quant+rope / v-quant prep ----------------
__global__ void kvprep_kernel(const float* __restrict__ qkv,
                              bf16* __restrict__ qh, bf16* __restrict__ ql,
                              bf16* __restrict__ kh, bf16* __restrict__ kl,
                              bf16* __restrict__ vn, float* __restrict__ vs) {
    int j = blockIdx.x;
    int d = threadIdx.x;
    __shared__ float smn[HDIM], smx[HDIM], sh[HDIM];
    if (j < TT * HH) {
        int t = j >> 3, hh = j & 7;
        sh[d] = qkv[(size_t)t * NQKV + hh * HDIM + d];
        __syncthreads();
        int pos = t & (SS - 1);
        int i = d & 63;
        float invf = expf(-13.815510557964274f * ((float)(2 * i) * (1.0f / HDIM)));
        float f = (float)pos * invf;
        float c = cosf(f), sn = sinf(f);
        float v = (d < 64) ? (sh[d] * c - sh[d + 64] * sn)
                           : (sh[d] * c + sh[d - 64] * sn);
        bf16 h, l; split_bf(v, h, l);
        qh[(size_t)j * HDIM + d] = h;
        ql[(size_t)j * HDIM + d] = l;
        return;
    }
    int j2 = j - TT * HH;
    bool isK = j2 < TT * KV;
    int rowid = isK ? j2 : (j2 - TT * KV);
    int t = rowid >> 1, kvh = rowid & 1;
    float v = qkv[(size_t)t * NQKV + (isK ? 1024 : 1280) + kvh * HDIM + d];
    smn[d] = v; smx[d] = v; __syncthreads();
    for (int o2 = 64; o2; o2 >>= 1) {
        if (d < o2) {
            smn[d] = fminf(smn[d], smn[d + o2]);
            smx[d] = fmaxf(smx[d], smx[d + o2]);
        }
        __syncthreads();
    }
    float scale = fmaxf(smx[0] - smn[0], 1e-5f) / 15.0f;
    float sinv = 1.0f / scale;
    float base = fminf(fmaxf(rintf(-smn[0] * sinv), 0.f), 15.f);
    float qn = fminf(fmaxf(rintf(v * sinv), -base), 15.0f - base);
    if (!isK) {
        vn[(size_t)rowid * HDIM + d] = __float2bfloat16(qn);
        if (d == 0) vs[rowid] = scale;
        return;
    }
    float q = qn * scale;
    sh[d] = q; __syncthreads();
    int pos = t & (SS - 1);
    int i = d & 63;
    float invf = expf(-13.815510557964274f * ((float)(2 * i) * (1.0f / HDIM)));
    float f = (float)pos * invf;
    float c = cosf(f), sn = sinf(f);
    q = (d < 64) ? (sh[d] * c - sh[d + 64] * sn)
                 : (sh[d] * c + sh[d - 64] * sn);
    bf16 h, l; split_bf(q, h, l);
    kh[(size_t)rowid * HDIM + d] = h;
    kl[(size_t)rowid * HDIM + d] = l;
}

// ---------------- TC scores ----------------
__global__ __launch_bounds__(256, 1) void scores_tc(
    const bf16* __restrict__ qh, const bf16* __restrict__ ql,
    const bf16* __restrict__ kh, const bf16* __restrict__ kl,
    float* __restrict__ sc)
{
    int z = blockIdx.z;
    int m0 = blockIdx.y * 128, n0 = blockIdx.x * 128;
    if (n0 > m0) return;
    int b = z >> 3, hh = z & 7, kvh = (z & 7) >> 2;
    int tid = threadIdx.x, wid = tid >> 5, lid = tid & 31;
    extern __shared__ char smem[];
    uint32_t sb = smem_u32(smem);

    const bf16* src[16]; uint32_t dst[16];
    #pragma unroll
    for (int ci = 0; ci < 16; ci++) {
        int gid = ci * 256 + tid;
        int t4 = gid >> 10;
        int r = (gid >> 3) & 127;
        int c8 = gid & 7;
        const bf16* p;
        if (t4 == 0)      p = qh + ((size_t)(b * SS + m0 + r) * HH + hh) * HDIM;
        else if (t4 == 1) p = ql + ((size_t)(b * SS + m0 + r) * HH + hh) * HDIM;
        else if (t4 == 2) p = kh + ((size_t)(b * SS + n0 + r) * KV + kvh) * HDIM;
        else              p = kl + ((size_t)(b * SS + n0 + r) * KV + kvh) * HDIM;
        src[ci] = p + c8 * 8;
        dst[ci] = (uint32_t)(t4 * TILE_BYTES) + swz((uint32_t)(r * 128 + c8 * 16));
    }
    #pragma unroll
    for (int ci = 0; ci < 16; ci++) cpa16(sb + dst[ci], src[ci]);
    cpa_commit();
    #pragma unroll
    for (int ci = 0; ci < 16; ci++) cpa16(sb + 4 * TILE_BYTES + dst[ci], src[ci] + 64);
    cpa_commit();

    int wr = (wid & 3) * 32;
    int wc = (wid >> 2) * 64;
    int rowm = (lid & 7) + ((lid >> 3) & 1) * 8;
    int colb = (lid >> 4) * 16;
    float acc[2][8][4] = {};

    #pragma unroll 1
    for (int ch = 0; ch < 2; ch++) {
        if (ch == 0) cpa_wait1(); else cpa_wait0();
        __syncthreads();
        uint32_t base = sb + ch * 4 * TILE_BYTES;
        #pragma unroll
        for (int s16 = 0; s16 < 4; s16++) {
            int kb0 = s16 * 32 + colb;
            uint32_t ah[2][4], al[2][4], bh[8][2], bl[8][2];
            #pragma unroll
            for (int i = 0; i < 2; i++) {
                uint32_t off = (uint32_t)((wr + i * 16 + rowm) * 128 + kb0);
                ldsm4(base + swz(off), ah[i][0], ah[i][1], ah[i][2], ah[i][3]);
                ldsm4(base + TILE_BYTES + swz(off), al[i][0], al[i][1], al[i][2], al[i][3]);
            }
            #pragma unroll
            for (int j = 0; j < 4; j++) {
                uint32_t off = (uint32_t)((wc + j * 16 + rowm) * 128 + kb0);
                uint32_t r0, r1, r2, r3;
                ldsm4(base + 2 * TILE_BYTES + swz(off), r0, r1, r2, r3);
                bh[j * 2][0] = r0; bh[j * 2][1] = r2;
                bh[j * 2 + 1][0] = r1; bh[j * 2 + 1][1] = r3;
                ldsm4(base + 3 * TILE_BYTES + swz(off), r0, r1, r2, r3);
                bl[j * 2][0] = r0; bl[j * 2][1] = r2;
                bl[j * 2 + 1][0] = r1; bl[j * 2 + 1][1] = r3;
            }
            #pragma unroll
            for (int i = 0; i < 2; i++)
                #pragma unroll
                for (int jn = 0; jn < 8; jn++) {
                    mma16816(acc[i][jn], ah[i], bh[jn]);
                    mma16816(acc[i][jn], ah[i], bl[jn]);
                    mma16816(acc[i][jn], al[i], bh[jn]);
                }
        }
    }
    const float scalef = 0.08838834764831845f;
    float* C = sc + (size_t)z * SS * SS;
    #pragma unroll
    for (int i = 0; i < 2; i++)
        #pragma unroll
        for (int jn = 0; jn < 8; jn++) {
            int r0 = m0 + wr + i * 16 + (lid >> 2);
            int cc = n0 + wc + jn * 8 + (lid & 3) * 2;
            #pragma unroll
            for (int half = 0; half < 2; half++) {
                int row = r0 + half * 8;
                float v0 = acc[i][jn][half * 2 + 0] * scalef;
                float v1 = acc[i][jn][half * 2 + 1] * scalef;
                *reinterpret_cast<float2*>(C + (size_t)row * SS + cc) = make_float2(v0, v1);
            }
        }
}

// ------- softmax: exp values kept in registers ----------
__global__ void softmax_kernel(const float* __restrict__ sc, const float* __restrict__ vs,
                               bf16* __restrict__ ph, bf16* __restrict__ pl) {
    int r = blockIdx.x;
    int z = r >> 10;
    int s = r & (SS - 1);
    int b = z >> 3, kvh = (z & 7) >> 2;
    const float* row = sc + (size_t)r * SS;
    int n = s + 1;
    int nlim = (s | 127) + 1;
    __shared__ float sh[256];
    float m = -INFINITY;
    #pragma unroll
    for (int j = 0; j < 4; j++) {
        int i = threadIdx.x + j * 256;
        if (i < n) m = fmaxf(m, row[i]);
    }
    sh[threadIdx.x] = m; __syncthreads();
    for (int o2 = 128; o2; o2 >>= 1) {
        if (threadIdx.x < o2) sh[threadIdx.x] = fmaxf(sh[threadIdx.x], sh[threadIdx.x + o2]);
        __syncthreads();
    }
    m = sh[0]; __syncthreads();
    float ev[4];
    float sum = 0.f;
    #pragma unroll
    for (int j = 0; j < 4; j++) {
        int i = threadIdx.x + j * 256;
        float e = (i < n) ? expf(row[i] - m) : 0.f;
        ev[j] = e; sum += e;
    }
    sh[threadIdx.x] = sum; __syncthreads();
    for (int o2 = 128; o2; o2 >>= 1) {
        if (threadIdx.x < o2) sh[threadIdx.x] += sh[threadIdx.x + o2];
        __syncthreads();
    }
    float inv = 1.0f / sh[0];
    #pragma unroll
    for (int j = 0; j < 4; j++) {
        int i = threadIdx.x + j * 256;
        if (i >= nlim) break;
        float pv = ev[j] * inv * vs[(size_t)((b * SS + i) * KV + kvh)];
        bf16 h, l; split_bf(pv, h, l);
        ph[(size_t)r * SS + i] = h;
        pl[(size_t)r * SS + i] = l;
    }
}

// ---------------- TC AV ----------------
__global__ __launch_bounds__(256, 1) void av_tc(
    const bf16* __restrict__ ph, const bf16* __restrict__ pl,
    const bf16* __restrict__ vn, bf16* __restrict__ oh, bf16* __restrict__ ol)
{
    int z = blockIdx.z;
    int b = z >> 3, hh = z & 7, kvh = (z & 7) >> 2;
    int m0 = blockIdx.y * 128;
    int tid = threadIdx.x, wid = tid >> 5, lid = tid & 31;
    extern __shared__ char smem[];
    uint32_t sb = smem_u32(smem);

    const bf16* srcP[4]; const bf16* srcV[4];
    uint32_t dstP[4], dstV[4];
    ptrdiff_t dpl = pl - ph;
    #pragma unroll
    for (int ci = 0; ci < 4; ci++) {
        int gid = ci * 256 + tid;
        int r = (gid >> 3) & 127;
        int c8 = gid & 7;
        srcP[ci] = ph + (size_t)z * SS * SS + (size_t)(m0 + r) * SS + c8 * 8;
        dstP[ci] = swz((uint32_t)(r * 128 + c8 * 16));
        int gid2 = 2048 + gid;
        int vrow = (gid2 >> 4) & 63;
        int c16 = gid2 & 15;
        int plane = c16 >> 3, cc8 = c16 & 7;
        srcV[ci] = vn + ((size_t)(b * SS + vrow) * KV + kvh) * HDIM + plane * 64 + cc8 * 8;
        dstV[ci] = (uint32_t)(2 * TILE_BYTES + plane * 8192) + swz((uint32_t)(vrow * 128 + cc8 * 16));
    }

    int n_ch = (m0 >> 6) + 2;
    #pragma unroll 1
    for (int p = 0; p < 2 && p < n_ch; p++) {
        uint32_t base = sb + p * AV_STAGE;
        #pragma unroll
        for (int ci = 0; ci < 4; ci++) {
            size_t ko = (size_t)p * KT;
            cpa16(base + dstP[ci], srcP[ci] + ko);
            cpa16(base + TILE_BYTES + dstP[ci], srcP[ci] + dpl + ko);
            cpa16(base + dstV[ci], srcV[ci] + ko * (KV * HDIM));
        }
        cpa_commit();
    }

    int wr = (wid & 3) * 32;
    int wc = (wid >> 2) * 64;
    int vplane = wc >> 6;
    int rowm = (lid & 7) + ((lid >> 3) & 1) * 8;
    int colb = (lid >> 4) * 16;
    float acc[2][8][4] = {};

    #pragma unroll 1
    for (int kt = 0; kt < n_ch; kt++) {
        cpa_wait1();
        __syncthreads();
        if (kt + 2 < n_ch) {
            int sl = (kt + 2) % 3;
            uint32_t base = sb + sl * AV_STAGE;
            size_t ko = (size_t)(kt + 2) * KT;
            #pragma unroll
            for (int ci = 0; ci < 4; ci++) {
                cpa16(base + dstP[ci], srcP[ci] + ko);
                cpa16(base + TILE_BYTES + dstP[ci], srcP[ci] + dpl + ko);
                cpa16(base + dstV[ci], srcV[ci] + ko * (KV * HDIM));
            }
            cpa_commit();
        }
        uint32_t sbase = sb + (kt % 3) * AV_STAGE;
        uint32_t vbase = sbase + 2 * TILE_BYTES + vplane * 8192;
        #pragma unroll
        for (int s16 = 0; s16 < 4; s16++) {
            int kb0 = s16 * 32 + colb;
            uint32_t ah[2][4], al[2][4], bv[8][2];
            #pragma unroll
            for (int i = 0; i < 2; i++) {
                uint32_t off = (uint32_t)((wr + i * 16 + rowm) * 128 + kb0);
                ldsm4(sbase + swz(off), ah[i][0], ah[i][1], ah[i][2], ah[i][3]);
                ldsm4(sbase + TILE_BYTES + swz(off), al[i][0], al[i][1], al[i][2], al[i][3]);
            }
            #pragma unroll
            for (int j16 = 0; j16 < 4; j16++) {
                uint32_t krow = (uint32_t)(s16 * 16 + (lid & 7) + 8 * ((lid >> 3) & 1));
                uint32_t off = krow * 128 + (uint32_t)(j16 * 32 + 16 * (lid >> 4));
                uint32_t r0, r1, r2, r3;
                ldsm4t(vbase + swz(off), r0, r1, r2, r3);
                bv[j16 * 2][0] = r0; bv[j16 * 2][1] = r1;
                bv[j16 * 2 + 1][0] = r2; bv[j16 * 2 + 1][1] = r3;
            }
            #pragma unroll
            for (int i = 0; i < 2; i++)
                #pragma unroll
                for (int jn = 0; jn < 8; jn++) {
                    mma16816(acc[i][jn], ah[i], bv[jn]);
                    mma16816(acc[i][jn], al[i], bv[jn]);
                }
        }
    }

    #pragma unroll
    for (int i = 0; i < 2; i++)
        #pragma unroll
        for (int jn = 0; jn < 8; jn++) {
            int r0 = m0 + wr + i * 16 + (lid >> 2);
            int cc = wc + jn * 8 + (lid & 3) * 2;
            #pragma unroll
            for (int half = 0; half < 2; half++) {
                int row = r0 + half * 8;
                float v0 = acc[i][jn][half * 2 + 0];
                float v1 = acc[i][jn][half * 2 + 1];
                size_t o = ((size_t)(b * SS + row) * HH + hh) * HDIM + cc;
                bf16 h0, l0, h1, l1;
                split_bf(v0, h0, l0); split_bf(v1, h1, l1);
                oh[o] = h0; oh[o + 1] = h1;
                ol[o] = l0; ol[o + 1] = l1;
            }
        }
}

// ---------------- router ----------------
__global__ __launch_bounds__(256) void router_kernel(
    const float* __restrict__ hn, const float* __restrict__ wg)
{
    int tkn = blockIdx.x;
    int w = threadIdx.x >> 5, lane = threadIdx.x & 31;
    const float* x = hn + (size_t)tkn * DD;
    const float* g = wg + (size_t)w * DD;
    float s = 0.f;
    for (int i = lane; i < DD; i += 32) s += x[i] * g[i];
    s = warp_sum(s);
    __shared__ float lg[EE];
    if (lane == 0) lg[w] = s;
    __syncthreads();
    if (threadIdx.x == 0) {
        float m = -INFINITY;
        #pragma unroll
        for (int e = 0; e < EE; e++) m = fmaxf(m, lg[e]);
        float ex[EE];
        #pragma unroll
        for (int e = 0; e < EE; e++) ex[e] = expf(lg[e] - m);
        int i1 = 0; float m1 = ex[0];
        #pragma unroll
        for (int e = 1; e < EE; e++) if (ex[e] > m1) { m1 = ex[e]; i1 = e; }
        int i2 = -1; float m2 = -1.f;
        #pragma unroll
        for (int e = 0; e < EE; e++) if (e != i1 && ex[e] > m2) { m2 = ex[e]; i2 = e; }
        float inv = 1.0f / (m1 + m2);
        int p1 = atomicAdd(&g_cnt[i1], 1);
        g_tok[i1 * TT + p1] = tkn; g_twt[i1 * TT + p1] = m1 * inv;
        int p2 = atomicAdd(&g_cnt[i2], 1);
        g_tok[i2 * TT + p2] = tkn; g_twt[i2 * TT + p2] = m2 * inv;
        g_tslot[tkn * 2 + 0] = i1 * TT + p1;
        g_tslot[tkn * 2 + 1] = i2 * TT + p2;
    }
}

// ---------------- final: out = h + w0*moeX[s0] + w1*moeX[s1] ----------------
__global__ void final_gather_kernel(const float* __restrict__ h,
                                    const float* __restrict__ moeX,
                                    const int* __restrict__ tsl,
                                    const float* __restrict__ twt,
                                    float* __restrict__ out) {
    int t = blockIdx.x;
    int s0 = tsl[t * 2], s1 = tsl[t * 2 + 1];
    float w0 = twt[s0], w1 = twt[s1];
    const float4* b0 = reinterpret_cast<const float4*>(moeX + (size_t)s0 * DD);
    const float4* b1 = reinterpret_cast<const float4*>(moeX + (size_t)s1 * DD);
    const float4* hr = reinterpret_cast<const float4*>(h + (size_t)t * DD);
    float4* o = reinterpret_cast<float4*>(out + (size_t)t * DD);
    int d = threadIdx.x;
    float4 a = hr[d], x0 = b0[d], x1 = b1[d];
    a.x += w0 * x0.x + w1 * x1.x;
    a.y += w0 * x0.y + w1 * x1.y;
    a.z += w0 * x0.z + w1 * x1.z;
    a.w += w0 * x0.w + w1 * x1.w;
    o[d] = a;
}

// ======================= host =======================
extern "C" void kernel_launch(void* const* d_in, const int* in_sizes, int n_in,
                              void* d_out, int out_size) {
    const float* hidden = (const float*)d_in[0];
    const float* w_q    = (const float*)d_in[1];
    const float* w_k    = (const float*)d_in[2];
    const float* w_v    = (const float*)d_in[3];
    const float* w_o    = (const float*)d_in[4];
    const float* g1     = (const float*)d_in[5];
    const float* g2     = (const float*)d_in[6];
    const float* w_gate = (const float*)d_in[7];
    const float* w1     = (const float*)d_in[8];
    const float* w3     = (const float*)d_in[9];
    const float* w2     = (const float*)d_in[10];
    float* out = (float*)d_out;

    bf16 *p_wqkvn, *p_won, *p_w1n, *p_w3n;
    f16 *p_w2n, *p_upf;
    float *p_wqkvs, *p_wos, *p_w1s, *p_w3s, *p_w2s;
    bf16 *p_hnh, *p_hnl, *p_oh, *p_ol;
    bf16 *p_xnh, *p_xnl;
    bf16 *p_qh, *p_ql, *p_kh, *p_kl, *p_vn, *p_ph, *p_pl;
    float *p_qkv, *p_vs, *p_sc, *p_h, *p_hn, *p_moeX, *p_twt;
    int *p_cnt, *p_tok, *p_tslot;
    cudaGetSymbolAddress((void**)&p_wqkvn, g_wqkvn); cudaGetSymbolAddress((void**)&p_wqkvs, g_wqkvs);
    cudaGetSymbolAddress((void**)&p_won, g_won); cudaGetSymbolAddress((void**)&p_wos, g_wos);
    cudaGetSymbolAddress((void**)&p_w1n, g_w1n); cudaGetSymbolAddress((void**)&p_w1s, g_w1s);
    cudaGetSymbolAddress((void**)&p_w3n, g_w3n); cudaGetSymbolAddress((void**)&p_w3s, g_w3s);
    cudaGetSymbolAddress((void**)&p_w2n, g_w2n); cudaGetSymbolAddress((void**)&p_w2s, g_w2s);
    cudaGetSymbolAddress((void**)&p_xnh, g_xnh); cudaGetSymbolAddress((void**)&p_xnl, g_xnl);
    cudaGetSymbolAddress((void**)&p_hnh, g_hnh); cudaGetSymbolAddress((void**)&p_hnl, g_hnl);
    cudaGetSymbolAddress((void**)&p_oh, g_oh);   cudaGetSymbolAddress((void**)&p_ol, g_ol);
    cudaGetSymbolAddress((void**)&p_upf, g_upf);
    cudaGetSymbolAddress((void**)&p_qkv, g_qkv);
    cudaGetSymbolAddress((void**)&p_qh, g_qh);   cudaGetSymbolAddress((void**)&p_ql, g_ql);
    cudaGetSymbolAddress((void**)&p_kh, g_kh);   cudaGetSymbolAddress((void**)&p_kl, g_kl);
    cudaGetSymbolAddress((void**)&p_vn, g_vn);   cudaGetSymbolAddress((void**)&p_vs, g_vs);
    cudaGetSymbolAddress((void**)&p_sc, g_sc);
    cudaGetSymbolAddress((void**)&p_ph, g_ph);   cudaGetSymbolAddress((void**)&p_pl, g_pl);
    cudaGetSymbolAddress((void**)&p_h, g_h);     cudaGetSymbolAddress((void**)&p_hn, g_hn);
    cudaGetSymbolAddress((void**)&p_moeX, g_moeX);
    cudaGetSymbolAddress((void**)&p_cnt, g_cnt); cudaGetSymbolAddress((void**)&p_tok, g_tok);
    cudaGetSymbolAddress((void**)&p_twt, g_twt); cudaGetSymbolAddress((void**)&p_tslot, g_tslot);

    cudaFuncSetAttribute(gemm_tc<0>, cudaFuncAttributeMaxDynamicSharedMemorySize, SMEM_SZ);
    cudaFuncSetAttribute(gemm_tc<1>, cudaFuncAttributeMaxDynamicSharedMemorySize, SMEM_SZ);
    cudaFuncSetAttribute(gemm_w13, cudaFuncAttributeMaxDynamicSharedMemorySize, W13_SMEM);
    cudaFuncSetAttribute(gemm_w2, cudaFuncAttributeMaxDynamicSharedMemorySize, W2_SMEM);
    cudaFuncSetAttribute(scores_tc, cudaFuncAttributeMaxDynamicSharedMemorySize, SCR_SMEM);
    cudaFuncSetAttribute(av_tc, cudaFuncAttributeMaxDynamicSharedMemorySize, AV_SMEM);

    static cudaStream_t s2 = nullptr;
    static cudaEvent_t ev_fork = nullptr, ev_join = nullptr;
    if (!s2) {
        cudaStreamCreateWithFlags(&s2, cudaStreamNonBlocking);
        cudaEventCreateWithFlags(&ev_fork, cudaEventDisableTiming);
        cudaEventCreateWithFlags(&ev_join, cudaEventDisableTiming);
    }

    zero_cnt_kernel<<<1, 32>>>(p_cnt);

    // fork: fused big MoE weight quants on s2
    const int NG_BIG = EE * FFND * DD / 128;
    cudaEventRecord(ev_fork, 0);
    cudaStreamWaitEvent(s2, ev_fork, 0);
    quantw3_kernel<<<dim3(NG_BIG / 16, 1, 3), 256, 0, s2>>>(
        w1, w3, w2, p_w1n, p_w3n, p_w2n, p_w1s, p_w3s, p_w2s, NG_BIG);
    cudaEventRecord(ev_join, s2);

    quantw_kernel<<<DD * DD / 128 / 16, 256>>>(w_q, p_wqkvn, p_wqkvs, DD * DD / 128);
    quantw_kernel<<<KV * HDIM * DD / 128 / 16, 256>>>(w_k, p_wqkvn + 1024 * DD,
        p_wqkvs + 1024 * 8, KV * HDIM * DD / 128);
    quantw_kernel<<<KV * HDIM * DD / 128 / 16, 256>>>(w_v, p_wqkvn + 1280 * DD,
        p_wqkvs + 1280 * 8, KV * HDIM * DD / 128);
    quantw_kernel<<<DD * DD / 128 / 16, 256>>>(w_o, p_won, p_wos, DD * DD / 128);

    // ---- attention ----
    rms_split_kernel<false><<<TT, 256>>>(hidden, g1, nullptr, p_xnh, p_xnl);
    gemm_tc<0><<<dim3(12, 16, 1), 256, SMEM_SZ>>>(p_xnh, p_xnl, DD,
        p_wqkvn, p_wqkvs, DD, p_qkv, NQKV, TT, DD, nullptr);
    kvprep_kernel<<<TT * (HH + KV + KV), HDIM>>>(p_qkv, p_qh, p_ql, p_kh, p_kl, p_vn, p_vs);
    scores_tc<<<dim3(8, 8, BB * HH), 256, SCR_SMEM>>>(p_qh, p_ql, p_kh, p_kl, p_sc);
    softmax_kernel<<<BB * HH * SS, 256>>>(p_sc, p_vs, p_ph, p_pl);
    av_tc<<<dim3(1, 8, BB * HH), 256, AV_SMEM>>>(p_ph, p_pl, p_vn, p_oh, p_ol);
    gemm_tc<1><<<dim3(8, 16, 1), 256, SMEM_SZ>>>(p_oh, p_ol, DD,
        p_won, p_wos, DD, p_h, DD, TT, DD, hidden);

    // ---- MoE ----
    rms_split_kernel<true><<<TT, 256>>>(p_h, g2, p_hn, p_hnh, p_hnl);
    router_kernel<<<TT, 256>>>(p_hn, w_gate);
    cudaStreamWaitEvent(0, ev_join, 0);
    gemm_w13<<<dim3(28, 16, EE), 256, W13_SMEM>>>(p_hnh, p_hnl, DD,
        p_w1n, p_w1s, p_w3n, p_w3s, DD, (size_t)FFND * DD, (size_t)FFND * 8,
        p_upf, FFND, (size_t)TT * FFND,
        p_cnt, DD, p_tok);
    gemm_w2<<<dim3(8, 16, EE), 256, W2_SMEM>>>(p_upf, FFND, (size_t)TT * FFND,
        p_w2n, p_w2s, FFND, (size_t)DD * FFND, (size_t)DD * 28,
        p_moeX, DD, (size_t)TT * DD,
        p_cnt, FFND);
    final_gather_kernel<<<TT, 256>>>(p_h, p_moeX, p_tslot, p_twt, out);
}